// round 1
// baseline (speedup 1.0000x reference)
#include <cuda_runtime.h>
#include <cuda_bf16.h>
#include <math.h>

#define Bq 2
#define Tq 4096
#define DIMq 2048
#define Hq 16
#define HKVq 4
#define HDq 128
#define NREPq 4
#define Rq 16
#define NBq 256
#define TOPKq 64

// ---------------- scratch (static device globals; no allocation) ----------------
__device__ float g_q[Bq * Tq * Hq * HDq];       // 16.8M  (B*T, H*HD)
__device__ float g_k[Bq * Tq * HKVq * HDq];     // 4.2M
__device__ float g_v[Bq * Tq * HKVq * HDq];     // 4.2M
__device__ float g_xo[Bq * Tq * DIMq];          // 16.8M  attention output (B*T, DIM)
__device__ float g_ck[Bq * HKVq * NBq * HDq];
__device__ float g_cv[Bq * HKVq * NBq * HDq];
__device__ float g_ksel[Bq * HKVq * TOPKq * HDq];
__device__ float g_vsel[Bq * HKVq * TOPKq * HDq];
__device__ float g_xmean_part[Bq * 16 * DIMq];
__device__ float g_xmean[Bq * DIMq];
__device__ float g_kimean[Bq * HDq];
__device__ float g_u[Bq * DIMq];
__device__ float g_scores[Bq * NBq];
__device__ int   g_topk[Bq * TOPKq];

// ---------------- generic tiled fp32 GEMM: C[M,N] = A[M,K] @ B[K,N] ----------------
// 128x128 tile, K-tile 16, 256 threads, 8x8 per thread. M%128==0, N%128==0, K%16==0.
__global__ __launch_bounds__(256, 2)
void gemm_tiled(const float* __restrict__ A, const float* __restrict__ B,
                float* __restrict__ C, int M, int N, int K) {
    __shared__ float As[16][132];  // transposed: As[k][m]
    __shared__ float Bs[16][132];  // Bs[k][n]
    const int tid = threadIdx.x;
    const int brow = blockIdx.y << 7;
    const int bcol = blockIdx.x << 7;
    const int tm = (tid >> 4) << 3;
    const int tn = (tid & 15) << 3;

    float acc[8][8];
#pragma unroll
    for (int i = 0; i < 8; i++)
#pragma unroll
        for (int j = 0; j < 8; j++) acc[i][j] = 0.f;

    for (int k0 = 0; k0 < K; k0 += 16) {
        // load A tile (128 rows x 16 k) -> As transposed. 512 float4, 2 per thread
#pragma unroll
        for (int i = 0; i < 2; i++) {
            int flat = tid + (i << 8);          // 0..511
            int r = flat >> 2;                  // 0..127
            int kq = (flat & 3) << 2;           // 0,4,8,12
            float4 av = *reinterpret_cast<const float4*>(
                A + (size_t)(brow + r) * K + k0 + kq);
            As[kq + 0][r] = av.x;
            As[kq + 1][r] = av.y;
            As[kq + 2][r] = av.z;
            As[kq + 3][r] = av.w;
        }
        // load B tile (16 k x 128 cols). 512 float4, 2 per thread
#pragma unroll
        for (int i = 0; i < 2; i++) {
            int flat = tid + (i << 8);
            int kk = flat >> 5;                 // 0..15
            int c4 = (flat & 31) << 2;          // 0..124
            float4 bv = *reinterpret_cast<const float4*>(
                B + (size_t)(k0 + kk) * N + bcol + c4);
            *reinterpret_cast<float4*>(&Bs[kk][c4]) = bv;
        }
        __syncthreads();
#pragma unroll
        for (int kk = 0; kk < 16; kk++) {
            float4 a0 = *reinterpret_cast<float4*>(&As[kk][tm]);
            float4 a1 = *reinterpret_cast<float4*>(&As[kk][tm + 4]);
            float4 b0 = *reinterpret_cast<float4*>(&Bs[kk][tn]);
            float4 b1 = *reinterpret_cast<float4*>(&Bs[kk][tn + 4]);
            float a[8] = {a0.x, a0.y, a0.z, a0.w, a1.x, a1.y, a1.z, a1.w};
            float b[8] = {b0.x, b0.y, b0.z, b0.w, b1.x, b1.y, b1.z, b1.w};
#pragma unroll
            for (int i = 0; i < 8; i++)
#pragma unroll
                for (int j = 0; j < 8; j++) acc[i][j] = fmaf(a[i], b[j], acc[i][j]);
        }
        __syncthreads();
    }
#pragma unroll
    for (int i = 0; i < 8; i++) {
#pragma unroll
        for (int j = 0; j < 8; j += 4) {
            float4 o = make_float4(acc[i][j], acc[i][j + 1], acc[i][j + 2], acc[i][j + 3]);
            *reinterpret_cast<float4*>(C + (size_t)(brow + tm + i) * N + bcol + tn + j) = o;
        }
    }
}

// ---------------- RoPE (interleaved pairs), double-precision angles ----------------
__global__ void rope_kernel(float* __restrict__ data, int nheads, size_t total_pairs) {
    size_t idx = (size_t)blockIdx.x * blockDim.x + threadIdx.x;
    if (idx >= total_pairs) return;
    int p = (int)(idx & 63);                   // 0..63
    size_t rest = idx >> 6;
    int h = (int)(rest % nheads);
    size_t bt = rest / nheads;
    int t = (int)(bt % Tq);
    double freq = exp(-((double)p / 64.0) * log(10000.0));
    double ang = (double)t * freq;
    double cd, sd;
    sincos(ang, &sd, &cd);
    float c = (float)cd, s = (float)sd;
    float* base = data + bt * ((size_t)nheads * HDq) + (size_t)h * HDq + 2 * p;
    float a = base[0], b = base[1];
    base[0] = a * c - b * s;
    base[1] = a * s + b * c;
}

// ---------------- block compression: w = 0.5*(softmax(k@cwa)+softmax(k@cwb)) ----------------
__global__ void compress_kernel(const float* __restrict__ cwa, const float* __restrict__ cwb) {
    int n = blockIdx.x % NBq;
    int hk = (blockIdx.x / NBq) % HKVq;
    int b = blockIdx.x / (NBq * HKVq);
    __shared__ float kb[Rq][HDq + 4];
    __shared__ float vb[Rq][HDq + 4];
    __shared__ float sa[Rq], sb[Rq], w[Rq];
    int d = threadIdx.x;  // 128
    for (int r = 0; r < Rq; r++) {
        int t = n * Rq + r;
        size_t off = ((size_t)(b * Tq + t)) * (HKVq * HDq) + hk * HDq + d;
        kb[r][d] = g_k[off];
        vb[r][d] = g_v[off];
    }
    __syncthreads();
    if (d < Rq) {
        float da = 0.f, db = 0.f;
        for (int i = 0; i < HDq; i++) {
            float kv = kb[d][i];
            da += kv * cwa[i];
            db += kv * cwb[i];
        }
        sa[d] = da;
        sb[d] = db;
    }
    __syncthreads();
    if (d == 0) {
        float ma = -INFINITY, mb = -INFINITY;
        for (int r = 0; r < Rq; r++) { ma = fmaxf(ma, sa[r]); mb = fmaxf(mb, sb[r]); }
        float ea[Rq], eb[Rq];
        float suma = 0.f, sumb = 0.f;
        for (int r = 0; r < Rq; r++) {
            ea[r] = expf(sa[r] - ma); suma += ea[r];
            eb[r] = expf(sb[r] - mb); sumb += eb[r];
        }
        float ia = 1.f / suma, ib = 1.f / sumb;
        for (int r = 0; r < Rq; r++) w[r] = 0.5f * (ea[r] * ia + eb[r] * ib);
    }
    __syncthreads();
    float ck = 0.f, cv = 0.f;
    for (int r = 0; r < Rq; r++) {
        ck += w[r] * kb[r][d];
        cv += w[r] * vb[r][d];
    }
    size_t o = ((size_t)((b * HKVq + hk) * NBq + n)) * HDq + d;
    g_ck[o] = ck;
    g_cv[o] = cv;
}

// ---------------- x row-mean (two stage) ----------------
__global__ void xmean_part_kernel(const float* __restrict__ x) {
    int b = blockIdx.z;
    int chunk = blockIdx.y;          // 16 chunks of 256 t
    int c = blockIdx.x * 128 + threadIdx.x;
    float s = 0.f;
    for (int tt = chunk * 256; tt < (chunk + 1) * 256; tt++)
        s += x[((size_t)(b * Tq + tt)) * DIMq + c];
    g_xmean_part[((size_t)(b * 16 + chunk)) * DIMq + c] = s;
}
__global__ void xmean_final_kernel() {
    int b = blockIdx.x / 16;
    int c = (blockIdx.x % 16) * 128 + threadIdx.x;
    float s = 0.f;
    for (int ch = 0; ch < 16; ch++) s += g_xmean_part[((size_t)(b * 16 + ch)) * DIMq + c];
    g_xmean[b * DIMq + c] = s * (1.0f / (float)Tq);
}

// ki_mean[b,d] = xmean[b,:] @ wik[:,d]
__global__ void kimean_kernel(const float* __restrict__ wik) {
    int b = blockIdx.x;
    int d = threadIdx.x;  // 128
    float s = 0.f;
    for (int c = 0; c < DIMq; c++) s += g_xmean[b * DIMq + c] * wik[(size_t)c * HDq + d];
    g_kimean[b * HDq + d] = s;
}

// u[b,c] = wiq[c,:] @ ki_mean[b,:]
__global__ void u_kernel(const float* __restrict__ wiq) {
    int b = blockIdx.x / 16;
    int c = (blockIdx.x % 16) * 128 + threadIdx.x;
    float s = 0.f;
    for (int d = 0; d < HDq; d++) s += wiq[(size_t)c * HDq + d] * g_kimean[b * HDq + d];
    g_u[b * DIMq + c] = s;
}

// scores[b,t] = x[b,t,:] . u[b,:]   (only t < NB)
__global__ void scores_kernel(const float* __restrict__ x) {
    int t = blockIdx.x % NBq;
    int b = blockIdx.x / NBq;
    __shared__ float red[128];
    float s = 0.f;
    const float* xp = x + ((size_t)(b * Tq + t)) * DIMq;
    const float* up = g_u + b * DIMq;
    for (int c = threadIdx.x; c < DIMq; c += 128) s += xp[c] * up[c];
    red[threadIdx.x] = s;
    __syncthreads();
    for (int off = 64; off > 0; off >>= 1) {
        if (threadIdx.x < off) red[threadIdx.x] += red[threadIdx.x + off];
        __syncthreads();
    }
    if (threadIdx.x == 0) g_scores[b * NBq + t] = red[0];
}

// top-64 of 256 per batch (iterative argmax; lower index wins ties like jax)
__global__ void topk_kernel() {
    int b = blockIdx.x;
    int t = threadIdx.x;  // 256
    __shared__ float rv[256];
    __shared__ int ri[256];
    float v = g_scores[b * NBq + t];
    for (int it = 0; it < TOPKq; it++) {
        rv[t] = v;
        ri[t] = t;
        __syncthreads();
        for (int s = 128; s > 0; s >>= 1) {
            if (t < s) {
                if (rv[t + s] > rv[t] || (rv[t + s] == rv[t] && ri[t + s] < ri[t])) {
                    rv[t] = rv[t + s];
                    ri[t] = ri[t + s];
                }
            }
            __syncthreads();
        }
        int win = ri[0];
        if (t == 0) g_topk[b * TOPKq + it] = win;
        if (t == win) v = -INFINITY;
        __syncthreads();
    }
}

// gather selected compressed K/V
__global__ void gather_kernel() {
    int j = blockIdx.x % TOPKq;
    int hk = (blockIdx.x / TOPKq) % HKVq;
    int b = blockIdx.x / (TOPKq * HKVq);
    int d = threadIdx.x;  // 128
    int n = g_topk[b * TOPKq + j];
    size_t src = ((size_t)((b * HKVq + hk) * NBq + n)) * HDq + d;
    size_t dst = ((size_t)((b * HKVq + hk) * TOPKq + j)) * HDq + d;
    g_ksel[dst] = g_ck[src];
    g_vsel[dst] = g_cv[src];
}

// ---------------- attention over 64 selected blocks ----------------
// block = (b, h, tile of 16 queries); 256 threads = 8 warps x 2 queries
__global__ __launch_bounds__(256)
void attn_kernel() {
    int ntiles = Tq / 16;
    int tile = blockIdx.x % ntiles;
    int h = (blockIdx.x / ntiles) % Hq;
    int b = blockIdx.x / (ntiles * Hq);
    int hk = h / NREPq;

    __shared__ float Ks[TOPKq][HDq + 1];
    const float* kselp = g_ksel + ((size_t)(b * HKVq + hk)) * TOPKq * HDq;
    const float* vselp = g_vsel + ((size_t)(b * HKVq + hk)) * TOPKq * HDq;
    for (int idx = threadIdx.x; idx < TOPKq * HDq; idx += blockDim.x)
        Ks[idx / HDq][idx % HDq] = kselp[idx];
    __syncthreads();

    int warp = threadIdx.x >> 5;
    int lane = threadIdx.x & 31;
    const float scale = 0.08838834764831845f;  // 1/sqrt(128)

#pragma unroll
    for (int qq = 0; qq < 2; qq++) {
        int t = tile * 16 + warp * 2 + qq;
        const float* qp = g_q + ((size_t)(b * Tq + t)) * (Hq * HDq) + h * HDq;
        float s0 = 0.f, s1 = 0.f;
        int j0 = lane * 2, j1 = lane * 2 + 1;
#pragma unroll 8
        for (int i = 0; i < HDq; i++) {
            float qv = __ldg(qp + i);
            s0 = fmaf(qv, Ks[j0][i], s0);
            s1 = fmaf(qv, Ks[j1][i], s1);
        }
        s0 *= scale;
        s1 *= scale;
        float m = fmaxf(s0, s1);
        for (int o = 16; o > 0; o >>= 1) m = fmaxf(m, __shfl_xor_sync(0xffffffffu, m, o));
        float e0 = expf(s0 - m), e1 = expf(s1 - m);
        float sum = e0 + e1;
        for (int o = 16; o > 0; o >>= 1) sum += __shfl_xor_sync(0xffffffffu, sum, o);
        float inv = 1.0f / sum;
        e0 *= inv;
        e1 *= inv;
        float acc0 = 0.f, acc1 = 0.f, acc2 = 0.f, acc3 = 0.f;
        for (int j = 0; j < TOPKq; j++) {
            float pa = __shfl_sync(0xffffffffu, e0, j >> 1);
            float pb = __shfl_sync(0xffffffffu, e1, j >> 1);
            float p = (j & 1) ? pb : pa;
            const float* vr = vselp + (size_t)j * HDq + lane;
            acc0 = fmaf(p, vr[0], acc0);
            acc1 = fmaf(p, vr[32], acc1);
            acc2 = fmaf(p, vr[64], acc2);
            acc3 = fmaf(p, vr[96], acc3);
        }
        float* op = g_xo + ((size_t)(b * Tq + t)) * DIMq + h * HDq + lane;
        op[0] = acc0;
        op[32] = acc1;
        op[64] = acc2;
        op[96] = acc3;
    }
}

// ---------------- launch ----------------
extern "C" void kernel_launch(void* const* d_in, const int* in_sizes, int n_in,
                              void* d_out, int out_size) {
    const float* x   = (const float*)d_in[0];
    const float* wq  = (const float*)d_in[1];
    const float* wk  = (const float*)d_in[2];
    const float* wv  = (const float*)d_in[3];
    const float* wo  = (const float*)d_in[4];
    const float* wiq = (const float*)d_in[5];
    const float* wik = (const float*)d_in[6];
    const float* cwa = (const float*)d_in[7];
    const float* cwb = (const float*)d_in[8];
    float* out = (float*)d_out;

    float *p_q, *p_k, *p_v, *p_xo;
    cudaGetSymbolAddress((void**)&p_q, g_q);
    cudaGetSymbolAddress((void**)&p_k, g_k);
    cudaGetSymbolAddress((void**)&p_v, g_v);
    cudaGetSymbolAddress((void**)&p_xo, g_xo);

    const int M = Bq * Tq;  // 8192

    // projections
    gemm_tiled<<<dim3(DIMq / 128, M / 128), 256>>>(x, wq, p_q, M, DIMq, DIMq);
    gemm_tiled<<<dim3((HKVq * HDq) / 128, M / 128), 256>>>(x, wk, p_k, M, HKVq * HDq, DIMq);
    gemm_tiled<<<dim3((HKVq * HDq) / 128, M / 128), 256>>>(x, wv, p_v, M, HKVq * HDq, DIMq);

    // rope
    {
        size_t qp = (size_t)Bq * Tq * Hq * 64;
        rope_kernel<<<(int)((qp + 255) / 256), 256>>>(p_q, Hq, qp);
        size_t kp = (size_t)Bq * Tq * HKVq * 64;
        rope_kernel<<<(int)((kp + 255) / 256), 256>>>(p_k, HKVq, kp);
    }

    // compression
    compress_kernel<<<Bq * HKVq * NBq, 128>>>(cwa, cwb);

    // selection scores (algebraically reduced)
    xmean_part_kernel<<<dim3(16, 16, Bq), 128>>>(x);
    xmean_final_kernel<<<Bq * 16, 128>>>();
    kimean_kernel<<<Bq, 128>>>(wik);
    u_kernel<<<Bq * 16, 128>>>(wiq);
    scores_kernel<<<Bq * NBq, 128>>>(x);
    topk_kernel<<<Bq, 256>>>();
    gather_kernel<<<Bq * HKVq * TOPKq, 128>>>();

    // attention
    attn_kernel<<<Bq * Hq * (Tq / 16), 256>>>();

    // output projection
    gemm_tiled<<<dim3(DIMq / 128, M / 128), 256>>>(p_xo, wo, out, M, DIMq, DIMq);
}

// round 3
// speedup vs baseline: 1.7849x; 1.7849x over previous
#include <cuda_runtime.h>
#include <cuda_fp16.h>
#include <math.h>
#include <cstdint>

#define Bq 2
#define Tq 4096
#define DIMq 2048
#define Hq 16
#define HKVq 4
#define HDq 128
#define NREPq 4
#define Rq 16
#define NBq 256
#define TOPKq 64
#define Mq (Bq * Tq)          // 8192

// ---------------- scratch (static device globals; no allocation) ----------------
__device__ float g_q[Mq * Hq * HDq];
__device__ float g_k[Mq * HKVq * HDq];
__device__ float g_v[Mq * HKVq * HDq];
__device__ float g_xo[Mq * DIMq];
__device__ float g_ck[Bq * HKVq * NBq * HDq];
__device__ float g_cv[Bq * HKVq * NBq * HDq];
__device__ float g_ksel[Bq * HKVq * TOPKq * HDq];
__device__ float g_vsel[Bq * HKVq * TOPKq * HDq];
__device__ float g_xmean_part[Bq * 16 * DIMq];
__device__ float g_xmean[Bq * DIMq];
__device__ float g_kimean[Bq * HDq];
__device__ float g_u[Bq * DIMq];
__device__ float g_scores[Bq * NBq];
__device__ int   g_topk[Bq * TOPKq];

// fp16 operands
__device__ __half g_xhi[Mq * DIMq];
__device__ __half g_xlo[Mq * DIMq];
__device__ __half g_xohi[Mq * DIMq];
__device__ __half g_xolo[Mq * DIMq];
__device__ __half g_wqT[DIMq * DIMq];              // [N][K]
__device__ __half g_wkT[(HKVq * HDq) * DIMq];
__device__ __half g_wvT[(HKVq * HDq) * DIMq];
__device__ __half g_woT[DIMq * DIMq];

// ---------------- helpers ----------------
__device__ __forceinline__ uint32_t smem_u32(const void* p) {
    uint32_t a;
    asm("{ .reg .u64 t; cvta.to.shared.u64 t, %1; cvt.u32.u64 %0, t; }" : "=r"(a) : "l"(p));
    return a;
}
__device__ __forceinline__ void cp16(uint32_t dst, const void* src) {
    asm volatile("cp.async.cg.shared.global [%0], [%1], 16;" :: "r"(dst), "l"(src));
}
__device__ __forceinline__ void ldsm4(uint32_t& r0, uint32_t& r1, uint32_t& r2, uint32_t& r3,
                                      uint32_t addr) {
    asm volatile("ldmatrix.sync.aligned.m8n8.x4.shared.b16 {%0,%1,%2,%3}, [%4];"
                 : "=r"(r0), "=r"(r1), "=r"(r2), "=r"(r3) : "r"(addr));
}
__device__ __forceinline__ void mma16816(float& c0, float& c1, float& c2, float& c3,
                                         uint32_t a0, uint32_t a1, uint32_t a2, uint32_t a3,
                                         uint32_t b0, uint32_t b1) {
    asm volatile(
        "mma.sync.aligned.m16n8k16.row.col.f32.f16.f16.f32 "
        "{%0,%1,%2,%3}, {%4,%5,%6,%7}, {%8,%9}, {%0,%1,%2,%3};"
        : "+f"(c0), "+f"(c1), "+f"(c2), "+f"(c3)
        : "r"(a0), "r"(a1), "r"(a2), "r"(a3), "r"(b0), "r"(b1));
}

// ---------------- mma.sync fp16 GEMM, activation hi/lo split (2 passes) ----------------
// C[M,N] = (Ahi + Alo)[M,K] @ Bt[N,K]^T.  All fp16 operands, fp32 accum.
// CTA 128x128, ktile 64, 4-stage cp.async, 8 warps (4m x 2n), warp tile 32x64.
#define KTILE 64
#define NSTAGE 4
#define STAGE_BYTES 32768
#define GEMM_SMEM (NSTAGE * STAGE_BYTES)

__global__ __launch_bounds__(256)
void gemm_f16_split(const __half* __restrict__ Ahi, const __half* __restrict__ Alo,
                    const __half* __restrict__ Bt, float* __restrict__ C,
                    int M, int N, int K) {
    extern __shared__ char smem[];
    const uint32_t tiles = smem_u32(smem);
    const int tid = threadIdx.x;
    const int wid = tid >> 5;
    const int lane = tid & 31;
    const int brow = blockIdx.y << 7;
    const int bcol = blockIdx.x << 7;
    const int kchunks = K >> 6;
    const int nchunks = 2 * kchunks;

    const int wm = (wid & 3) << 5;   // 0,32,64,96
    const int wn = (wid >> 2) << 6;  // 0,64

    float acc[2][8][4];
#pragma unroll
    for (int i = 0; i < 2; i++)
#pragma unroll
        for (int j = 0; j < 8; j++)
#pragma unroll
            for (int c = 0; c < 4; c++) acc[i][j][c] = 0.f;

    auto produce = [&](int ci) {
        const int slot = ci & (NSTAGE - 1);
        const __half* Ap = (ci < kchunks) ? Ahi : Alo;
        const int kk = ((ci < kchunks) ? ci : ci - kchunks) << 6;
        const uint32_t sA = tiles + slot * STAGE_BYTES;
        const uint32_t sB = sA + 16384;
#pragma unroll
        for (int i = 0; i < 4; i++) {
            int ch = tid + (i << 8);        // 0..1023
            int row = ch >> 3;              // 0..127
            int c = ch & 7;                 // 16B chunk
            uint32_t soff = (row << 7) + (((c ^ (row & 7))) << 4);
            cp16(sA + soff, Ap + (size_t)(brow + row) * K + kk + c * 8);
            cp16(sB + soff, Bt + (size_t)(bcol + row) * K + kk + c * 8);
        }
        asm volatile("cp.async.commit_group;" ::: "memory");
    };

    // prologue: 3 stages in flight
    produce(0);
    produce(1);
    produce(2);

    for (int ci = 0; ci < nchunks; ci++) {
        if (ci + 2 < nchunks)
            asm volatile("cp.async.wait_group 2;" ::: "memory");
        else if (ci + 1 < nchunks)
            asm volatile("cp.async.wait_group 1;" ::: "memory");
        else
            asm volatile("cp.async.wait_group 0;" ::: "memory");
        __syncthreads();
        if (ci + 3 < nchunks) produce(ci + 3);

        const int slot = ci & (NSTAGE - 1);
        const uint32_t sA = tiles + slot * STAGE_BYTES;
        const uint32_t sB = sA + 16384;

#pragma unroll
        for (int ks = 0; ks < 4; ks++) {
            const int kc = (ks << 1) + (lane >> 4);  // 16B chunk for this lane
            uint32_t a[2][4];
#pragma unroll
            for (int ma = 0; ma < 2; ma++) {
                int row = wm + (ma << 4) + (lane & 15);
                uint32_t addr = sA + (row << 7) + ((kc ^ (row & 7)) << 4);
                ldsm4(a[ma][0], a[ma][1], a[ma][2], a[ma][3], addr);
            }
            uint32_t b[4][4];
#pragma unroll
            for (int nb = 0; nb < 4; nb++) {
                int row = wn + (nb << 4) + (lane & 15);
                uint32_t addr = sB + (row << 7) + ((kc ^ (row & 7)) << 4);
                ldsm4(b[nb][0], b[nb][1], b[nb][2], b[nb][3], addr);
            }
#pragma unroll
            for (int ma = 0; ma < 2; ma++)
#pragma unroll
                for (int j = 0; j < 8; j++) {
                    int nb = j >> 1, sel = j & 1;
                    mma16816(acc[ma][j][0], acc[ma][j][1], acc[ma][j][2], acc[ma][j][3],
                             a[ma][0], a[ma][1], a[ma][2], a[ma][3],
                             b[nb][sel], b[nb][sel + 2]);
                }
        }
    }

    // epilogue
    const int g = lane >> 2;       // groupID
    const int tg = lane & 3;       // threadInGroup
#pragma unroll
    for (int ma = 0; ma < 2; ma++) {
#pragma unroll
        for (int j = 0; j < 8; j++) {
            int row = brow + wm + (ma << 4) + g;
            int col = bcol + wn + (j << 3) + (tg << 1);
            float2 lo = make_float2(acc[ma][j][0], acc[ma][j][1]);
            float2 hi = make_float2(acc[ma][j][2], acc[ma][j][3]);
            *reinterpret_cast<float2*>(C + (size_t)row * N + col) = lo;
            *reinterpret_cast<float2*>(C + (size_t)(row + 8) * N + col) = hi;
        }
    }
}

// ---------------- fp32 -> fp16 hi/lo split ----------------
__global__ void split_act_h(const float* __restrict__ src, __half* __restrict__ hi,
                            __half* __restrict__ lo, size_t n) {
    size_t i = (size_t)blockIdx.x * blockDim.x + threadIdx.x;
    size_t stride = (size_t)gridDim.x * blockDim.x;
    for (; i < n; i += stride) {
        float v = src[i];
        __half h = __float2half(v);
        hi[i] = h;
        lo[i] = __float2half(v - __half2float(h));
    }
}

// transpose + convert: w [K,N] fp32 -> wT [N,K] fp16
__global__ void transpose_h(const float* __restrict__ w, __half* __restrict__ wT,
                            int K, int N) {
    __shared__ float t[32][33];
    int n0 = blockIdx.x << 5, k0 = blockIdx.y << 5;
    int tx = threadIdx.x, ty = threadIdx.y;
#pragma unroll
    for (int j = 0; j < 4; j++)
        t[ty + j * 8][tx] = w[(size_t)(k0 + ty + j * 8) * N + n0 + tx];
    __syncthreads();
#pragma unroll
    for (int j = 0; j < 4; j++) {
        int n = n0 + ty + j * 8;
        wT[(size_t)n * K + k0 + tx] = __float2half(t[tx][ty + j * 8]);
    }
}

// ---------------- RoPE ----------------
__global__ void rope_kernel(float* __restrict__ data, int nheads, size_t total_pairs) {
    size_t idx = (size_t)blockIdx.x * blockDim.x + threadIdx.x;
    if (idx >= total_pairs) return;
    int p = (int)(idx & 63);
    size_t rest = idx >> 6;
    int h = (int)(rest % nheads);
    size_t bt = rest / nheads;
    int t = (int)(bt % Tq);
    double freq = exp(-((double)p / 64.0) * log(10000.0));
    double ang = (double)t * freq;
    double cd, sd;
    sincos(ang, &sd, &cd);
    float c = (float)cd, s = (float)sd;
    float* bp = data + bt * ((size_t)nheads * HDq) + (size_t)h * HDq + 2 * p;
    float a = bp[0], b = bp[1];
    bp[0] = a * c - b * s;
    bp[1] = a * s + b * c;
}

// ---------------- block compression ----------------
__global__ void compress_kernel(const float* __restrict__ cwa, const float* __restrict__ cwb) {
    int n = blockIdx.x % NBq;
    int hk = (blockIdx.x / NBq) % HKVq;
    int b = blockIdx.x / (NBq * HKVq);
    __shared__ float kb[Rq][HDq + 4];
    __shared__ float vb[Rq][HDq + 4];
    __shared__ float sa[Rq], sb[Rq], w[Rq];
    int d = threadIdx.x;
    for (int r = 0; r < Rq; r++) {
        int t = n * Rq + r;
        size_t off = ((size_t)(b * Tq + t)) * (HKVq * HDq) + hk * HDq + d;
        kb[r][d] = g_k[off];
        vb[r][d] = g_v[off];
    }
    __syncthreads();
    if (d < Rq) {
        float da = 0.f, db = 0.f;
        for (int i = 0; i < HDq; i++) {
            float kv = kb[d][i];
            da += kv * cwa[i];
            db += kv * cwb[i];
        }
        sa[d] = da;
        sb[d] = db;
    }
    __syncthreads();
    if (d == 0) {
        float ma = -INFINITY, mb = -INFINITY;
        for (int r = 0; r < Rq; r++) { ma = fmaxf(ma, sa[r]); mb = fmaxf(mb, sb[r]); }
        float ea[Rq], eb[Rq];
        float suma = 0.f, sumb = 0.f;
        for (int r = 0; r < Rq; r++) {
            ea[r] = expf(sa[r] - ma); suma += ea[r];
            eb[r] = expf(sb[r] - mb); sumb += eb[r];
        }
        float ia = 1.f / suma, ib = 1.f / sumb;
        for (int r = 0; r < Rq; r++) w[r] = 0.5f * (ea[r] * ia + eb[r] * ib);
    }
    __syncthreads();
    float ck = 0.f, cv = 0.f;
    for (int r = 0; r < Rq; r++) {
        ck += w[r] * kb[r][d];
        cv += w[r] * vb[r][d];
    }
    size_t o = ((size_t)((b * HKVq + hk) * NBq + n)) * HDq + d;
    g_ck[o] = ck;
    g_cv[o] = cv;
}

// ---------------- selection chain ----------------
__global__ void xmean_part_kernel(const float* __restrict__ x) {
    int b = blockIdx.z;
    int chunk = blockIdx.y;
    int c = blockIdx.x * 128 + threadIdx.x;
    float s = 0.f;
    for (int tt = chunk * 256; tt < (chunk + 1) * 256; tt++)
        s += x[((size_t)(b * Tq + tt)) * DIMq + c];
    g_xmean_part[((size_t)(b * 16 + chunk)) * DIMq + c] = s;
}
__global__ void xmean_final_kernel() {
    int b = blockIdx.x / 16;
    int c = (blockIdx.x % 16) * 128 + threadIdx.x;
    float s = 0.f;
    for (int ch = 0; ch < 16; ch++) s += g_xmean_part[((size_t)(b * 16 + ch)) * DIMq + c];
    g_xmean[b * DIMq + c] = s * (1.0f / (float)Tq);
}
__global__ void kimean_kernel(const float* __restrict__ wik) {
    int b = blockIdx.x;
    int d = threadIdx.x;
    float s = 0.f;
    for (int c = 0; c < DIMq; c++) s += g_xmean[b * DIMq + c] * wik[(size_t)c * HDq + d];
    g_kimean[b * HDq + d] = s;
}
__global__ void u_kernel(const float* __restrict__ wiq) {
    int b = blockIdx.x / 16;
    int c = (blockIdx.x % 16) * 128 + threadIdx.x;
    float s = 0.f;
    for (int d = 0; d < HDq; d++) s += wiq[(size_t)c * HDq + d] * g_kimean[b * HDq + d];
    g_u[b * DIMq + c] = s;
}
__global__ void scores_kernel(const float* __restrict__ x) {
    int t = blockIdx.x % NBq;
    int b = blockIdx.x / NBq;
    __shared__ float red[128];
    float s = 0.f;
    const float* xp = x + ((size_t)(b * Tq + t)) * DIMq;
    const float* up = g_u + b * DIMq;
    for (int c = threadIdx.x; c < DIMq; c += 128) s += xp[c] * up[c];
    red[threadIdx.x] = s;
    __syncthreads();
    for (int off = 64; off > 0; off >>= 1) {
        if (threadIdx.x < off) red[threadIdx.x] += red[threadIdx.x + off];
        __syncthreads();
    }
    if (threadIdx.x == 0) g_scores[b * NBq + t] = red[0];
}
__global__ void topk_kernel() {
    int b = blockIdx.x;
    int t = threadIdx.x;
    __shared__ float rv[256];
    __shared__ int ri[256];
    float v = g_scores[b * NBq + t];
    for (int it = 0; it < TOPKq; it++) {
        rv[t] = v;
        ri[t] = t;
        __syncthreads();
        for (int s = 128; s > 0; s >>= 1) {
            if (t < s) {
                if (rv[t + s] > rv[t] || (rv[t + s] == rv[t] && ri[t + s] < ri[t])) {
                    rv[t] = rv[t + s];
                    ri[t] = ri[t + s];
                }
            }
            __syncthreads();
        }
        int win = ri[0];
        if (t == 0) g_topk[b * TOPKq + it] = win;
        if (t == win) v = -INFINITY;
        __syncthreads();
    }
}
__global__ void gather_kernel() {
    int j = blockIdx.x % TOPKq;
    int hk = (blockIdx.x / TOPKq) % HKVq;
    int b = blockIdx.x / (TOPKq * HKVq);
    int d = threadIdx.x;
    int n = g_topk[b * TOPKq + j];
    size_t src = ((size_t)((b * HKVq + hk) * NBq + n)) * HDq + d;
    size_t dst = ((size_t)((b * HKVq + hk) * TOPKq + j)) * HDq + d;
    g_ksel[dst] = g_ck[src];
    g_vsel[dst] = g_cv[src];
}

// ---------------- attention ----------------
__global__ __launch_bounds__(256)
void attn_kernel() {
    int ntiles = Tq / 16;
    int tile = blockIdx.x % ntiles;
    int h = (blockIdx.x / ntiles) % Hq;
    int b = blockIdx.x / (ntiles * Hq);
    int hk = h / NREPq;

    __shared__ float Ks[TOPKq][HDq + 1];
    const float* kselp = g_ksel + ((size_t)(b * HKVq + hk)) * TOPKq * HDq;
    const float* vselp = g_vsel + ((size_t)(b * HKVq + hk)) * TOPKq * HDq;
    for (int idx = threadIdx.x; idx < TOPKq * HDq; idx += blockDim.x)
        Ks[idx / HDq][idx % HDq] = kselp[idx];
    __syncthreads();

    int warp = threadIdx.x >> 5;
    int lane = threadIdx.x & 31;
    const float scale = 0.08838834764831845f;

#pragma unroll
    for (int qq = 0; qq < 2; qq++) {
        int t = tile * 16 + warp * 2 + qq;
        const float* qp = g_q + ((size_t)(b * Tq + t)) * (Hq * HDq) + h * HDq;
        float s0 = 0.f, s1 = 0.f;
        int j0 = lane * 2, j1 = lane * 2 + 1;
#pragma unroll 8
        for (int i = 0; i < HDq; i++) {
            float qv = __ldg(qp + i);
            s0 = fmaf(qv, Ks[j0][i], s0);
            s1 = fmaf(qv, Ks[j1][i], s1);
        }
        s0 *= scale;
        s1 *= scale;
        float m = fmaxf(s0, s1);
        for (int o = 16; o > 0; o >>= 1) m = fmaxf(m, __shfl_xor_sync(0xffffffffu, m, o));
        float e0 = expf(s0 - m), e1 = expf(s1 - m);
        float sum = e0 + e1;
        for (int o = 16; o > 0; o >>= 1) sum += __shfl_xor_sync(0xffffffffu, sum, o);
        float inv = 1.0f / sum;
        e0 *= inv;
        e1 *= inv;
        float acc0 = 0.f, acc1 = 0.f, acc2 = 0.f, acc3 = 0.f;
        for (int j = 0; j < TOPKq; j++) {
            float pa = __shfl_sync(0xffffffffu, e0, j >> 1);
            float pb = __shfl_sync(0xffffffffu, e1, j >> 1);
            float p = (j & 1) ? pb : pa;
            const float* vr = vselp + (size_t)j * HDq + lane;
            acc0 = fmaf(p, vr[0], acc0);
            acc1 = fmaf(p, vr[32], acc1);
            acc2 = fmaf(p, vr[64], acc2);
            acc3 = fmaf(p, vr[96], acc3);
        }
        float* op = g_xo + ((size_t)(b * Tq + t)) * DIMq + h * HDq + lane;
        op[0] = acc0;
        op[32] = acc1;
        op[64] = acc2;
        op[96] = acc3;
    }
}

// ---------------- launch ----------------
extern "C" void kernel_launch(void* const* d_in, const int* in_sizes, int n_in,
                              void* d_out, int out_size) {
    const float* x   = (const float*)d_in[0];
    const float* wq  = (const float*)d_in[1];
    const float* wk  = (const float*)d_in[2];
    const float* wv  = (const float*)d_in[3];
    const float* wo  = (const float*)d_in[4];
    const float* wiq = (const float*)d_in[5];
    const float* wik = (const float*)d_in[6];
    const float* cwa = (const float*)d_in[7];
    const float* cwb = (const float*)d_in[8];
    float* out = (float*)d_out;

    cudaFuncSetAttribute(gemm_f16_split, cudaFuncAttributeMaxDynamicSharedMemorySize, GEMM_SMEM);

    float *p_q, *p_k, *p_v, *p_xo;
    cudaGetSymbolAddress((void**)&p_q, g_q);
    cudaGetSymbolAddress((void**)&p_k, g_k);
    cudaGetSymbolAddress((void**)&p_v, g_v);
    cudaGetSymbolAddress((void**)&p_xo, g_xo);
    __half *xhi, *xlo, *xohi, *xolo, *wqT, *wkT, *wvT, *woT;
    cudaGetSymbolAddress((void**)&xhi, g_xhi);
    cudaGetSymbolAddress((void**)&xlo, g_xlo);
    cudaGetSymbolAddress((void**)&xohi, g_xohi);
    cudaGetSymbolAddress((void**)&xolo, g_xolo);
    cudaGetSymbolAddress((void**)&wqT, g_wqT);
    cudaGetSymbolAddress((void**)&wkT, g_wkT);
    cudaGetSymbolAddress((void**)&wvT, g_wvT);
    cudaGetSymbolAddress((void**)&woT, g_woT);

    // splits / transposes
    split_act_h<<<4096, 256>>>(x, xhi, xlo, (size_t)Mq * DIMq);
    transpose_h<<<dim3(DIMq / 32, DIMq / 32), dim3(32, 8)>>>(wq, wqT, DIMq, DIMq);
    transpose_h<<<dim3((HKVq * HDq) / 32, DIMq / 32), dim3(32, 8)>>>(wk, wkT, DIMq, HKVq * HDq);
    transpose_h<<<dim3((HKVq * HDq) / 32, DIMq / 32), dim3(32, 8)>>>(wv, wvT, DIMq, HKVq * HDq);
    transpose_h<<<dim3(DIMq / 32, DIMq / 32), dim3(32, 8)>>>(wo, woT, DIMq, DIMq);

    // projections (mma.sync tensor cores)
    gemm_f16_split<<<dim3(DIMq / 128, Mq / 128), 256, GEMM_SMEM>>>(xhi, xlo, wqT, p_q, Mq, DIMq, DIMq);
    gemm_f16_split<<<dim3((HKVq * HDq) / 128, Mq / 128), 256, GEMM_SMEM>>>(xhi, xlo, wkT, p_k, Mq, HKVq * HDq, DIMq);
    gemm_f16_split<<<dim3((HKVq * HDq) / 128, Mq / 128), 256, GEMM_SMEM>>>(xhi, xlo, wvT, p_v, Mq, HKVq * HDq, DIMq);

    // rope
    {
        size_t qp = (size_t)Mq * Hq * 64;
        rope_kernel<<<(int)((qp + 255) / 256), 256>>>(p_q, Hq, qp);
        size_t kp = (size_t)Mq * HKVq * 64;
        rope_kernel<<<(int)((kp + 255) / 256), 256>>>(p_k, HKVq, kp);
    }

    // compression + selection
    compress_kernel<<<Bq * HKVq * NBq, 128>>>(cwa, cwb);
    xmean_part_kernel<<<dim3(16, 16, Bq), 128>>>(x);
    xmean_final_kernel<<<Bq * 16, 128>>>();
    kimean_kernel<<<Bq, 128>>>(wik);
    u_kernel<<<Bq * 16, 128>>>(wiq);
    scores_kernel<<<Bq * NBq, 128>>>(x);
    topk_kernel<<<Bq, 256>>>();
    gather_kernel<<<Bq * HKVq * TOPKq, 128>>>();

    // attention
    attn_kernel<<<Bq * Hq * (Tq / 16), 256>>>();

    // output projection
    split_act_h<<<4096, 256>>>(p_xo, xohi, xolo, (size_t)Mq * DIMq);
    gemm_f16_split<<<dim3(DIMq / 128, Mq / 128), 256, GEMM_SMEM>>>(xohi, xolo, woT, out, Mq, DIMq, DIMq);
}

// round 4
// speedup vs baseline: 2.0783x; 1.1644x over previous
#include <cuda_runtime.h>
#include <cuda_fp16.h>
#include <math.h>
#include <cstdint>

#define Bq 2
#define Tq 4096
#define DIMq 2048
#define Hq 16
#define HKVq 4
#define HDq 128
#define NREPq 4
#define Rq 16
#define NBq 256
#define TOPKq 64
#define Mq (Bq * Tq)          // 8192

// ---------------- scratch ----------------
__device__ float g_q[Mq * Hq * HDq];
__device__ float g_k[Mq * HKVq * HDq];
__device__ float g_v[Mq * HKVq * HDq];
__device__ float g_ck[Bq * HKVq * NBq * HDq];
__device__ float g_cv[Bq * HKVq * NBq * HDq];
__device__ float g_ksel[Bq * HKVq * TOPKq * HDq];
__device__ float g_vsel[Bq * HKVq * TOPKq * HDq];
__device__ float g_xmean_part[Bq * 16 * DIMq];
__device__ float g_xmean[Bq * DIMq];
__device__ float g_kimean[Bq * HDq];
__device__ float g_u[Bq * DIMq];
__device__ float g_scores[Bq * NBq];
__device__ int   g_topk[Bq * TOPKq];

__device__ __half g_xh[Mq * DIMq];                 // x in fp16
__device__ __half g_xoh[Mq * DIMq];                // attention output in fp16
__device__ __half g_wqT[DIMq * DIMq];              // [N][K]
__device__ __half g_wkT[(HKVq * HDq) * DIMq];
__device__ __half g_wvT[(HKVq * HDq) * DIMq];
__device__ __half g_woT[DIMq * DIMq];

// ---------------- helpers ----------------
__device__ __forceinline__ uint32_t smem_u32(const void* p) {
    uint32_t a;
    asm("{ .reg .u64 t; cvta.to.shared.u64 t, %1; cvt.u32.u64 %0, t; }" : "=r"(a) : "l"(p));
    return a;
}
__device__ __forceinline__ void cp16(uint32_t dst, const void* src) {
    asm volatile("cp.async.cg.shared.global [%0], [%1], 16;" :: "r"(dst), "l"(src));
}
__device__ __forceinline__ void ldsm4(uint32_t& r0, uint32_t& r1, uint32_t& r2, uint32_t& r3,
                                      uint32_t addr) {
    asm volatile("ldmatrix.sync.aligned.m8n8.x4.shared.b16 {%0,%1,%2,%3}, [%4];"
                 : "=r"(r0), "=r"(r1), "=r"(r2), "=r"(r3) : "r"(addr));
}
__device__ __forceinline__ void mma16816(float& c0, float& c1, float& c2, float& c3,
                                         uint32_t a0, uint32_t a1, uint32_t a2, uint32_t a3,
                                         uint32_t b0, uint32_t b1) {
    asm volatile(
        "mma.sync.aligned.m16n8k16.row.col.f32.f16.f16.f32 "
        "{%0,%1,%2,%3}, {%4,%5,%6,%7}, {%8,%9}, {%0,%1,%2,%3};"
        : "+f"(c0), "+f"(c1), "+f"(c2), "+f"(c3)
        : "r"(a0), "r"(a1), "r"(a2), "r"(a3), "r"(b0), "r"(b1));
}

// ---------------- single-pass fp16 mma.sync GEMM ----------------
// C[M,N] = A[M,K] @ Bt[N,K]^T, fp16 in, fp32 accum/out.
// CTA 128x128, ktile 64, 4-stage cp.async, 8 warps (4m x 2n), warp tile 32x64.
#define NSTAGE 4
#define STAGE_BYTES 32768
#define GEMM_SMEM (NSTAGE * STAGE_BYTES)

__global__ __launch_bounds__(256)
void gemm_f16(const __half* __restrict__ A, const __half* __restrict__ Bt,
              float* __restrict__ C, int M, int N, int K) {
    extern __shared__ char smem[];
    const uint32_t tiles = smem_u32(smem);
    const int tid = threadIdx.x;
    const int wid = tid >> 5;
    const int lane = tid & 31;
    const int brow = blockIdx.y << 7;
    const int bcol = blockIdx.x << 7;
    const int nchunks = K >> 6;

    const int wm = (wid & 3) << 5;
    const int wn = (wid >> 2) << 6;

    float acc[2][8][4];
#pragma unroll
    for (int i = 0; i < 2; i++)
#pragma unroll
        for (int j = 0; j < 8; j++)
#pragma unroll
            for (int c = 0; c < 4; c++) acc[i][j][c] = 0.f;

    auto produce = [&](int ci) {
        const int slot = ci & (NSTAGE - 1);
        const int kk = ci << 6;
        const uint32_t sA = tiles + slot * STAGE_BYTES;
        const uint32_t sB = sA + 16384;
#pragma unroll
        for (int i = 0; i < 4; i++) {
            int ch = tid + (i << 8);
            int row = ch >> 3;
            int c = ch & 7;
            uint32_t soff = (row << 7) + (((c ^ (row & 7))) << 4);
            cp16(sA + soff, A + (size_t)(brow + row) * K + kk + c * 8);
            cp16(sB + soff, Bt + (size_t)(bcol + row) * K + kk + c * 8);
        }
        asm volatile("cp.async.commit_group;" ::: "memory");
    };

    produce(0);
    produce(1);
    produce(2);

    for (int ci = 0; ci < nchunks; ci++) {
        if (ci + 2 < nchunks)
            asm volatile("cp.async.wait_group 2;" ::: "memory");
        else if (ci + 1 < nchunks)
            asm volatile("cp.async.wait_group 1;" ::: "memory");
        else
            asm volatile("cp.async.wait_group 0;" ::: "memory");
        __syncthreads();
        if (ci + 3 < nchunks) produce(ci + 3);

        const int slot = ci & (NSTAGE - 1);
        const uint32_t sA = tiles + slot * STAGE_BYTES;
        const uint32_t sB = sA + 16384;

#pragma unroll
        for (int ks = 0; ks < 4; ks++) {
            const int kc = (ks << 1) + (lane >> 4);
            uint32_t a[2][4];
#pragma unroll
            for (int ma = 0; ma < 2; ma++) {
                int row = wm + (ma << 4) + (lane & 15);
                uint32_t addr = sA + (row << 7) + ((kc ^ (row & 7)) << 4);
                ldsm4(a[ma][0], a[ma][1], a[ma][2], a[ma][3], addr);
            }
            uint32_t b[4][4];
#pragma unroll
            for (int nb = 0; nb < 4; nb++) {
                int row = wn + (nb << 4) + (lane & 15);
                uint32_t addr = sB + (row << 7) + ((kc ^ (row & 7)) << 4);
                ldsm4(b[nb][0], b[nb][1], b[nb][2], b[nb][3], addr);
            }
#pragma unroll
            for (int ma = 0; ma < 2; ma++)
#pragma unroll
                for (int j = 0; j < 8; j++) {
                    int nb = j >> 1, sel = j & 1;
                    mma16816(acc[ma][j][0], acc[ma][j][1], acc[ma][j][2], acc[ma][j][3],
                             a[ma][0], a[ma][1], a[ma][2], a[ma][3],
                             b[nb][sel], b[nb][sel + 2]);
                }
        }
    }

    const int g = lane >> 2;
    const int tg = lane & 3;
#pragma unroll
    for (int ma = 0; ma < 2; ma++) {
#pragma unroll
        for (int j = 0; j < 8; j++) {
            int row = brow + wm + (ma << 4) + g;
            int col = bcol + wn + (j << 3) + (tg << 1);
            float2 lo = make_float2(acc[ma][j][0], acc[ma][j][1]);
            float2 hi = make_float2(acc[ma][j][2], acc[ma][j][3]);
            *reinterpret_cast<float2*>(C + (size_t)row * N + col) = lo;
            *reinterpret_cast<float2*>(C + (size_t)(row + 8) * N + col) = hi;
        }
    }
}

// ---------------- fp32 -> fp16 convert ----------------
__global__ void conv_h(const float* __restrict__ src, __half* __restrict__ dst, size_t n) {
    size_t i = ((size_t)blockIdx.x * blockDim.x + threadIdx.x) * 4;
    size_t stride = (size_t)gridDim.x * blockDim.x * 4;
    for (; i < n; i += stride) {
        float4 v = *reinterpret_cast<const float4*>(src + i);
        __half2 a = __floats2half2_rn(v.x, v.y);
        __half2 b = __floats2half2_rn(v.z, v.w);
        *reinterpret_cast<__half2*>(dst + i) = a;
        *reinterpret_cast<__half2*>(dst + i + 2) = b;
    }
}

// transpose + convert: w [K,N] fp32 -> wT [N,K] fp16
__global__ void transpose_h(const float* __restrict__ w, __half* __restrict__ wT,
                            int K, int N) {
    __shared__ float t[32][33];
    int n0 = blockIdx.x << 5, k0 = blockIdx.y << 5;
    int tx = threadIdx.x, ty = threadIdx.y;
#pragma unroll
    for (int j = 0; j < 4; j++)
        t[ty + j * 8][tx] = w[(size_t)(k0 + ty + j * 8) * N + n0 + tx];
    __syncthreads();
#pragma unroll
    for (int j = 0; j < 4; j++) {
        int n = n0 + ty + j * 8;
        wT[(size_t)n * K + k0 + tx] = __float2half(t[tx][ty + j * 8]);
    }
}

// ---------------- RoPE ----------------
__global__ void rope_kernel(float* __restrict__ data, int nheads, size_t total_pairs) {
    size_t idx = (size_t)blockIdx.x * blockDim.x + threadIdx.x;
    if (idx >= total_pairs) return;
    int p = (int)(idx & 63);
    size_t rest = idx >> 6;
    int h = (int)(rest % nheads);
    size_t bt = rest / nheads;
    int t = (int)(bt % Tq);
    double freq = exp(-((double)p / 64.0) * log(10000.0));
    double ang = (double)t * freq;
    double cd, sd;
    sincos(ang, &sd, &cd);
    float c = (float)cd, s = (float)sd;
    float* bp = data + bt * ((size_t)nheads * HDq) + (size_t)h * HDq + 2 * p;
    float a = bp[0], b = bp[1];
    bp[0] = a * c - b * s;
    bp[1] = a * s + b * c;
}

// ---------------- block compression ----------------
__global__ void compress_kernel(const float* __restrict__ cwa, const float* __restrict__ cwb) {
    int n = blockIdx.x % NBq;
    int hk = (blockIdx.x / NBq) % HKVq;
    int b = blockIdx.x / (NBq * HKVq);
    __shared__ float kb[Rq][HDq + 4];
    __shared__ float vb[Rq][HDq + 4];
    __shared__ float sa[Rq], sb[Rq], w[Rq];
    int d = threadIdx.x;
    for (int r = 0; r < Rq; r++) {
        int t = n * Rq + r;
        size_t off = ((size_t)(b * Tq + t)) * (HKVq * HDq) + hk * HDq + d;
        kb[r][d] = g_k[off];
        vb[r][d] = g_v[off];
    }
    __syncthreads();
    if (d < Rq) {
        float da = 0.f, db = 0.f;
        for (int i = 0; i < HDq; i++) {
            float kv = kb[d][i];
            da += kv * cwa[i];
            db += kv * cwb[i];
        }
        sa[d] = da;
        sb[d] = db;
    }
    __syncthreads();
    if (d == 0) {
        float ma = -INFINITY, mb = -INFINITY;
        for (int r = 0; r < Rq; r++) { ma = fmaxf(ma, sa[r]); mb = fmaxf(mb, sb[r]); }
        float ea[Rq], eb[Rq];
        float suma = 0.f, sumb = 0.f;
        for (int r = 0; r < Rq; r++) {
            ea[r] = expf(sa[r] - ma); suma += ea[r];
            eb[r] = expf(sb[r] - mb); sumb += eb[r];
        }
        float ia = 1.f / suma, ib = 1.f / sumb;
        for (int r = 0; r < Rq; r++) w[r] = 0.5f * (ea[r] * ia + eb[r] * ib);
    }
    __syncthreads();
    float ck = 0.f, cv = 0.f;
    for (int r = 0; r < Rq; r++) {
        ck += w[r] * kb[r][d];
        cv += w[r] * vb[r][d];
    }
    size_t o = ((size_t)((b * HKVq + hk) * NBq + n)) * HDq + d;
    g_ck[o] = ck;
    g_cv[o] = cv;
}

// ---------------- selection chain ----------------
__global__ void xmean_part_kernel(const float* __restrict__ x) {
    int b = blockIdx.z;
    int chunk = blockIdx.y;
    int c = blockIdx.x * 128 + threadIdx.x;
    float s = 0.f;
    for (int tt = chunk * 256; tt < (chunk + 1) * 256; tt++)
        s += x[((size_t)(b * Tq + tt)) * DIMq + c];
    g_xmean_part[((size_t)(b * 16 + chunk)) * DIMq + c] = s;
}
__global__ void xmean_final_kernel() {
    int b = blockIdx.x / 16;
    int c = (blockIdx.x % 16) * 128 + threadIdx.x;
    float s = 0.f;
    for (int ch = 0; ch < 16; ch++) s += g_xmean_part[((size_t)(b * 16 + ch)) * DIMq + c];
    g_xmean[b * DIMq + c] = s * (1.0f / (float)Tq);
}
__global__ void kimean_kernel(const float* __restrict__ wik) {
    int b = blockIdx.x;
    int d = threadIdx.x;
    float s = 0.f;
    for (int c = 0; c < DIMq; c++) s += g_xmean[b * DIMq + c] * wik[(size_t)c * HDq + d];
    g_kimean[b * HDq + d] = s;
}
__global__ void u_kernel(const float* __restrict__ wiq) {
    int b = blockIdx.x / 16;
    int c = (blockIdx.x % 16) * 128 + threadIdx.x;
    float s = 0.f;
    for (int d = 0; d < HDq; d++) s += wiq[(size_t)c * HDq + d] * g_kimean[b * HDq + d];
    g_u[b * DIMq + c] = s;
}
__global__ void scores_kernel(const float* __restrict__ x) {
    int t = blockIdx.x % NBq;
    int b = blockIdx.x / NBq;
    __shared__ float red[128];
    float s = 0.f;
    const float* xp = x + ((size_t)(b * Tq + t)) * DIMq;
    const float* up = g_u + b * DIMq;
    for (int c = threadIdx.x; c < DIMq; c += 128) s += xp[c] * up[c];
    red[threadIdx.x] = s;
    __syncthreads();
    for (int off = 64; off > 0; off >>= 1) {
        if (threadIdx.x < off) red[threadIdx.x] += red[threadIdx.x + off];
        __syncthreads();
    }
    if (threadIdx.x == 0) g_scores[b * NBq + t] = red[0];
}
__global__ void topk_kernel() {
    int b = blockIdx.x;
    int t = threadIdx.x;
    __shared__ float rv[256];
    __shared__ int ri[256];
    float v = g_scores[b * NBq + t];
    for (int it = 0; it < TOPKq; it++) {
        rv[t] = v;
        ri[t] = t;
        __syncthreads();
        for (int s = 128; s > 0; s >>= 1) {
            if (t < s) {
                if (rv[t + s] > rv[t] || (rv[t + s] == rv[t] && ri[t + s] < ri[t])) {
                    rv[t] = rv[t + s];
                    ri[t] = ri[t + s];
                }
            }
            __syncthreads();
        }
        int win = ri[0];
        if (t == 0) g_topk[b * TOPKq + it] = win;
        if (t == win) v = -INFINITY;
        __syncthreads();
    }
}
__global__ void gather_kernel() {
    int j = blockIdx.x % TOPKq;
    int hk = (blockIdx.x / TOPKq) % HKVq;
    int b = blockIdx.x / (TOPKq * HKVq);
    int d = threadIdx.x;
    int n = g_topk[b * TOPKq + j];
    size_t src = ((size_t)((b * HKVq + hk) * NBq + n)) * HDq + d;
    size_t dst = ((size_t)((b * HKVq + hk) * TOPKq + j)) * HDq + d;
    g_ksel[dst] = g_ck[src];
    g_vsel[dst] = g_cv[src];
}

// ---------------- attention (float4 QK, smem V, fp16 output) ----------------
// dynamic smem: Ks float4[64][33] + Vs float[64][132]
#define ATTN_SMEM (64 * 33 * 16 + 64 * 132 * 4)
__global__ __launch_bounds__(256)
void attn_kernel() {
    extern __shared__ char asmem[];
    float4 (*Ks)[33] = reinterpret_cast<float4(*)[33]>(asmem);
    float (*Vs)[132] = reinterpret_cast<float(*)[132]>(asmem + 64 * 33 * 16);

    int ntiles = Tq / 16;
    int tile = blockIdx.x % ntiles;
    int h = (blockIdx.x / ntiles) % Hq;
    int b = blockIdx.x / (ntiles * Hq);
    int hk = h / NREPq;

    const float* kselp = g_ksel + ((size_t)(b * HKVq + hk)) * TOPKq * HDq;
    const float* vselp = g_vsel + ((size_t)(b * HKVq + hk)) * TOPKq * HDq;
    for (int idx = threadIdx.x; idx < TOPKq * 32; idx += blockDim.x) {
        int r = idx >> 5, c = idx & 31;
        Ks[r][c] = *reinterpret_cast<const float4*>(kselp + r * HDq + c * 4);
        float4 v = *reinterpret_cast<const float4*>(vselp + r * HDq + c * 4);
        Vs[r][c * 4 + 0] = v.x;
        Vs[r][c * 4 + 1] = v.y;
        Vs[r][c * 4 + 2] = v.z;
        Vs[r][c * 4 + 3] = v.w;
    }
    __syncthreads();

    int warp = threadIdx.x >> 5;
    int lane = threadIdx.x & 31;
    const float scale = 0.08838834764831845f;

#pragma unroll
    for (int qq = 0; qq < 2; qq++) {
        int t = tile * 16 + warp * 2 + qq;
        const float4* q4 = reinterpret_cast<const float4*>(
            g_q + ((size_t)(b * Tq + t)) * (Hq * HDq) + h * HDq);
        float s0 = 0.f, s1 = 0.f;
        int j0 = lane * 2, j1 = lane * 2 + 1;
#pragma unroll 8
        for (int i = 0; i < 32; i++) {
            float4 qv = __ldg(q4 + i);
            float4 k0 = Ks[j0][i];
            float4 k1 = Ks[j1][i];
            s0 = fmaf(qv.x, k0.x, s0); s0 = fmaf(qv.y, k0.y, s0);
            s0 = fmaf(qv.z, k0.z, s0); s0 = fmaf(qv.w, k0.w, s0);
            s1 = fmaf(qv.x, k1.x, s1); s1 = fmaf(qv.y, k1.y, s1);
            s1 = fmaf(qv.z, k1.z, s1); s1 = fmaf(qv.w, k1.w, s1);
        }
        s0 *= scale;
        s1 *= scale;
        float m = fmaxf(s0, s1);
        for (int o = 16; o > 0; o >>= 1) m = fmaxf(m, __shfl_xor_sync(0xffffffffu, m, o));
        float e0 = expf(s0 - m), e1 = expf(s1 - m);
        float sum = e0 + e1;
        for (int o = 16; o > 0; o >>= 1) sum += __shfl_xor_sync(0xffffffffu, sum, o);
        float inv = 1.0f / sum;
        e0 *= inv;
        e1 *= inv;
        float acc0 = 0.f, acc1 = 0.f, acc2 = 0.f, acc3 = 0.f;
#pragma unroll 4
        for (int j = 0; j < TOPKq; j++) {
            float pa = __shfl_sync(0xffffffffu, e0, j >> 1);
            float pb = __shfl_sync(0xffffffffu, e1, j >> 1);
            float p = (j & 1) ? pb : pa;
            acc0 = fmaf(p, Vs[j][lane], acc0);
            acc1 = fmaf(p, Vs[j][lane + 32], acc1);
            acc2 = fmaf(p, Vs[j][lane + 64], acc2);
            acc3 = fmaf(p, Vs[j][lane + 96], acc3);
        }
        __half* op = g_xoh + ((size_t)(b * Tq + t)) * DIMq + h * HDq + lane;
        op[0] = __float2half(acc0);
        op[32] = __float2half(acc1);
        op[64] = __float2half(acc2);
        op[96] = __float2half(acc3);
    }
}

// ---------------- launch ----------------
extern "C" void kernel_launch(void* const* d_in, const int* in_sizes, int n_in,
                              void* d_out, int out_size) {
    const float* x   = (const float*)d_in[0];
    const float* wq  = (const float*)d_in[1];
    const float* wk  = (const float*)d_in[2];
    const float* wv  = (const float*)d_in[3];
    const float* wo  = (const float*)d_in[4];
    const float* wiq = (const float*)d_in[5];
    const float* wik = (const float*)d_in[6];
    const float* cwa = (const float*)d_in[7];
    const float* cwb = (const float*)d_in[8];
    float* out = (float*)d_out;

    cudaFuncSetAttribute(gemm_f16, cudaFuncAttributeMaxDynamicSharedMemorySize, GEMM_SMEM);
    cudaFuncSetAttribute(attn_kernel, cudaFuncAttributeMaxDynamicSharedMemorySize, ATTN_SMEM);

    float *p_q, *p_k, *p_v;
    cudaGetSymbolAddress((void**)&p_q, g_q);
    cudaGetSymbolAddress((void**)&p_k, g_k);
    cudaGetSymbolAddress((void**)&p_v, g_v);
    __half *xh, *xoh, *wqT, *wkT, *wvT, *woT;
    cudaGetSymbolAddress((void**)&xh, g_xh);
    cudaGetSymbolAddress((void**)&xoh, g_xoh);
    cudaGetSymbolAddress((void**)&wqT, g_wqT);
    cudaGetSymbolAddress((void**)&wkT, g_wkT);
    cudaGetSymbolAddress((void**)&wvT, g_wvT);
    cudaGetSymbolAddress((void**)&woT, g_woT);

    // converts / transposes
    conv_h<<<2048, 256>>>(x, xh, (size_t)Mq * DIMq);
    transpose_h<<<dim3(DIMq / 32, DIMq / 32), dim3(32, 8)>>>(wq, wqT, DIMq, DIMq);
    transpose_h<<<dim3((HKVq * HDq) / 32, DIMq / 32), dim3(32, 8)>>>(wk, wkT, DIMq, HKVq * HDq);
    transpose_h<<<dim3((HKVq * HDq) / 32, DIMq / 32), dim3(32, 8)>>>(wv, wvT, DIMq, HKVq * HDq);
    transpose_h<<<dim3(DIMq / 32, DIMq / 32), dim3(32, 8)>>>(wo, woT, DIMq, DIMq);

    // projections
    gemm_f16<<<dim3(DIMq / 128, Mq / 128), 256, GEMM_SMEM>>>(xh, wqT, p_q, Mq, DIMq, DIMq);
    gemm_f16<<<dim3((HKVq * HDq) / 128, Mq / 128), 256, GEMM_SMEM>>>(xh, wkT, p_k, Mq, HKVq * HDq, DIMq);
    gemm_f16<<<dim3((HKVq * HDq) / 128, Mq / 128), 256, GEMM_SMEM>>>(xh, wvT, p_v, Mq, HKVq * HDq, DIMq);

    // rope
    {
        size_t qp = (size_t)Mq * Hq * 64;
        rope_kernel<<<(int)((qp + 255) / 256), 256>>>(p_q, Hq, qp);
        size_t kp = (size_t)Mq * HKVq * 64;
        rope_kernel<<<(int)((kp + 255) / 256), 256>>>(p_k, HKVq, kp);
    }

    // compression + selection
    compress_kernel<<<Bq * HKVq * NBq, 128>>>(cwa, cwb);
    xmean_part_kernel<<<dim3(16, 16, Bq), 128>>>(x);
    xmean_final_kernel<<<Bq * 16, 128>>>();
    kimean_kernel<<<Bq, 128>>>(wik);
    u_kernel<<<Bq * 16, 128>>>(wiq);
    scores_kernel<<<Bq * NBq, 128>>>(x);
    topk_kernel<<<Bq, 256>>>();
    gather_kernel<<<Bq * HKVq * TOPKq, 128>>>();

    // attention (writes fp16 directly)
    attn_kernel<<<Bq * Hq * (Tq / 16), 256, ATTN_SMEM>>>();

    // output projection
    gemm_f16<<<dim3(DIMq / 128, Mq / 128), 256, GEMM_SMEM>>>(xoh, woT, out, Mq, DIMq, DIMq);
}

// round 5
// speedup vs baseline: 4.2920x; 2.0652x over previous
#include <cuda_runtime.h>
#include <cuda_fp16.h>
#include <math.h>
#include <cstdint>

#define Bq 2
#define Tq 4096
#define DIMq 2048
#define Hq 16
#define HKVq 4
#define HDq 128
#define NREPq 4
#define Rq 16
#define NBq 256
#define TOPKq 64
#define Mq (Bq * Tq)          // 8192

// ---------------- scratch ----------------
__device__ float g_q[Mq * Hq * HDq];
__device__ float g_k[Mq * HKVq * HDq];
__device__ float g_v[Mq * HKVq * HDq];
__device__ float g_ck[Bq * HKVq * NBq * HDq];
__device__ float g_cv[Bq * HKVq * NBq * HDq];
__device__ float g_ksel[Bq * HKVq * TOPKq * HDq];
__device__ float g_vsel[Bq * HKVq * TOPKq * HDq];
__device__ float g_xmean_part[Bq * 16 * DIMq];
__device__ float g_xmean[Bq * DIMq];
__device__ float g_kimean[Bq * HDq];
__device__ float g_u[Bq * DIMq];
__device__ float g_scores[Bq * NBq];
__device__ int   g_topk[Bq * TOPKq];
__device__ float2 g_trig[Tq * 64];                 // (cos, sin) per (t, pair)

__device__ __half g_xh[Mq * DIMq];                 // x in fp16
__device__ __half g_xoh[Mq * DIMq];                // attention output in fp16
__device__ __half g_wqT[DIMq * DIMq];              // [N][K]
__device__ __half g_wkT[(HKVq * HDq) * DIMq];
__device__ __half g_wvT[(HKVq * HDq) * DIMq];
__device__ __half g_woT[DIMq * DIMq];

// ---------------- helpers ----------------
__device__ __forceinline__ uint32_t smem_u32(const void* p) {
    uint32_t a;
    asm("{ .reg .u64 t; cvta.to.shared.u64 t, %1; cvt.u32.u64 %0, t; }" : "=r"(a) : "l"(p));
    return a;
}
__device__ __forceinline__ void cp16(uint32_t dst, const void* src) {
    asm volatile("cp.async.cg.shared.global [%0], [%1], 16;" :: "r"(dst), "l"(src));
}
__device__ __forceinline__ void ldsm4(uint32_t& r0, uint32_t& r1, uint32_t& r2, uint32_t& r3,
                                      uint32_t addr) {
    asm volatile("ldmatrix.sync.aligned.m8n8.x4.shared.b16 {%0,%1,%2,%3}, [%4];"
                 : "=r"(r0), "=r"(r1), "=r"(r2), "=r"(r3) : "r"(addr));
}
__device__ __forceinline__ void mma16816(float& c0, float& c1, float& c2, float& c3,
                                         uint32_t a0, uint32_t a1, uint32_t a2, uint32_t a3,
                                         uint32_t b0, uint32_t b1) {
    asm volatile(
        "mma.sync.aligned.m16n8k16.row.col.f32.f16.f16.f32 "
        "{%0,%1,%2,%3}, {%4,%5,%6,%7}, {%8,%9}, {%0,%1,%2,%3};"
        : "+f"(c0), "+f"(c1), "+f"(c2), "+f"(c3)
        : "r"(a0), "r"(a1), "r"(a2), "r"(a3), "r"(b0), "r"(b1));
}

// ---------------- single-pass fp16 mma.sync GEMM ----------------
#define NSTAGE 4
#define STAGE_BYTES 32768
#define GEMM_SMEM (NSTAGE * STAGE_BYTES)

__global__ __launch_bounds__(256)
void gemm_f16(const __half* __restrict__ A, const __half* __restrict__ Bt,
              float* __restrict__ C, int M, int N, int K) {
    extern __shared__ char smem[];
    const uint32_t tiles = smem_u32(smem);
    const int tid = threadIdx.x;
    const int wid = tid >> 5;
    const int lane = tid & 31;
    const int brow = blockIdx.y << 7;
    const int bcol = blockIdx.x << 7;
    const int nchunks = K >> 6;

    const int wm = (wid & 3) << 5;
    const int wn = (wid >> 2) << 6;

    float acc[2][8][4];
#pragma unroll
    for (int i = 0; i < 2; i++)
#pragma unroll
        for (int j = 0; j < 8; j++)
#pragma unroll
            for (int c = 0; c < 4; c++) acc[i][j][c] = 0.f;

    auto produce = [&](int ci) {
        const int slot = ci & (NSTAGE - 1);
        const int kk = ci << 6;
        const uint32_t sA = tiles + slot * STAGE_BYTES;
        const uint32_t sB = sA + 16384;
#pragma unroll
        for (int i = 0; i < 4; i++) {
            int ch = tid + (i << 8);
            int row = ch >> 3;
            int c = ch & 7;
            uint32_t soff = (row << 7) + (((c ^ (row & 7))) << 4);
            cp16(sA + soff, A + (size_t)(brow + row) * K + kk + c * 8);
            cp16(sB + soff, Bt + (size_t)(bcol + row) * K + kk + c * 8);
        }
        asm volatile("cp.async.commit_group;" ::: "memory");
    };

    produce(0);
    produce(1);
    produce(2);

    for (int ci = 0; ci < nchunks; ci++) {
        if (ci + 2 < nchunks)
            asm volatile("cp.async.wait_group 2;" ::: "memory");
        else if (ci + 1 < nchunks)
            asm volatile("cp.async.wait_group 1;" ::: "memory");
        else
            asm volatile("cp.async.wait_group 0;" ::: "memory");
        __syncthreads();
        if (ci + 3 < nchunks) produce(ci + 3);

        const int slot = ci & (NSTAGE - 1);
        const uint32_t sA = tiles + slot * STAGE_BYTES;
        const uint32_t sB = sA + 16384;

#pragma unroll
        for (int ks = 0; ks < 4; ks++) {
            const int kc = (ks << 1) + (lane >> 4);
            uint32_t a[2][4];
#pragma unroll
            for (int ma = 0; ma < 2; ma++) {
                int row = wm + (ma << 4) + (lane & 15);
                uint32_t addr = sA + (row << 7) + ((kc ^ (row & 7)) << 4);
                ldsm4(a[ma][0], a[ma][1], a[ma][2], a[ma][3], addr);
            }
            uint32_t b[4][4];
#pragma unroll
            for (int nb = 0; nb < 4; nb++) {
                int row = wn + (nb << 4) + (lane & 15);
                uint32_t addr = sB + (row << 7) + ((kc ^ (row & 7)) << 4);
                ldsm4(b[nb][0], b[nb][1], b[nb][2], b[nb][3], addr);
            }
#pragma unroll
            for (int ma = 0; ma < 2; ma++)
#pragma unroll
                for (int j = 0; j < 8; j++) {
                    int nb = j >> 1, sel = j & 1;
                    mma16816(acc[ma][j][0], acc[ma][j][1], acc[ma][j][2], acc[ma][j][3],
                             a[ma][0], a[ma][1], a[ma][2], a[ma][3],
                             b[nb][sel], b[nb][sel + 2]);
                }
        }
    }

    const int g = lane >> 2;
    const int tg = lane & 3;
#pragma unroll
    for (int ma = 0; ma < 2; ma++) {
#pragma unroll
        for (int j = 0; j < 8; j++) {
            int row = brow + wm + (ma << 4) + g;
            int col = bcol + wn + (j << 3) + (tg << 1);
            float2 lo = make_float2(acc[ma][j][0], acc[ma][j][1]);
            float2 hi = make_float2(acc[ma][j][2], acc[ma][j][3]);
            *reinterpret_cast<float2*>(C + (size_t)row * N + col) = lo;
            *reinterpret_cast<float2*>(C + (size_t)(row + 8) * N + col) = hi;
        }
    }
}

// ---------------- fp32 -> fp16 convert ----------------
__global__ void conv_h(const float* __restrict__ src, __half* __restrict__ dst, size_t n) {
    size_t i = ((size_t)blockIdx.x * blockDim.x + threadIdx.x) * 4;
    size_t stride = (size_t)gridDim.x * blockDim.x * 4;
    for (; i < n; i += stride) {
        float4 v = *reinterpret_cast<const float4*>(src + i);
        __half2 a = __floats2half2_rn(v.x, v.y);
        __half2 b = __floats2half2_rn(v.z, v.w);
        *reinterpret_cast<__half2*>(dst + i) = a;
        *reinterpret_cast<__half2*>(dst + i + 2) = b;
    }
}

// transpose + convert: w [K,N] fp32 -> wT [N,K] fp16
__global__ void transpose_h(const float* __restrict__ w, __half* __restrict__ wT,
                            int K, int N) {
    __shared__ float t[32][33];
    int n0 = blockIdx.x << 5, k0 = blockIdx.y << 5;
    int tx = threadIdx.x, ty = threadIdx.y;
#pragma unroll
    for (int j = 0; j < 4; j++)
        t[ty + j * 8][tx] = w[(size_t)(k0 + ty + j * 8) * N + n0 + tx];
    __syncthreads();
#pragma unroll
    for (int j = 0; j < 4; j++) {
        int n = n0 + ty + j * 8;
        wT[(size_t)n * K + k0 + tx] = __float2half(t[tx][ty + j * 8]);
    }
}

// ---------------- trig table: one double sincos per (t, pair) ----------------
__global__ void trig_table_kernel() {
    int idx = blockIdx.x * blockDim.x + threadIdx.x;
    if (idx >= Tq * 64) return;
    int p = idx & 63;
    int t = idx >> 6;
    double freq = exp(-((double)p / 64.0) * log(10000.0));
    double ang = (double)t * freq;
    double sd, cd;
    sincos(ang, &sd, &cd);
    g_trig[idx] = make_float2((float)cd, (float)sd);
}

// ---------------- RoPE (fp32 table lookup) ----------------
__global__ void rope_kernel(float* __restrict__ data, int nheads, size_t total_pairs) {
    size_t idx = (size_t)blockIdx.x * blockDim.x + threadIdx.x;
    if (idx >= total_pairs) return;
    int p = (int)(idx & 63);
    size_t rest = idx >> 6;
    size_t bt = rest / nheads;
    int h = (int)(rest - bt * nheads);
    int t = (int)(bt % Tq);
    float2 cs = g_trig[(t << 6) + p];
    float* bp = data + bt * ((size_t)nheads * HDq) + (size_t)h * HDq + 2 * p;
    float a = bp[0], b = bp[1];
    bp[0] = a * cs.x - b * cs.y;
    bp[1] = a * cs.y + b * cs.x;
}

// ---------------- block compression ----------------
__global__ void compress_kernel(const float* __restrict__ cwa, const float* __restrict__ cwb) {
    int n = blockIdx.x % NBq;
    int hk = (blockIdx.x / NBq) % HKVq;
    int b = blockIdx.x / (NBq * HKVq);
    __shared__ float kb[Rq][HDq + 4];
    __shared__ float vb[Rq][HDq + 4];
    __shared__ float sa[Rq], sb[Rq], w[Rq];
    int d = threadIdx.x;
    for (int r = 0; r < Rq; r++) {
        int t = n * Rq + r;
        size_t off = ((size_t)(b * Tq + t)) * (HKVq * HDq) + hk * HDq + d;
        kb[r][d] = g_k[off];
        vb[r][d] = g_v[off];
    }
    __syncthreads();
    if (d < Rq) {
        float da = 0.f, db = 0.f;
        for (int i = 0; i < HDq; i++) {
            float kv = kb[d][i];
            da += kv * cwa[i];
            db += kv * cwb[i];
        }
        sa[d] = da;
        sb[d] = db;
    }
    __syncthreads();
    if (d == 0) {
        float ma = -INFINITY, mb = -INFINITY;
        for (int r = 0; r < Rq; r++) { ma = fmaxf(ma, sa[r]); mb = fmaxf(mb, sb[r]); }
        float ea[Rq], eb[Rq];
        float suma = 0.f, sumb = 0.f;
        for (int r = 0; r < Rq; r++) {
            ea[r] = expf(sa[r] - ma); suma += ea[r];
            eb[r] = expf(sb[r] - mb); sumb += eb[r];
        }
        float ia = 1.f / suma, ib = 1.f / sumb;
        for (int r = 0; r < Rq; r++) w[r] = 0.5f * (ea[r] * ia + eb[r] * ib);
    }
    __syncthreads();
    float ck = 0.f, cv = 0.f;
    for (int r = 0; r < Rq; r++) {
        ck += w[r] * kb[r][d];
        cv += w[r] * vb[r][d];
    }
    size_t o = ((size_t)((b * HKVq + hk) * NBq + n)) * HDq + d;
    g_ck[o] = ck;
    g_cv[o] = cv;
}

// ---------------- selection chain ----------------
__global__ void xmean_part_kernel(const float* __restrict__ x) {
    int b = blockIdx.z;
    int chunk = blockIdx.y;
    int c = blockIdx.x * 128 + threadIdx.x;
    float s = 0.f;
    for (int tt = chunk * 256; tt < (chunk + 1) * 256; tt++)
        s += x[((size_t)(b * Tq + tt)) * DIMq + c];
    g_xmean_part[((size_t)(b * 16 + chunk)) * DIMq + c] = s;
}
__global__ void xmean_final_kernel() {
    int b = blockIdx.x / 16;
    int c = (blockIdx.x % 16) * 128 + threadIdx.x;
    float s = 0.f;
    for (int ch = 0; ch < 16; ch++) s += g_xmean_part[((size_t)(b * 16 + ch)) * DIMq + c];
    g_xmean[b * DIMq + c] = s * (1.0f / (float)Tq);
}
__global__ void kimean_kernel(const float* __restrict__ wik) {
    int b = blockIdx.x;
    int d = threadIdx.x;
    float s = 0.f;
    for (int c = 0; c < DIMq; c++) s += g_xmean[b * DIMq + c] * wik[(size_t)c * HDq + d];
    g_kimean[b * HDq + d] = s;
}
__global__ void u_kernel(const float* __restrict__ wiq) {
    int b = blockIdx.x / 16;
    int c = (blockIdx.x % 16) * 128 + threadIdx.x;
    float s = 0.f;
    for (int d = 0; d < HDq; d++) s += wiq[(size_t)c * HDq + d] * g_kimean[b * HDq + d];
    g_u[b * DIMq + c] = s;
}
__global__ void scores_kernel(const float* __restrict__ x) {
    int t = blockIdx.x % NBq;
    int b = blockIdx.x / NBq;
    __shared__ float red[128];
    float s = 0.f;
    const float* xp = x + ((size_t)(b * Tq + t)) * DIMq;
    const float* up = g_u + b * DIMq;
    for (int c = threadIdx.x; c < DIMq; c += 128) s += xp[c] * up[c];
    red[threadIdx.x] = s;
    __syncthreads();
    for (int off = 64; off > 0; off >>= 1) {
        if (threadIdx.x < off) red[threadIdx.x] += red[threadIdx.x + off];
        __syncthreads();
    }
    if (threadIdx.x == 0) g_scores[b * NBq + t] = red[0];
}
__global__ void topk_kernel() {
    int b = blockIdx.x;
    int t = threadIdx.x;
    __shared__ float rv[256];
    __shared__ int ri[256];
    float v = g_scores[b * NBq + t];
    for (int it = 0; it < TOPKq; it++) {
        rv[t] = v;
        ri[t] = t;
        __syncthreads();
        for (int s = 128; s > 0; s >>= 1) {
            if (t < s) {
                if (rv[t + s] > rv[t] || (rv[t + s] == rv[t] && ri[t + s] < ri[t])) {
                    rv[t] = rv[t + s];
                    ri[t] = ri[t + s];
                }
            }
            __syncthreads();
        }
        int win = ri[0];
        if (t == 0) g_topk[b * TOPKq + it] = win;
        if (t == win) v = -INFINITY;
        __syncthreads();
    }
}
__global__ void gather_kernel() {
    int j = blockIdx.x % TOPKq;
    int hk = (blockIdx.x / TOPKq) % HKVq;
    int b = blockIdx.x / (TOPKq * HKVq);
    int d = threadIdx.x;
    int n = g_topk[b * TOPKq + j];
    size_t src = ((size_t)((b * HKVq + hk) * NBq + n)) * HDq + d;
    size_t dst = ((size_t)((b * HKVq + hk) * TOPKq + j)) * HDq + d;
    g_ksel[dst] = g_ck[src];
    g_vsel[dst] = g_cv[src];
}

// ---------------- attention (float4 QK, smem V, fp16 output) ----------------
#define ATTN_SMEM (64 * 33 * 16 + 64 * 132 * 4)
__global__ __launch_bounds__(256)
void attn_kernel() {
    extern __shared__ char asmem[];
    float4 (*Ks)[33] = reinterpret_cast<float4(*)[33]>(asmem);
    float (*Vs)[132] = reinterpret_cast<float(*)[132]>(asmem + 64 * 33 * 16);

    int ntiles = Tq / 16;
    int tile = blockIdx.x % ntiles;
    int h = (blockIdx.x / ntiles) % Hq;
    int b = blockIdx.x / (ntiles * Hq);
    int hk = h / NREPq;

    const float* kselp = g_ksel + ((size_t)(b * HKVq + hk)) * TOPKq * HDq;
    const float* vselp = g_vsel + ((size_t)(b * HKVq + hk)) * TOPKq * HDq;
    for (int idx = threadIdx.x; idx < TOPKq * 32; idx += blockDim.x) {
        int r = idx >> 5, c = idx & 31;
        Ks[r][c] = *reinterpret_cast<const float4*>(kselp + r * HDq + c * 4);
        float4 v = *reinterpret_cast<const float4*>(vselp + r * HDq + c * 4);
        Vs[r][c * 4 + 0] = v.x;
        Vs[r][c * 4 + 1] = v.y;
        Vs[r][c * 4 + 2] = v.z;
        Vs[r][c * 4 + 3] = v.w;
    }
    __syncthreads();

    int warp = threadIdx.x >> 5;
    int lane = threadIdx.x & 31;
    const float scale = 0.08838834764831845f;

#pragma unroll
    for (int qq = 0; qq < 2; qq++) {
        int t = tile * 16 + warp * 2 + qq;
        const float4* q4 = reinterpret_cast<const float4*>(
            g_q + ((size_t)(b * Tq + t)) * (Hq * HDq) + h * HDq);
        float s0 = 0.f, s1 = 0.f;
        int j0 = lane * 2, j1 = lane * 2 + 1;
#pragma unroll 8
        for (int i = 0; i < 32; i++) {
            float4 qv = __ldg(q4 + i);
            float4 k0 = Ks[j0][i];
            float4 k1 = Ks[j1][i];
            s0 = fmaf(qv.x, k0.x, s0); s0 = fmaf(qv.y, k0.y, s0);
            s0 = fmaf(qv.z, k0.z, s0); s0 = fmaf(qv.w, k0.w, s0);
            s1 = fmaf(qv.x, k1.x, s1); s1 = fmaf(qv.y, k1.y, s1);
            s1 = fmaf(qv.z, k1.z, s1); s1 = fmaf(qv.w, k1.w, s1);
        }
        s0 *= scale;
        s1 *= scale;
        float m = fmaxf(s0, s1);
        for (int o = 16; o > 0; o >>= 1) m = fmaxf(m, __shfl_xor_sync(0xffffffffu, m, o));
        float e0 = expf(s0 - m), e1 = expf(s1 - m);
        float sum = e0 + e1;
        for (int o = 16; o > 0; o >>= 1) sum += __shfl_xor_sync(0xffffffffu, sum, o);
        float inv = 1.0f / sum;
        e0 *= inv;
        e1 *= inv;
        float acc0 = 0.f, acc1 = 0.f, acc2 = 0.f, acc3 = 0.f;
#pragma unroll 4
        for (int j = 0; j < TOPKq; j++) {
            float pa = __shfl_sync(0xffffffffu, e0, j >> 1);
            float pb = __shfl_sync(0xffffffffu, e1, j >> 1);
            float p = (j & 1) ? pb : pa;
            acc0 = fmaf(p, Vs[j][lane], acc0);
            acc1 = fmaf(p, Vs[j][lane + 32], acc1);
            acc2 = fmaf(p, Vs[j][lane + 64], acc2);
            acc3 = fmaf(p, Vs[j][lane + 96], acc3);
        }
        __half* op = g_xoh + ((size_t)(b * Tq + t)) * DIMq + h * HDq + lane;
        op[0] = __float2half(acc0);
        op[32] = __float2half(acc1);
        op[64] = __float2half(acc2);
        op[96] = __float2half(acc3);
    }
}

// ---------------- launch ----------------
extern "C" void kernel_launch(void* const* d_in, const int* in_sizes, int n_in,
                              void* d_out, int out_size) {
    const float* x   = (const float*)d_in[0];
    const float* wq  = (const float*)d_in[1];
    const float* wk  = (const float*)d_in[2];
    const float* wv  = (const float*)d_in[3];
    const float* wo  = (const float*)d_in[4];
    const float* wiq = (const float*)d_in[5];
    const float* wik = (const float*)d_in[6];
    const float* cwa = (const float*)d_in[7];
    const float* cwb = (const float*)d_in[8];
    float* out = (float*)d_out;

    cudaFuncSetAttribute(gemm_f16, cudaFuncAttributeMaxDynamicSharedMemorySize, GEMM_SMEM);
    cudaFuncSetAttribute(attn_kernel, cudaFuncAttributeMaxDynamicSharedMemorySize, ATTN_SMEM);

    float *p_q, *p_k, *p_v;
    cudaGetSymbolAddress((void**)&p_q, g_q);
    cudaGetSymbolAddress((void**)&p_k, g_k);
    cudaGetSymbolAddress((void**)&p_v, g_v);
    __half *xh, *xoh, *wqT, *wkT, *wvT, *woT;
    cudaGetSymbolAddress((void**)&xh, g_xh);
    cudaGetSymbolAddress((void**)&xoh, g_xoh);
    cudaGetSymbolAddress((void**)&wqT, g_wqT);
    cudaGetSymbolAddress((void**)&wkT, g_wkT);
    cudaGetSymbolAddress((void**)&wvT, g_wvT);
    cudaGetSymbolAddress((void**)&woT, g_woT);

    // trig table (FP64 hoisted out of hot path) + converts / transposes
    trig_table_kernel<<<(Tq * 64 + 255) / 256, 256>>>();
    conv_h<<<2048, 256>>>(x, xh, (size_t)Mq * DIMq);
    transpose_h<<<dim3(DIMq / 32, DIMq / 32), dim3(32, 8)>>>(wq, wqT, DIMq, DIMq);
    transpose_h<<<dim3((HKVq * HDq) / 32, DIMq / 32), dim3(32, 8)>>>(wk, wkT, DIMq, HKVq * HDq);
    transpose_h<<<dim3((HKVq * HDq) / 32, DIMq / 32), dim3(32, 8)>>>(wv, wvT, DIMq, HKVq * HDq);
    transpose_h<<<dim3(DIMq / 32, DIMq / 32), dim3(32, 8)>>>(wo, woT, DIMq, DIMq);

    // projections
    gemm_f16<<<dim3(DIMq / 128, Mq / 128), 256, GEMM_SMEM>>>(xh, wqT, p_q, Mq, DIMq, DIMq);
    gemm_f16<<<dim3((HKVq * HDq) / 128, Mq / 128), 256, GEMM_SMEM>>>(xh, wkT, p_k, Mq, HKVq * HDq, DIMq);
    gemm_f16<<<dim3((HKVq * HDq) / 128, Mq / 128), 256, GEMM_SMEM>>>(xh, wvT, p_v, Mq, HKVq * HDq, DIMq);

    // rope (fp32, table lookup)
    {
        size_t qp = (size_t)Mq * Hq * 64;
        rope_kernel<<<(int)((qp + 255) / 256), 256>>>(p_q, Hq, qp);
        size_t kp = (size_t)Mq * HKVq * 64;
        rope_kernel<<<(int)((kp + 255) / 256), 256>>>(p_k, HKVq, kp);
    }

    // compression + selection
    compress_kernel<<<Bq * HKVq * NBq, 128>>>(cwa, cwb);
    xmean_part_kernel<<<dim3(16, 16, Bq), 128>>>(x);
    xmean_final_kernel<<<Bq * 16, 128>>>();
    kimean_kernel<<<Bq, 128>>>(wik);
    u_kernel<<<Bq * 16, 128>>>(wiq);
    scores_kernel<<<Bq * NBq, 128>>>(x);
    topk_kernel<<<Bq, 256>>>();
    gather_kernel<<<Bq * HKVq * TOPKq, 128>>>();

    // attention (writes fp16 directly)
    attn_kernel<<<Bq * Hq * (Tq / 16), 256, ATTN_SMEM>>>();

    // output projection
    gemm_f16<<<dim3(DIMq / 128, Mq / 128), 256, GEMM_SMEM>>>(xoh, woT, out, Mq, DIMq, DIMq);
}

// round 6
// speedup vs baseline: 4.5618x; 1.0628x over previous
#include <cuda_runtime.h>
#include <cuda_fp16.h>
#include <math.h>
#include <cstdint>

#define Bq 2
#define Tq 4096
#define DIMq 2048
#define Hq 16
#define HKVq 4
#define HDq 128
#define NREPq 4
#define Rq 16
#define NBq 256
#define TOPKq 64
#define Mq (Bq * Tq)          // 8192
#define NQKV 3072             // 2048 + 512 + 512

// ---------------- scratch ----------------
__device__ float g_q[Mq * Hq * HDq];
__device__ float g_k[Mq * HKVq * HDq];
__device__ float g_v[Mq * HKVq * HDq];
__device__ float g_ck[Bq * HKVq * NBq * HDq];
__device__ float g_cv[Bq * HKVq * NBq * HDq];
__device__ float g_ksel[Bq * HKVq * TOPKq * HDq];
__device__ float g_vsel[Bq * HKVq * TOPKq * HDq];
__device__ float g_xmean_part[Bq * 16 * DIMq];
__device__ float g_xmean[Bq * DIMq];
__device__ float g_kimean[Bq * HDq];
__device__ float g_u[Bq * DIMq];
__device__ float g_scores[Bq * NBq];
__device__ int   g_topk[Bq * TOPKq];
__device__ float2 g_trig[Tq * 64];

__device__ __half g_xh[Mq * DIMq];
__device__ __half g_xoh[Mq * DIMq];
__device__ __half g_wqkvT[NQKV * DIMq];            // rows: wq 0..2047, wk 2048..2559, wv 2560..3071
__device__ __half g_woT[DIMq * DIMq];

// ---------------- helpers ----------------
__device__ __forceinline__ uint32_t smem_u32(const void* p) {
    uint32_t a;
    asm("{ .reg .u64 t; cvta.to.shared.u64 t, %1; cvt.u32.u64 %0, t; }" : "=r"(a) : "l"(p));
    return a;
}
__device__ __forceinline__ void cp16(uint32_t dst, const void* src) {
    asm volatile("cp.async.cg.shared.global [%0], [%1], 16;" :: "r"(dst), "l"(src));
}
__device__ __forceinline__ void ldsm4(uint32_t& r0, uint32_t& r1, uint32_t& r2, uint32_t& r3,
                                      uint32_t addr) {
    asm volatile("ldmatrix.sync.aligned.m8n8.x4.shared.b16 {%0,%1,%2,%3}, [%4];"
                 : "=r"(r0), "=r"(r1), "=r"(r2), "=r"(r3) : "r"(addr));
}
__device__ __forceinline__ void mma16816(float& c0, float& c1, float& c2, float& c3,
                                         uint32_t a0, uint32_t a1, uint32_t a2, uint32_t a3,
                                         uint32_t b0, uint32_t b1) {
    asm volatile(
        "mma.sync.aligned.m16n8k16.row.col.f32.f16.f16.f32 "
        "{%0,%1,%2,%3}, {%4,%5,%6,%7}, {%8,%9}, {%0,%1,%2,%3};"
        : "+f"(c0), "+f"(c1), "+f"(c2), "+f"(c3)
        : "r"(a0), "r"(a1), "r"(a2), "r"(a3), "r"(b0), "r"(b1));
}

// ---------------- GEMM core (shared by both kernels via macro) ----------------
#define NSTAGE 3
#define STAGE_BYTES 32768
#define GEMM_SMEM (NSTAGE * STAGE_BYTES)

// Computes 128x128 CTA tile of A[M,K] @ Bt[N,K]^T into acc[2][8][4].
// Assumes: tiles (smem base), tid/wid/lane, brow, bcol, K, A, Bt in scope.
#define GEMM_MAINLOOP(A_, Bt_, K_)                                                  \
    const int nchunks = (K_) >> 6;                                                  \
    const int wm = (wid & 3) << 5;                                                  \
    const int wn = (wid >> 2) << 6;                                                 \
    float acc[2][8][4];                                                             \
    _Pragma("unroll") for (int i = 0; i < 2; i++)                                   \
        _Pragma("unroll") for (int j = 0; j < 8; j++)                               \
            _Pragma("unroll") for (int c = 0; c < 4; c++) acc[i][j][c] = 0.f;       \
    auto produce = [&](int ci) {                                                    \
        const int slot = ci % NSTAGE;                                               \
        const int kk = ci << 6;                                                     \
        const uint32_t sA = tiles + slot * STAGE_BYTES;                             \
        const uint32_t sB = sA + 16384;                                             \
        _Pragma("unroll") for (int i = 0; i < 4; i++) {                             \
            int ch = tid + (i << 8);                                                \
            int row = ch >> 3;                                                      \
            int c = ch & 7;                                                         \
            uint32_t soff = (row << 7) + (((c ^ (row & 7))) << 4);                  \
            cp16(sA + soff, (A_) + (size_t)(brow + row) * (K_) + kk + c * 8);       \
            cp16(sB + soff, (Bt_) + (size_t)(bcol + row) * (K_) + kk + c * 8);      \
        }                                                                           \
        asm volatile("cp.async.commit_group;" ::: "memory");                        \
    };                                                                              \
    produce(0);                                                                     \
    produce(1);                                                                     \
    for (int ci = 0; ci < nchunks; ci++) {                                          \
        if (ci + 1 < nchunks)                                                       \
            asm volatile("cp.async.wait_group 1;" ::: "memory");                    \
        else                                                                        \
            asm volatile("cp.async.wait_group 0;" ::: "memory");                    \
        __syncthreads();                                                            \
        if (ci + 2 < nchunks) produce(ci + 2);                                      \
        const int slot = ci % NSTAGE;                                               \
        const uint32_t sA = tiles + slot * STAGE_BYTES;                             \
        const uint32_t sB = sA + 16384;                                             \
        _Pragma("unroll") for (int ks = 0; ks < 4; ks++) {                          \
            const int kc = (ks << 1) + (lane >> 4);                                 \
            uint32_t a[2][4];                                                       \
            _Pragma("unroll") for (int ma = 0; ma < 2; ma++) {                      \
                int row = wm + (ma << 4) + (lane & 15);                             \
                uint32_t addr = sA + (row << 7) + ((kc ^ (row & 7)) << 4);          \
                ldsm4(a[ma][0], a[ma][1], a[ma][2], a[ma][3], addr);                \
            }                                                                       \
            uint32_t b[4][4];                                                       \
            _Pragma("unroll") for (int nb = 0; nb < 4; nb++) {                      \
                int row = wn + (nb << 4) + (lane & 15);                             \
                uint32_t addr = sB + (row << 7) + ((kc ^ (row & 7)) << 4);          \
                ldsm4(b[nb][0], b[nb][1], b[nb][2], b[nb][3], addr);                \
            }                                                                       \
            _Pragma("unroll") for (int ma = 0; ma < 2; ma++)                        \
                _Pragma("unroll") for (int j = 0; j < 8; j++) {                     \
                    int nb = j >> 1, sel = j & 1;                                   \
                    mma16816(acc[ma][j][0], acc[ma][j][1], acc[ma][j][2],           \
                             acc[ma][j][3], a[ma][0], a[ma][1], a[ma][2],           \
                             a[ma][3], b[nb][sel], b[nb][sel + 2]);                 \
                }                                                                   \
        }                                                                           \
    }

// fused QKV projection: Bt = wqkvT [3072][2048]; columns route to g_q/g_k/g_v
__global__ __launch_bounds__(256, 2)
void gemm_qkv(const __half* __restrict__ A, const __half* __restrict__ Bt) {
    extern __shared__ char smem[];
    const uint32_t tiles = smem_u32(smem);
    const int tid = threadIdx.x;
    const int wid = tid >> 5;
    const int lane = tid & 31;
    const int brow = blockIdx.y << 7;
    const int bcol = blockIdx.x << 7;

    GEMM_MAINLOOP(A, Bt, DIMq)

    float* Cout;
    int cbase, cstride;
    if (bcol < 2048)      { Cout = g_q; cbase = bcol;        cstride = 2048; }
    else if (bcol < 2560) { Cout = g_k; cbase = bcol - 2048; cstride = 512; }
    else                  { Cout = g_v; cbase = bcol - 2560; cstride = 512; }

    const int g = lane >> 2;
    const int tg = lane & 3;
#pragma unroll
    for (int ma = 0; ma < 2; ma++) {
#pragma unroll
        for (int j = 0; j < 8; j++) {
            int row = brow + wm + (ma << 4) + g;
            int col = cbase + wn + (j << 3) + (tg << 1);
            float2 lo = make_float2(acc[ma][j][0], acc[ma][j][1]);
            float2 hi = make_float2(acc[ma][j][2], acc[ma][j][3]);
            *reinterpret_cast<float2*>(Cout + (size_t)row * cstride + col) = lo;
            *reinterpret_cast<float2*>(Cout + (size_t)(row + 8) * cstride + col) = hi;
        }
    }
}

// generic GEMM (used for output projection)
__global__ __launch_bounds__(256, 2)
void gemm_f16(const __half* __restrict__ A, const __half* __restrict__ Bt,
              float* __restrict__ C, int M, int N, int K) {
    extern __shared__ char smem[];
    const uint32_t tiles = smem_u32(smem);
    const int tid = threadIdx.x;
    const int wid = tid >> 5;
    const int lane = tid & 31;
    const int brow = blockIdx.y << 7;
    const int bcol = blockIdx.x << 7;

    GEMM_MAINLOOP(A, Bt, K)

    const int g = lane >> 2;
    const int tg = lane & 3;
#pragma unroll
    for (int ma = 0; ma < 2; ma++) {
#pragma unroll
        for (int j = 0; j < 8; j++) {
            int row = brow + wm + (ma << 4) + g;
            int col = bcol + wn + (j << 3) + (tg << 1);
            float2 lo = make_float2(acc[ma][j][0], acc[ma][j][1]);
            float2 hi = make_float2(acc[ma][j][2], acc[ma][j][3]);
            *reinterpret_cast<float2*>(C + (size_t)row * N + col) = lo;
            *reinterpret_cast<float2*>(C + (size_t)(row + 8) * N + col) = hi;
        }
    }
}

// ---------------- fp32 -> fp16 convert ----------------
__global__ void conv_h(const float* __restrict__ src, __half* __restrict__ dst, size_t n) {
    size_t i = ((size_t)blockIdx.x * blockDim.x + threadIdx.x) * 4;
    size_t stride = (size_t)gridDim.x * blockDim.x * 4;
    for (; i < n; i += stride) {
        float4 v = *reinterpret_cast<const float4*>(src + i);
        __half2 a = __floats2half2_rn(v.x, v.y);
        __half2 b = __floats2half2_rn(v.z, v.w);
        *reinterpret_cast<__half2*>(dst + i) = a;
        *reinterpret_cast<__half2*>(dst + i + 2) = b;
    }
}

// transpose + convert: w [K,N] fp32 -> wT [N,K] fp16 (wT pointer pre-offset)
__global__ void transpose_h(const float* __restrict__ w, __half* __restrict__ wT,
                            int K, int N) {
    __shared__ float t[32][33];
    int n0 = blockIdx.x << 5, k0 = blockIdx.y << 5;
    int tx = threadIdx.x, ty = threadIdx.y;
#pragma unroll
    for (int j = 0; j < 4; j++)
        t[ty + j * 8][tx] = w[(size_t)(k0 + ty + j * 8) * N + n0 + tx];
    __syncthreads();
#pragma unroll
    for (int j = 0; j < 4; j++) {
        int n = n0 + ty + j * 8;
        wT[(size_t)n * K + k0 + tx] = __float2half(t[tx][ty + j * 8]);
    }
}

// ---------------- trig table ----------------
__global__ void trig_table_kernel() {
    int idx = blockIdx.x * blockDim.x + threadIdx.x;
    if (idx >= Tq * 64) return;
    int p = idx & 63;
    int t = idx >> 6;
    double freq = exp(-((double)p / 64.0) * log(10000.0));
    double ang = (double)t * freq;
    double sd, cd;
    sincos(ang, &sd, &cd);
    g_trig[idx] = make_float2((float)cd, (float)sd);
}

// ---------------- RoPE (fp32 table lookup) ----------------
__global__ void rope_kernel(float* __restrict__ data, int nheads, size_t total_pairs) {
    size_t idx = (size_t)blockIdx.x * blockDim.x + threadIdx.x;
    if (idx >= total_pairs) return;
    int p = (int)(idx & 63);
    size_t rest = idx >> 6;
    size_t bt = rest / nheads;
    int h = (int)(rest - bt * nheads);
    int t = (int)(bt % Tq);
    float2 cs = g_trig[(t << 6) + p];
    float* bp = data + bt * ((size_t)nheads * HDq) + (size_t)h * HDq + 2 * p;
    float a = bp[0], b = bp[1];
    bp[0] = a * cs.x - b * cs.y;
    bp[1] = a * cs.y + b * cs.x;
}

// ---------------- block compression ----------------
__global__ void compress_kernel(const float* __restrict__ cwa, const float* __restrict__ cwb) {
    int n = blockIdx.x % NBq;
    int hk = (blockIdx.x / NBq) % HKVq;
    int b = blockIdx.x / (NBq * HKVq);
    __shared__ float kb[Rq][HDq + 4];
    __shared__ float vb[Rq][HDq + 4];
    __shared__ float sa[Rq], sb[Rq], w[Rq];
    int d = threadIdx.x;
    for (int r = 0; r < Rq; r++) {
        int t = n * Rq + r;
        size_t off = ((size_t)(b * Tq + t)) * (HKVq * HDq) + hk * HDq + d;
        kb[r][d] = g_k[off];
        vb[r][d] = g_v[off];
    }
    __syncthreads();
    if (d < Rq) {
        float da = 0.f, db = 0.f;
        for (int i = 0; i < HDq; i++) {
            float kv = kb[d][i];
            da += kv * cwa[i];
            db += kv * cwb[i];
        }
        sa[d] = da;
        sb[d] = db;
    }
    __syncthreads();
    if (d == 0) {
        float ma = -INFINITY, mb = -INFINITY;
        for (int r = 0; r < Rq; r++) { ma = fmaxf(ma, sa[r]); mb = fmaxf(mb, sb[r]); }
        float ea[Rq], eb[Rq];
        float suma = 0.f, sumb = 0.f;
        for (int r = 0; r < Rq; r++) {
            ea[r] = expf(sa[r] - ma); suma += ea[r];
            eb[r] = expf(sb[r] - mb); sumb += eb[r];
        }
        float ia = 1.f / suma, ib = 1.f / sumb;
        for (int r = 0; r < Rq; r++) w[r] = 0.5f * (ea[r] * ia + eb[r] * ib);
    }
    __syncthreads();
    float ck = 0.f, cv = 0.f;
    for (int r = 0; r < Rq; r++) {
        ck += w[r] * kb[r][d];
        cv += w[r] * vb[r][d];
    }
    size_t o = ((size_t)((b * HKVq + hk) * NBq + n)) * HDq + d;
    g_ck[o] = ck;
    g_cv[o] = cv;
}

// ---------------- selection chain ----------------
__global__ void xmean_part_kernel(const float* __restrict__ x) {
    int b = blockIdx.z;
    int chunk = blockIdx.y;
    int c = blockIdx.x * 128 + threadIdx.x;
    float s = 0.f;
    for (int tt = chunk * 256; tt < (chunk + 1) * 256; tt++)
        s += x[((size_t)(b * Tq + tt)) * DIMq + c];
    g_xmean_part[((size_t)(b * 16 + chunk)) * DIMq + c] = s;
}
__global__ void xmean_final_kernel() {
    int b = blockIdx.x / 16;
    int c = (blockIdx.x % 16) * 128 + threadIdx.x;
    float s = 0.f;
    for (int ch = 0; ch < 16; ch++) s += g_xmean_part[((size_t)(b * 16 + ch)) * DIMq + c];
    g_xmean[b * DIMq + c] = s * (1.0f / (float)Tq);
}
__global__ void kimean_kernel(const float* __restrict__ wik) {
    int b = blockIdx.x;
    int d = threadIdx.x;
    float s = 0.f;
    for (int c = 0; c < DIMq; c++) s += g_xmean[b * DIMq + c] * wik[(size_t)c * HDq + d];
    g_kimean[b * HDq + d] = s;
}
__global__ void u_kernel(const float* __restrict__ wiq) {
    int b = blockIdx.x / 16;
    int c = (blockIdx.x % 16) * 128 + threadIdx.x;
    float s = 0.f;
    for (int d = 0; d < HDq; d++) s += wiq[(size_t)c * HDq + d] * g_kimean[b * HDq + d];
    g_u[b * DIMq + c] = s;
}
__global__ void scores_kernel(const float* __restrict__ x) {
    int t = blockIdx.x % NBq;
    int b = blockIdx.x / NBq;
    __shared__ float red[128];
    float s = 0.f;
    const float* xp = x + ((size_t)(b * Tq + t)) * DIMq;
    const float* up = g_u + b * DIMq;
    for (int c = threadIdx.x; c < DIMq; c += 128) s += xp[c] * up[c];
    red[threadIdx.x] = s;
    __syncthreads();
    for (int off = 64; off > 0; off >>= 1) {
        if (threadIdx.x < off) red[threadIdx.x] += red[threadIdx.x + off];
        __syncthreads();
    }
    if (threadIdx.x == 0) g_scores[b * NBq + t] = red[0];
}
__global__ void topk_kernel() {
    int b = blockIdx.x;
    int t = threadIdx.x;
    __shared__ float rv[256];
    __shared__ int ri[256];
    float v = g_scores[b * NBq + t];
    for (int it = 0; it < TOPKq; it++) {
        rv[t] = v;
        ri[t] = t;
        __syncthreads();
        for (int s = 128; s > 0; s >>= 1) {
            if (t < s) {
                if (rv[t + s] > rv[t] || (rv[t + s] == rv[t] && ri[t + s] < ri[t])) {
                    rv[t] = rv[t + s];
                    ri[t] = ri[t + s];
                }
            }
            __syncthreads();
        }
        int win = ri[0];
        if (t == 0) g_topk[b * TOPKq + it] = win;
        if (t == win) v = -INFINITY;
        __syncthreads();
    }
}
__global__ void gather_kernel() {
    int j = blockIdx.x % TOPKq;
    int hk = (blockIdx.x / TOPKq) % HKVq;
    int b = blockIdx.x / (TOPKq * HKVq);
    int d = threadIdx.x;
    int n = g_topk[b * TOPKq + j];
    size_t src = ((size_t)((b * HKVq + hk) * NBq + n)) * HDq + d;
    size_t dst = ((size_t)((b * HKVq + hk) * TOPKq + j)) * HDq + d;
    g_ksel[dst] = g_ck[src];
    g_vsel[dst] = g_cv[src];
}

// ---------------- attention (32 queries/CTA, float4 QK, smem V, fp16 out) ----------------
#define ATTN_SMEM (64 * 33 * 16 + 64 * 132 * 4)
__global__ __launch_bounds__(256)
void attn_kernel() {
    extern __shared__ char asmem[];
    float4 (*Ks)[33] = reinterpret_cast<float4(*)[33]>(asmem);
    float (*Vs)[132] = reinterpret_cast<float(*)[132]>(asmem + 64 * 33 * 16);

    int ntiles = Tq / 32;
    int tile = blockIdx.x % ntiles;
    int h = (blockIdx.x / ntiles) % Hq;
    int b = blockIdx.x / (ntiles * Hq);
    int hk = h / NREPq;

    const float* kselp = g_ksel + ((size_t)(b * HKVq + hk)) * TOPKq * HDq;
    const float* vselp = g_vsel + ((size_t)(b * HKVq + hk)) * TOPKq * HDq;
    for (int idx = threadIdx.x; idx < TOPKq * 32; idx += blockDim.x) {
        int r = idx >> 5, c = idx & 31;
        Ks[r][c] = *reinterpret_cast<const float4*>(kselp + r * HDq + c * 4);
        float4 v = *reinterpret_cast<const float4*>(vselp + r * HDq + c * 4);
        Vs[r][c * 4 + 0] = v.x;
        Vs[r][c * 4 + 1] = v.y;
        Vs[r][c * 4 + 2] = v.z;
        Vs[r][c * 4 + 3] = v.w;
    }
    __syncthreads();

    int warp = threadIdx.x >> 5;
    int lane = threadIdx.x & 31;
    const float scale = 0.08838834764831845f;

#pragma unroll
    for (int qq = 0; qq < 4; qq++) {
        int t = tile * 32 + warp * 4 + qq;
        const float4* q4 = reinterpret_cast<const float4*>(
            g_q + ((size_t)(b * Tq + t)) * (Hq * HDq) + h * HDq);
        float s0 = 0.f, s1 = 0.f;
        int j0 = lane * 2, j1 = lane * 2 + 1;
#pragma unroll 8
        for (int i = 0; i < 32; i++) {
            float4 qv = __ldg(q4 + i);
            float4 k0 = Ks[j0][i];
            float4 k1 = Ks[j1][i];
            s0 = fmaf(qv.x, k0.x, s0); s0 = fmaf(qv.y, k0.y, s0);
            s0 = fmaf(qv.z, k0.z, s0); s0 = fmaf(qv.w, k0.w, s0);
            s1 = fmaf(qv.x, k1.x, s1); s1 = fmaf(qv.y, k1.y, s1);
            s1 = fmaf(qv.z, k1.z, s1); s1 = fmaf(qv.w, k1.w, s1);
        }
        s0 *= scale;
        s1 *= scale;
        float m = fmaxf(s0, s1);
        for (int o = 16; o > 0; o >>= 1) m = fmaxf(m, __shfl_xor_sync(0xffffffffu, m, o));
        float e0 = expf(s0 - m), e1 = expf(s1 - m);
        float sum = e0 + e1;
        for (int o = 16; o > 0; o >>= 1) sum += __shfl_xor_sync(0xffffffffu, sum, o);
        float inv = 1.0f / sum;
        e0 *= inv;
        e1 *= inv;
        float acc0 = 0.f, acc1 = 0.f, acc2 = 0.f, acc3 = 0.f;
#pragma unroll 4
        for (int j = 0; j < TOPKq; j++) {
            float pa = __shfl_sync(0xffffffffu, e0, j >> 1);
            float pb = __shfl_sync(0xffffffffu, e1, j >> 1);
            float p = (j & 1) ? pb : pa;
            acc0 = fmaf(p, Vs[j][lane], acc0);
            acc1 = fmaf(p, Vs[j][lane + 32], acc1);
            acc2 = fmaf(p, Vs[j][lane + 64], acc2);
            acc3 = fmaf(p, Vs[j][lane + 96], acc3);
        }
        __half* op = g_xoh + ((size_t)(b * Tq + t)) * DIMq + h * HDq + lane;
        op[0] = __float2half(acc0);
        op[32] = __float2half(acc1);
        op[64] = __float2half(acc2);
        op[96] = __float2half(acc3);
    }
}

// ---------------- launch ----------------
extern "C" void kernel_launch(void* const* d_in, const int* in_sizes, int n_in,
                              void* d_out, int out_size) {
    const float* x   = (const float*)d_in[0];
    const float* wq  = (const float*)d_in[1];
    const float* wk  = (const float*)d_in[2];
    const float* wv  = (const float*)d_in[3];
    const float* wo  = (const float*)d_in[4];
    const float* wiq = (const float*)d_in[5];
    const float* wik = (const float*)d_in[6];
    const float* cwa = (const float*)d_in[7];
    const float* cwb = (const float*)d_in[8];
    float* out = (float*)d_out;

    cudaFuncSetAttribute(gemm_qkv, cudaFuncAttributeMaxDynamicSharedMemorySize, GEMM_SMEM);
    cudaFuncSetAttribute(gemm_f16, cudaFuncAttributeMaxDynamicSharedMemorySize, GEMM_SMEM);
    cudaFuncSetAttribute(attn_kernel, cudaFuncAttributeMaxDynamicSharedMemorySize, ATTN_SMEM);

    float *p_q, *p_k;
    cudaGetSymbolAddress((void**)&p_q, g_q);
    cudaGetSymbolAddress((void**)&p_k, g_k);
    __half *xh, *xoh, *wqkvT, *woT;
    cudaGetSymbolAddress((void**)&xh, g_xh);
    cudaGetSymbolAddress((void**)&xoh, g_xoh);
    cudaGetSymbolAddress((void**)&wqkvT, g_wqkvT);
    cudaGetSymbolAddress((void**)&woT, g_woT);

    // launches 1-5: transposes + convert (6th launch = gemm_qkv, for ncu -s 5)
    transpose_h<<<dim3(DIMq / 32, DIMq / 32), dim3(32, 8)>>>(wq, wqkvT, DIMq, DIMq);
    transpose_h<<<dim3((HKVq * HDq) / 32, DIMq / 32), dim3(32, 8)>>>(wk, wqkvT + (size_t)2048 * DIMq, DIMq, HKVq * HDq);
    transpose_h<<<dim3((HKVq * HDq) / 32, DIMq / 32), dim3(32, 8)>>>(wv, wqkvT + (size_t)2560 * DIMq, DIMq, HKVq * HDq);
    transpose_h<<<dim3(DIMq / 32, DIMq / 32), dim3(32, 8)>>>(wo, woT, DIMq, DIMq);
    conv_h<<<2048, 256>>>(x, xh, (size_t)Mq * DIMq);

    // launch 6: fused QKV projection
    gemm_qkv<<<dim3(NQKV / 128, Mq / 128), 256, GEMM_SMEM>>>(xh, wqkvT);

    // trig + rope
    trig_table_kernel<<<(Tq * 64 + 255) / 256, 256>>>();
    {
        size_t qp = (size_t)Mq * Hq * 64;
        rope_kernel<<<(int)((qp + 255) / 256), 256>>>(p_q, Hq, qp);
        size_t kp = (size_t)Mq * HKVq * 64;
        rope_kernel<<<(int)((kp + 255) / 256), 256>>>(p_k, HKVq, kp);
    }

    // compression + selection
    compress_kernel<<<Bq * HKVq * NBq, 128>>>(cwa, cwb);
    xmean_part_kernel<<<dim3(16, 16, Bq), 128>>>(x);
    xmean_final_kernel<<<Bq * 16, 128>>>();
    kimean_kernel<<<Bq, 128>>>(wik);
    u_kernel<<<Bq * 16, 128>>>(wiq);
    scores_kernel<<<Bq * NBq, 128>>>(x);
    topk_kernel<<<Bq, 256>>>();
    gather_kernel<<<Bq * HKVq * TOPKq, 128>>>();

    // attention
    attn_kernel<<<Bq * Hq * (Tq / 32), 256, ATTN_SMEM>>>();

    // output projection
    gemm_f16<<<dim3(DIMq / 128, Mq / 128), 256, GEMM_SMEM>>>(xoh, woT, out, Mq, DIMq, DIMq);
}

// round 7
// speedup vs baseline: 5.7664x; 1.2641x over previous
#include <cuda_runtime.h>
#include <cuda_fp16.h>
#include <math.h>
#include <cstdint>

#define Bq 2
#define Tq 4096
#define DIMq 2048
#define Hq 16
#define HKVq 4
#define HDq 128
#define NREPq 4
#define Rq 16
#define NBq 256
#define TOPKq 64
#define Mq (Bq * Tq)
#define NQKV 3072

// ---------------- scratch ----------------
__device__ float g_q[Mq * Hq * HDq];
__device__ float g_k[Mq * HKVq * HDq];
__device__ float g_v[Mq * HKVq * HDq];
__device__ float g_ck[Bq * HKVq * NBq * HDq];
__device__ float g_cv[Bq * HKVq * NBq * HDq];
__device__ float g_ksel[Bq * HKVq * TOPKq * HDq];
__device__ float g_vsel[Bq * HKVq * TOPKq * HDq];
__device__ float g_xmean_part[Bq * 16 * DIMq];
__device__ float g_xmean[Bq * DIMq];
__device__ float g_kimean[Bq * HDq];
__device__ float g_u[Bq * DIMq];
__device__ float g_scores[Bq * NBq];
__device__ int   g_topk[Bq * TOPKq];
__device__ float2 g_trig[Tq * 64];

__device__ __half g_xh[Mq * DIMq];
__device__ __half g_xoh[Mq * DIMq];
__device__ __half g_wqkvT[NQKV * DIMq];
__device__ __half g_woT[DIMq * DIMq];

// ---------------- helpers ----------------
__device__ __forceinline__ uint32_t smem_u32(const void* p) {
    uint32_t a;
    asm("{ .reg .u64 t; cvta.to.shared.u64 t, %1; cvt.u32.u64 %0, t; }" : "=r"(a) : "l"(p));
    return a;
}
__device__ __forceinline__ void cp16(uint32_t dst, const void* src) {
    asm volatile("cp.async.cg.shared.global [%0], [%1], 16;" :: "r"(dst), "l"(src));
}
__device__ __forceinline__ void ldsm4(uint32_t& r0, uint32_t& r1, uint32_t& r2, uint32_t& r3,
                                      uint32_t addr) {
    asm volatile("ldmatrix.sync.aligned.m8n8.x4.shared.b16 {%0,%1,%2,%3}, [%4];"
                 : "=r"(r0), "=r"(r1), "=r"(r2), "=r"(r3) : "r"(addr));
}
__device__ __forceinline__ void mma16816(float& c0, float& c1, float& c2, float& c3,
                                         uint32_t a0, uint32_t a1, uint32_t a2, uint32_t a3,
                                         uint32_t b0, uint32_t b1) {
    asm volatile(
        "mma.sync.aligned.m16n8k16.row.col.f32.f16.f16.f32 "
        "{%0,%1,%2,%3}, {%4,%5,%6,%7}, {%8,%9}, {%0,%1,%2,%3};"
        : "+f"(c0), "+f"(c1), "+f"(c2), "+f"(c3)
        : "r"(a0), "r"(a1), "r"(a2), "r"(a3), "r"(b0), "r"(b1));
}

// ---------------- GEMM core ----------------
#define NSTAGE 3
#define STAGE_BYTES 32768
#define GEMM_SMEM (NSTAGE * STAGE_BYTES)

#define GEMM_MAINLOOP(A_, Bt_, K_)                                                  \
    const int nchunks = (K_) >> 6;                                                  \
    const int wm = (wid & 3) << 5;                                                  \
    const int wn = (wid >> 2) << 6;                                                 \
    float acc[2][8][4];                                                             \
    _Pragma("unroll") for (int i = 0; i < 2; i++)                                   \
        _Pragma("unroll") for (int j = 0; j < 8; j++)                               \
            _Pragma("unroll") for (int c = 0; c < 4; c++) acc[i][j][c] = 0.f;       \
    auto produce = [&](int ci) {                                                    \
        const int slot = ci % NSTAGE;                                               \
        const int kk = ci << 6;                                                     \
        const uint32_t sA = tiles + slot * STAGE_BYTES;                             \
        const uint32_t sB = sA + 16384;                                             \
        _Pragma("unroll") for (int i = 0; i < 4; i++) {                             \
            int ch = tid + (i << 8);                                                \
            int row = ch >> 3;                                                      \
            int c = ch & 7;                                                         \
            uint32_t soff = (row << 7) + (((c ^ (row & 7))) << 4);                  \
            cp16(sA + soff, (A_) + (size_t)(brow + row) * (K_) + kk + c * 8);       \
            cp16(sB + soff, (Bt_) + (size_t)(bcol + row) * (K_) + kk + c * 8);      \
        }                                                                           \
        asm volatile("cp.async.commit_group;" ::: "memory");                        \
    };                                                                              \
    produce(0);                                                                     \
    produce(1);                                                                     \
    for (int ci = 0; ci < nchunks; ci++) {                                          \
        if (ci + 1 < nchunks)                                                       \
            asm volatile("cp.async.wait_group 1;" ::: "memory");                    \
        else                                                                        \
            asm volatile("cp.async.wait_group 0;" ::: "memory");                    \
        __syncthreads();                                                            \
        if (ci + 2 < nchunks) produce(ci + 2);                                      \
        const int slot = ci % NSTAGE;                                               \
        const uint32_t sA = tiles + slot * STAGE_BYTES;                             \
        const uint32_t sB = sA + 16384;                                             \
        _Pragma("unroll") for (int ks = 0; ks < 4; ks++) {                          \
            const int kc = (ks << 1) + (lane >> 4);                                 \
            uint32_t a[2][4];                                                       \
            _Pragma("unroll") for (int ma = 0; ma < 2; ma++) {                      \
                int row = wm + (ma << 4) + (lane & 15);                             \
                uint32_t addr = sA + (row << 7) + ((kc ^ (row & 7)) << 4);          \
                ldsm4(a[ma][0], a[ma][1], a[ma][2], a[ma][3], addr);                \
            }                                                                       \
            uint32_t b[4][4];                                                       \
            _Pragma("unroll") for (int nb = 0; nb < 4; nb++) {                      \
                int row = wn + (nb << 4) + (lane & 15);                             \
                uint32_t addr = sB + (row << 7) + ((kc ^ (row & 7)) << 4);          \
                ldsm4(b[nb][0], b[nb][1], b[nb][2], b[nb][3], addr);                \
            }                                                                       \
            _Pragma("unroll") for (int ma = 0; ma < 2; ma++)                        \
                _Pragma("unroll") for (int j = 0; j < 8; j++) {                     \
                    int nb = j >> 1, sel = j & 1;                                   \
                    mma16816(acc[ma][j][0], acc[ma][j][1], acc[ma][j][2],           \
                             acc[ma][j][3], a[ma][0], a[ma][1], a[ma][2],           \
                             a[ma][3], b[nb][sel], b[nb][sel + 2]);                 \
                }                                                                   \
        }                                                                           \
    }

// fused QKV projection + RoPE epilogue
__global__ __launch_bounds__(256, 2)
void gemm_qkv(const __half* __restrict__ A, const __half* __restrict__ Bt) {
    extern __shared__ char smem[];
    const uint32_t tiles = smem_u32(smem);
    const int tid = threadIdx.x;
    const int wid = tid >> 5;
    const int lane = tid & 31;
    const int brow = blockIdx.y << 7;
    const int bcol = blockIdx.x << 7;

    GEMM_MAINLOOP(A, Bt, DIMq)

    float* Cout;
    int cbase, cstride;
    bool dorope;
    if (bcol < 2048)      { Cout = g_q; cbase = bcol;        cstride = 2048; dorope = true; }
    else if (bcol < 2560) { Cout = g_k; cbase = bcol - 2048; cstride = 512;  dorope = true; }
    else                  { Cout = g_v; cbase = bcol - 2560; cstride = 512;  dorope = false; }

    const int g = lane >> 2;
    const int tg = lane & 3;
#pragma unroll
    for (int ma = 0; ma < 2; ma++) {
#pragma unroll
        for (int j = 0; j < 8; j++) {
            int row = brow + wm + (ma << 4) + g;
            int col = cbase + wn + (j << 3) + (tg << 1);
            float2 lo = make_float2(acc[ma][j][0], acc[ma][j][1]);
            float2 hi = make_float2(acc[ma][j][2], acc[ma][j][3]);
            if (dorope) {
                int p = (col & 127) >> 1;
                float2 c1 = g_trig[((row & (Tq - 1)) << 6) + p];
                float2 c2 = g_trig[(((row + 8) & (Tq - 1)) << 6) + p];
                lo = make_float2(lo.x * c1.x - lo.y * c1.y, lo.x * c1.y + lo.y * c1.x);
                hi = make_float2(hi.x * c2.x - hi.y * c2.y, hi.x * c2.y + hi.y * c2.x);
            }
            *reinterpret_cast<float2*>(Cout + (size_t)row * cstride + col) = lo;
            *reinterpret_cast<float2*>(Cout + (size_t)(row + 8) * cstride + col) = hi;
        }
    }
}

// generic GEMM (output projection)
__global__ __launch_bounds__(256, 2)
void gemm_f16(const __half* __restrict__ A, const __half* __restrict__ Bt,
              float* __restrict__ C, int M, int N, int K) {
    extern __shared__ char smem[];
    const uint32_t tiles = smem_u32(smem);
    const int tid = threadIdx.x;
    const int wid = tid >> 5;
    const int lane = tid & 31;
    const int brow = blockIdx.y << 7;
    const int bcol = blockIdx.x << 7;

    GEMM_MAINLOOP(A, Bt, K)

    const int g = lane >> 2;
    const int tg = lane & 3;
#pragma unroll
    for (int ma = 0; ma < 2; ma++) {
#pragma unroll
        for (int j = 0; j < 8; j++) {
            int row = brow + wm + (ma << 4) + g;
            int col = bcol + wn + (j << 3) + (tg << 1);
            float2 lo = make_float2(acc[ma][j][0], acc[ma][j][1]);
            float2 hi = make_float2(acc[ma][j][2], acc[ma][j][3]);
            *reinterpret_cast<float2*>(C + (size_t)row * N + col) = lo;
            *reinterpret_cast<float2*>(C + (size_t)(row + 8) * N + col) = hi;
        }
    }
}

// ---------------- fp32 -> fp16 convert ----------------
__global__ void conv_h(const float* __restrict__ src, __half* __restrict__ dst, size_t n) {
    size_t i = ((size_t)blockIdx.x * blockDim.x + threadIdx.x) * 4;
    size_t stride = (size_t)gridDim.x * blockDim.x * 4;
    for (; i < n; i += stride) {
        float4 v = *reinterpret_cast<const float4*>(src + i);
        *reinterpret_cast<__half2*>(dst + i) = __floats2half2_rn(v.x, v.y);
        *reinterpret_cast<__half2*>(dst + i + 2) = __floats2half2_rn(v.z, v.w);
    }
}

// transpose + convert: w [K,N] fp32 -> wT [N,K] fp16
__global__ void transpose_h(const float* __restrict__ w, __half* __restrict__ wT,
                            int K, int N) {
    __shared__ float t[32][33];
    int n0 = blockIdx.x << 5, k0 = blockIdx.y << 5;
    int tx = threadIdx.x, ty = threadIdx.y;
#pragma unroll
    for (int j = 0; j < 4; j++)
        t[ty + j * 8][tx] = w[(size_t)(k0 + ty + j * 8) * N + n0 + tx];
    __syncthreads();
#pragma unroll
    for (int j = 0; j < 4; j++) {
        int n = n0 + ty + j * 8;
        wT[(size_t)n * K + k0 + tx] = __float2half(t[tx][ty + j * 8]);
    }
}

// ---------------- trig table ----------------
__global__ void trig_table_kernel() {
    int idx = blockIdx.x * blockDim.x + threadIdx.x;
    if (idx >= Tq * 64) return;
    int p = idx & 63;
    int t = idx >> 6;
    double freq = exp(-((double)p / 64.0) * log(10000.0));
    double ang = (double)t * freq;
    double sd, cd;
    sincos(ang, &sd, &cd);
    g_trig[idx] = make_float2((float)cd, (float)sd);
}

// ---------------- block compression (parallel dots + warp softmax) ----------------
__global__ void compress_kernel(const float* __restrict__ cwa, const float* __restrict__ cwb) {
    int n = blockIdx.x % NBq;
    int hk = (blockIdx.x / NBq) % HKVq;
    int b = blockIdx.x / (NBq * HKVq);
    __shared__ float kb[Rq][HDq + 4];
    __shared__ float vb[Rq][HDq + 4];
    __shared__ float sa[Rq], sb[Rq], w[Rq];
    int d = threadIdx.x;
    for (int r = 0; r < Rq; r++) {
        int t = n * Rq + r;
        size_t off = ((size_t)(b * Tq + t)) * (HKVq * HDq) + hk * HDq + d;
        kb[r][d] = g_k[off];
        vb[r][d] = g_v[off];
    }
    __syncthreads();
    {
        int grp = d >> 3, sub = d & 7;
        float da = 0.f, db = 0.f;
        for (int i = sub; i < HDq; i += 8) {
            float kv = kb[grp][i];
            da = fmaf(kv, __ldg(cwa + i), da);
            db = fmaf(kv, __ldg(cwb + i), db);
        }
#pragma unroll
        for (int o = 4; o > 0; o >>= 1) {
            da += __shfl_down_sync(0xffffffffu, da, o, 8);
            db += __shfl_down_sync(0xffffffffu, db, o, 8);
        }
        if (sub == 0) { sa[grp] = da; sb[grp] = db; }
    }
    __syncthreads();
    if (d < 16) {
        float a = sa[d], bb = sb[d];
        float ma = a, mb = bb;
#pragma unroll
        for (int o = 8; o > 0; o >>= 1) {
            ma = fmaxf(ma, __shfl_xor_sync(0x0000ffffu, ma, o, 16));
            mb = fmaxf(mb, __shfl_xor_sync(0x0000ffffu, mb, o, 16));
        }
        float ea = expf(a - ma), eb = expf(bb - mb);
        float sua = ea, sub2 = eb;
#pragma unroll
        for (int o = 8; o > 0; o >>= 1) {
            sua += __shfl_xor_sync(0x0000ffffu, sua, o, 16);
            sub2 += __shfl_xor_sync(0x0000ffffu, sub2, o, 16);
        }
        w[d] = 0.5f * (ea / sua + eb / sub2);
    }
    __syncthreads();
    float ck = 0.f, cv = 0.f;
#pragma unroll
    for (int r = 0; r < Rq; r++) {
        ck = fmaf(w[r], kb[r][d], ck);
        cv = fmaf(w[r], vb[r][d], cv);
    }
    size_t o = ((size_t)((b * HKVq + hk) * NBq + n)) * HDq + d;
    g_ck[o] = ck;
    g_cv[o] = cv;
}

// ---------------- selection chain ----------------
__global__ void xmean_part_kernel(const float* __restrict__ x) {
    int b = blockIdx.z;
    int chunk = blockIdx.y;
    int c = blockIdx.x * 128 + threadIdx.x;
    float s = 0.f;
    for (int tt = chunk * 256; tt < (chunk + 1) * 256; tt++)
        s += x[((size_t)(b * Tq + tt)) * DIMq + c];
    g_xmean_part[((size_t)(b * 16 + chunk)) * DIMq + c] = s;
}
__global__ void xmean_final_kernel() {
    int b = blockIdx.x / 16;
    int c = (blockIdx.x % 16) * 128 + threadIdx.x;
    float s = 0.f;
    for (int ch = 0; ch < 16; ch++) s += g_xmean_part[((size_t)(b * 16 + ch)) * DIMq + c];
    g_xmean[b * DIMq + c] = s * (1.0f / (float)Tq);
}
__global__ void kimean_kernel(const float* __restrict__ wik) {
    int b = blockIdx.x;
    int d = threadIdx.x;
    float s = 0.f;
    for (int c = 0; c < DIMq; c++) s += g_xmean[b * DIMq + c] * wik[(size_t)c * HDq + d];
    g_kimean[b * HDq + d] = s;
}
__global__ void u_kernel(const float* __restrict__ wiq) {
    int b = blockIdx.x / 16;
    int c = (blockIdx.x % 16) * 128 + threadIdx.x;
    float s = 0.f;
    for (int d = 0; d < HDq; d++) s += wiq[(size_t)c * HDq + d] * g_kimean[b * HDq + d];
    g_u[b * DIMq + c] = s;
}
__global__ void scores_kernel(const float* __restrict__ x) {
    int t = blockIdx.x % NBq;
    int b = blockIdx.x / NBq;
    __shared__ float red[128];
    float s = 0.f;
    const float* xp = x + ((size_t)(b * Tq + t)) * DIMq;
    const float* up = g_u + b * DIMq;
    for (int c = threadIdx.x; c < DIMq; c += 128) s += xp[c] * up[c];
    red[threadIdx.x] = s;
    __syncthreads();
    for (int off = 64; off > 0; off >>= 1) {
        if (threadIdx.x < off) red[threadIdx.x] += red[threadIdx.x + off];
        __syncthreads();
    }
    if (threadIdx.x == 0) g_scores[b * NBq + t] = red[0];
}
// one-pass rank selection (top-64 of 256; downstream is order-invariant)
__global__ void topk_kernel() {
    int b = blockIdx.x;
    int t = threadIdx.x;
    __shared__ float sc[256];
    sc[t] = g_scores[b * NBq + t];
    __syncthreads();
    float v = sc[t];
    int rank = 0;
    for (int j = 0; j < 256; j++) {
        float o = sc[j];
        rank += (o > v) || (o == v && j < t);
    }
    if (rank < TOPKq) g_topk[b * TOPKq + rank] = t;
}
__global__ void gather_kernel() {
    int j = blockIdx.x % TOPKq;
    int hk = (blockIdx.x / TOPKq) % HKVq;
    int b = blockIdx.x / (TOPKq * HKVq);
    int d = threadIdx.x;
    int n = g_topk[b * TOPKq + j];
    size_t src = ((size_t)((b * HKVq + hk) * NBq + n)) * HDq + d;
    size_t dst = ((size_t)((b * HKVq + hk) * TOPKq + j)) * HDq + d;
    g_ksel[dst] = g_ck[src];
    g_vsel[dst] = g_cv[src];
}

// ---------------- attention (transposed K, conflict-free, query-pair sharing) ----------------
#define ATTN_SMEM (128 * 66 * 4 + 64 * 132 * 4)
__global__ __launch_bounds__(256)
void attn_kernel() {
    extern __shared__ char asmem[];
    float (*Kt)[66] = reinterpret_cast<float(*)[66]>(asmem);           // [d][key]
    float (*Vs)[132] = reinterpret_cast<float(*)[132]>(asmem + 128 * 66 * 4);

    int ntiles = Tq / 32;
    int tile = blockIdx.x % ntiles;
    int h = (blockIdx.x / ntiles) % Hq;
    int b = blockIdx.x / (ntiles * Hq);
    int hk = h / NREPq;

    const float* kselp = g_ksel + ((size_t)(b * HKVq + hk)) * TOPKq * HDq;
    const float* vselp = g_vsel + ((size_t)(b * HKVq + hk)) * TOPKq * HDq;
    int lane = threadIdx.x & 31;
    int warp = threadIdx.x >> 5;

    // K transposed into smem: lane <-> key j, warp strides d-chunks (conflict-free STS)
#pragma unroll
    for (int half = 0; half < 2; half++) {
        int j = lane + (half << 5);
        const float4* krow = reinterpret_cast<const float4*>(kselp + (size_t)j * HDq);
        for (int c = warp; c < 32; c += 8) {
            float4 kv = __ldg(krow + c);
            Kt[c * 4 + 0][j] = kv.x;
            Kt[c * 4 + 1][j] = kv.y;
            Kt[c * 4 + 2][j] = kv.z;
            Kt[c * 4 + 3][j] = kv.w;
        }
    }
    // V padded rows (coalesced loads, conflict-free reads)
    for (int idx = threadIdx.x; idx < TOPKq * 32; idx += 256) {
        int r = idx >> 5, c = idx & 31;
        float4 v = __ldg(reinterpret_cast<const float4*>(vselp + (size_t)r * HDq + c * 4));
        Vs[r][c * 4 + 0] = v.x;
        Vs[r][c * 4 + 1] = v.y;
        Vs[r][c * 4 + 2] = v.z;
        Vs[r][c * 4 + 3] = v.w;
    }
    __syncthreads();

    const float scale = 0.08838834764831845f;
    const int j0 = lane << 1;

#pragma unroll
    for (int pp = 0; pp < 2; pp++) {
        int t = tile * 32 + warp * 4 + pp * 2;
        const float4* qa = reinterpret_cast<const float4*>(
            g_q + ((size_t)(b * Tq + t)) * (Hq * HDq) + h * HDq);
        const float4* qb = qa + (Hq * HDq) / 4;
        float s0a = 0.f, s1a = 0.f, s0b = 0.f, s1b = 0.f;
#pragma unroll 4
        for (int i = 0; i < 32; i++) {
            float4 qav = __ldg(qa + i);
            float4 qbv = __ldg(qb + i);
#pragma unroll
            for (int ii = 0; ii < 4; ii++) {
                float2 k2 = *reinterpret_cast<const float2*>(&Kt[i * 4 + ii][j0]);
                float qas = (ii == 0) ? qav.x : (ii == 1) ? qav.y : (ii == 2) ? qav.z : qav.w;
                float qbs = (ii == 0) ? qbv.x : (ii == 1) ? qbv.y : (ii == 2) ? qbv.z : qbv.w;
                s0a = fmaf(qas, k2.x, s0a);
                s1a = fmaf(qas, k2.y, s1a);
                s0b = fmaf(qbs, k2.x, s0b);
                s1b = fmaf(qbs, k2.y, s1b);
            }
        }
        s0a *= scale; s1a *= scale; s0b *= scale; s1b *= scale;

        float ma = fmaxf(s0a, s1a);
        float mb = fmaxf(s0b, s1b);
#pragma unroll
        for (int o = 16; o > 0; o >>= 1) {
            ma = fmaxf(ma, __shfl_xor_sync(0xffffffffu, ma, o));
            mb = fmaxf(mb, __shfl_xor_sync(0xffffffffu, mb, o));
        }
        float e0a = expf(s0a - ma), e1a = expf(s1a - ma);
        float e0b = expf(s0b - mb), e1b = expf(s1b - mb);
        float sua = e0a + e1a, sub = e0b + e1b;
#pragma unroll
        for (int o = 16; o > 0; o >>= 1) {
            sua += __shfl_xor_sync(0xffffffffu, sua, o);
            sub += __shfl_xor_sync(0xffffffffu, sub, o);
        }
        float inva = 1.f / sua, invb = 1.f / sub;
        e0a *= inva; e1a *= inva; e0b *= invb; e1b *= invb;

        float aa0 = 0.f, aa1 = 0.f, aa2 = 0.f, aa3 = 0.f;
        float ab0 = 0.f, ab1 = 0.f, ab2 = 0.f, ab3 = 0.f;
#pragma unroll 4
        for (int j2 = 0; j2 < 32; j2++) {
            float pa0 = __shfl_sync(0xffffffffu, e0a, j2);
            float pa1 = __shfl_sync(0xffffffffu, e1a, j2);
            float pb0 = __shfl_sync(0xffffffffu, e0b, j2);
            float pb1 = __shfl_sync(0xffffffffu, e1b, j2);
            int j = j2 << 1;
            float v0 = Vs[j][lane], v1 = Vs[j][lane + 32];
            float v2 = Vs[j][lane + 64], v3 = Vs[j][lane + 96];
            aa0 = fmaf(pa0, v0, aa0); aa1 = fmaf(pa0, v1, aa1);
            aa2 = fmaf(pa0, v2, aa2); aa3 = fmaf(pa0, v3, aa3);
            ab0 = fmaf(pb0, v0, ab0); ab1 = fmaf(pb0, v1, ab1);
            ab2 = fmaf(pb0, v2, ab2); ab3 = fmaf(pb0, v3, ab3);
            v0 = Vs[j + 1][lane]; v1 = Vs[j + 1][lane + 32];
            v2 = Vs[j + 1][lane + 64]; v3 = Vs[j + 1][lane + 96];
            aa0 = fmaf(pa1, v0, aa0); aa1 = fmaf(pa1, v1, aa1);
            aa2 = fmaf(pa1, v2, aa2); aa3 = fmaf(pa1, v3, aa3);
            ab0 = fmaf(pb1, v0, ab0); ab1 = fmaf(pb1, v1, ab1);
            ab2 = fmaf(pb1, v2, ab2); ab3 = fmaf(pb1, v3, ab3);
        }
        __half* opa = g_xoh + ((size_t)(b * Tq + t)) * DIMq + h * HDq + lane;
        opa[0] = __float2half(aa0);
        opa[32] = __float2half(aa1);
        opa[64] = __float2half(aa2);
        opa[96] = __float2half(aa3);
        __half* opb = opa + DIMq;
        opb[0] = __float2half(ab0);
        opb[32] = __float2half(ab1);
        opb[64] = __float2half(ab2);
        opb[96] = __float2half(ab3);
    }
}

// ---------------- launch ----------------
extern "C" void kernel_launch(void* const* d_in, const int* in_sizes, int n_in,
                              void* d_out, int out_size) {
    const float* x   = (const float*)d_in[0];
    const float* wq  = (const float*)d_in[1];
    const float* wk  = (const float*)d_in[2];
    const float* wv  = (const float*)d_in[3];
    const float* wo  = (const float*)d_in[4];
    const float* wiq = (const float*)d_in[5];
    const float* wik = (const float*)d_in[6];
    const float* cwa = (const float*)d_in[7];
    const float* cwb = (const float*)d_in[8];
    float* out = (float*)d_out;

    cudaFuncSetAttribute(gemm_qkv, cudaFuncAttributeMaxDynamicSharedMemorySize, GEMM_SMEM);
    cudaFuncSetAttribute(gemm_f16, cudaFuncAttributeMaxDynamicSharedMemorySize, GEMM_SMEM);
    cudaFuncSetAttribute(attn_kernel, cudaFuncAttributeMaxDynamicSharedMemorySize, ATTN_SMEM);

    __half *xh, *xoh, *wqkvT, *woT;
    cudaGetSymbolAddress((void**)&xh, g_xh);
    cudaGetSymbolAddress((void**)&xoh, g_xoh);
    cudaGetSymbolAddress((void**)&wqkvT, g_wqkvT);
    cudaGetSymbolAddress((void**)&woT, g_woT);

    // launches 1-5 (6th = gemm_qkv for ncu -s 5 -c 1)
    trig_table_kernel<<<(Tq * 64 + 255) / 256, 256>>>();
    transpose_h<<<dim3(DIMq / 32, DIMq / 32), dim3(32, 8)>>>(wq, wqkvT, DIMq, DIMq);
    transpose_h<<<dim3((HKVq * HDq) / 32, DIMq / 32), dim3(32, 8)>>>(wk, wqkvT + (size_t)2048 * DIMq, DIMq, HKVq * HDq);
    transpose_h<<<dim3((HKVq * HDq) / 32, DIMq / 32), dim3(32, 8)>>>(wv, wqkvT + (size_t)2560 * DIMq, DIMq, HKVq * HDq);
    conv_h<<<2048, 256>>>(x, xh, (size_t)Mq * DIMq);

    // launch 6: fused QKV projection + RoPE
    gemm_qkv<<<dim3(NQKV / 128, Mq / 128), 256, GEMM_SMEM>>>(xh, wqkvT);

    transpose_h<<<dim3(DIMq / 32, DIMq / 32), dim3(32, 8)>>>(wo, woT, DIMq, DIMq);

    // compression + selection
    compress_kernel<<<Bq * HKVq * NBq, 128>>>(cwa, cwb);
    xmean_part_kernel<<<dim3(16, 16, Bq), 128>>>(x);
    xmean_final_kernel<<<Bq * 16, 128>>>();
    kimean_kernel<<<Bq, 128>>>(wik);
    u_kernel<<<Bq * 16, 128>>>(wiq);
    scores_kernel<<<Bq * NBq, 128>>>(x);
    topk_kernel<<<Bq, 256>>>();
    gather_kernel<<<Bq * HKVq * TOPKq, 128>>>();

    // attention
    attn_kernel<<<Bq * Hq * (Tq / 32), 256, ATTN_SMEM>>>();

    // output projection
    gemm_f16<<<dim3(DIMq / 128, Mq / 128), 256, GEMM_SMEM>>>(xoh, woT, out, Mq, DIMq, DIMq);
}

// round 8
// speedup vs baseline: 6.9317x; 1.2021x over previous
#include <cuda_runtime.h>
#include <cuda_fp16.h>
#include <math.h>
#include <cstdint>

#define Bq 2
#define Tq 4096
#define DIMq 2048
#define Hq 16
#define HKVq 4
#define HDq 128
#define NREPq 4
#define Rq 16
#define NBq 256
#define TOPKq 64
#define Mq (Bq * Tq)
#define NQKV 3072

// ---------------- scratch ----------------
__device__ float g_q[Mq * Hq * HDq];
__device__ float g_k[Mq * HKVq * HDq];
__device__ float g_v[Mq * HKVq * HDq];
__device__ float g_ck[Bq * HKVq * NBq * HDq];
__device__ float g_cv[Bq * HKVq * NBq * HDq];
__device__ float g_ksel[Bq * HKVq * TOPKq * HDq];
__device__ float g_vsel[Bq * HKVq * TOPKq * HDq];
__device__ float g_xmean_part[Bq * 16 * DIMq];
__device__ float g_xmean[Bq * DIMq];
__device__ float g_kimean[Bq * HDq];
__device__ float g_u[Bq * DIMq];
__device__ float g_scores[Bq * NBq];
__device__ int   g_topk[Bq * TOPKq];
__device__ float2 g_trig[Tq * 64];

__device__ __half g_xh[Mq * DIMq];
__device__ __half g_xoh[Mq * DIMq];
__device__ __half g_wqkvT[NQKV * DIMq];
__device__ __half g_woT[DIMq * DIMq];

// ---------------- helpers ----------------
__device__ __forceinline__ uint32_t smem_u32(const void* p) {
    uint32_t a;
    asm("{ .reg .u64 t; cvta.to.shared.u64 t, %1; cvt.u32.u64 %0, t; }" : "=r"(a) : "l"(p));
    return a;
}
__device__ __forceinline__ void cp16(uint32_t dst, const void* src) {
    asm volatile("cp.async.cg.shared.global [%0], [%1], 16;" :: "r"(dst), "l"(src));
}
__device__ __forceinline__ void ldsm4(uint32_t& r0, uint32_t& r1, uint32_t& r2, uint32_t& r3,
                                      uint32_t addr) {
    asm volatile("ldmatrix.sync.aligned.m8n8.x4.shared.b16 {%0,%1,%2,%3}, [%4];"
                 : "=r"(r0), "=r"(r1), "=r"(r2), "=r"(r3) : "r"(addr));
}
__device__ __forceinline__ void mma16816(float& c0, float& c1, float& c2, float& c3,
                                         uint32_t a0, uint32_t a1, uint32_t a2, uint32_t a3,
                                         uint32_t b0, uint32_t b1) {
    asm volatile(
        "mma.sync.aligned.m16n8k16.row.col.f32.f16.f16.f32 "
        "{%0,%1,%2,%3}, {%4,%5,%6,%7}, {%8,%9}, {%0,%1,%2,%3};"
        : "+f"(c0), "+f"(c1), "+f"(c2), "+f"(c3)
        : "r"(a0), "r"(a1), "r"(a2), "r"(a3), "r"(b0), "r"(b1));
}

// ---------------- GEMM core ----------------
#define NSTAGE 3
#define STAGE_BYTES 32768
#define GEMM_SMEM (NSTAGE * STAGE_BYTES)

#define GEMM_MAINLOOP(A_, Bt_, K_)                                                  \
    const int nchunks = (K_) >> 6;                                                  \
    const int wm = (wid & 3) << 5;                                                  \
    const int wn = (wid >> 2) << 6;                                                 \
    float acc[2][8][4];                                                             \
    _Pragma("unroll") for (int i = 0; i < 2; i++)                                   \
        _Pragma("unroll") for (int j = 0; j < 8; j++)                               \
            _Pragma("unroll") for (int c = 0; c < 4; c++) acc[i][j][c] = 0.f;       \
    auto produce = [&](int ci) {                                                    \
        const int slot = ci % NSTAGE;                                               \
        const int kk = ci << 6;                                                     \
        const uint32_t sA = tiles + slot * STAGE_BYTES;                             \
        const uint32_t sB = sA + 16384;                                             \
        _Pragma("unroll") for (int i = 0; i < 4; i++) {                             \
            int ch = tid + (i << 8);                                                \
            int row = ch >> 3;                                                      \
            int c = ch & 7;                                                         \
            uint32_t soff = (row << 7) + (((c ^ (row & 7))) << 4);                  \
            cp16(sA + soff, (A_) + (size_t)(brow + row) * (K_) + kk + c * 8);       \
            cp16(sB + soff, (Bt_) + (size_t)(bcol + row) * (K_) + kk + c * 8);      \
        }                                                                           \
        asm volatile("cp.async.commit_group;" ::: "memory");                        \
    };                                                                              \
    produce(0);                                                                     \
    produce(1);                                                                     \
    for (int ci = 0; ci < nchunks; ci++) {                                          \
        if (ci + 1 < nchunks)                                                       \
            asm volatile("cp.async.wait_group 1;" ::: "memory");                    \
        else                                                                        \
            asm volatile("cp.async.wait_group 0;" ::: "memory");                    \
        __syncthreads();                                                            \
        if (ci + 2 < nchunks) produce(ci + 2);                                      \
        const int slot = ci % NSTAGE;                                               \
        const uint32_t sA = tiles + slot * STAGE_BYTES;                             \
        const uint32_t sB = sA + 16384;                                             \
        _Pragma("unroll") for (int ks = 0; ks < 4; ks++) {                          \
            const int kc = (ks << 1) + (lane >> 4);                                 \
            uint32_t a[2][4];                                                       \
            _Pragma("unroll") for (int ma = 0; ma < 2; ma++) {                      \
                int row = wm + (ma << 4) + (lane & 15);                             \
                uint32_t addr = sA + (row << 7) + ((kc ^ (row & 7)) << 4);          \
                ldsm4(a[ma][0], a[ma][1], a[ma][2], a[ma][3], addr);                \
            }                                                                       \
            uint32_t b[4][4];                                                       \
            _Pragma("unroll") for (int nb = 0; nb < 4; nb++) {                      \
                int row = wn + (nb << 4) + (lane & 15);                             \
                uint32_t addr = sB + (row << 7) + ((kc ^ (row & 7)) << 4);          \
                ldsm4(b[nb][0], b[nb][1], b[nb][2], b[nb][3], addr);                \
            }                                                                       \
            _Pragma("unroll") for (int ma = 0; ma < 2; ma++)                        \
                _Pragma("unroll") for (int j = 0; j < 8; j++) {                     \
                    int nb = j >> 1, sel = j & 1;                                   \
                    mma16816(acc[ma][j][0], acc[ma][j][1], acc[ma][j][2],           \
                             acc[ma][j][3], a[ma][0], a[ma][1], a[ma][2],           \
                             a[ma][3], b[nb][sel], b[nb][sel + 2]);                 \
                }                                                                   \
        }                                                                           \
    }

// fused QKV projection + RoPE epilogue
__global__ __launch_bounds__(256, 2)
void gemm_qkv(const __half* __restrict__ A, const __half* __restrict__ Bt) {
    extern __shared__ char smem[];
    const uint32_t tiles = smem_u32(smem);
    const int tid = threadIdx.x;
    const int wid = tid >> 5;
    const int lane = tid & 31;
    const int brow = blockIdx.y << 7;
    const int bcol = blockIdx.x << 7;

    GEMM_MAINLOOP(A, Bt, DIMq)

    float* Cout;
    int cbase, cstride;
    bool dorope;
    if (bcol < 2048)      { Cout = g_q; cbase = bcol;        cstride = 2048; dorope = true; }
    else if (bcol < 2560) { Cout = g_k; cbase = bcol - 2048; cstride = 512;  dorope = true; }
    else                  { Cout = g_v; cbase = bcol - 2560; cstride = 512;  dorope = false; }

    const int g = lane >> 2;
    const int tg = lane & 3;
#pragma unroll
    for (int ma = 0; ma < 2; ma++) {
#pragma unroll
        for (int j = 0; j < 8; j++) {
            int row = brow + wm + (ma << 4) + g;
            int col = cbase + wn + (j << 3) + (tg << 1);
            float2 lo = make_float2(acc[ma][j][0], acc[ma][j][1]);
            float2 hi = make_float2(acc[ma][j][2], acc[ma][j][3]);
            if (dorope) {
                int p = (col & 127) >> 1;
                float2 c1 = g_trig[((row & (Tq - 1)) << 6) + p];
                float2 c2 = g_trig[(((row + 8) & (Tq - 1)) << 6) + p];
                lo = make_float2(lo.x * c1.x - lo.y * c1.y, lo.x * c1.y + lo.y * c1.x);
                hi = make_float2(hi.x * c2.x - hi.y * c2.y, hi.x * c2.y + hi.y * c2.x);
            }
            *reinterpret_cast<float2*>(Cout + (size_t)row * cstride + col) = lo;
            *reinterpret_cast<float2*>(Cout + (size_t)(row + 8) * cstride + col) = hi;
        }
    }
}

// generic GEMM (output projection)
__global__ __launch_bounds__(256, 2)
void gemm_f16(const __half* __restrict__ A, const __half* __restrict__ Bt,
              float* __restrict__ C, int M, int N, int K) {
    extern __shared__ char smem[];
    const uint32_t tiles = smem_u32(smem);
    const int tid = threadIdx.x;
    const int wid = tid >> 5;
    const int lane = tid & 31;
    const int brow = blockIdx.y << 7;
    const int bcol = blockIdx.x << 7;

    GEMM_MAINLOOP(A, Bt, K)

    const int g = lane >> 2;
    const int tg = lane & 3;
#pragma unroll
    for (int ma = 0; ma < 2; ma++) {
#pragma unroll
        for (int j = 0; j < 8; j++) {
            int row = brow + wm + (ma << 4) + g;
            int col = bcol + wn + (j << 3) + (tg << 1);
            float2 lo = make_float2(acc[ma][j][0], acc[ma][j][1]);
            float2 hi = make_float2(acc[ma][j][2], acc[ma][j][3]);
            *reinterpret_cast<float2*>(C + (size_t)row * N + col) = lo;
            *reinterpret_cast<float2*>(C + (size_t)(row + 8) * N + col) = hi;
        }
    }
}

// ---------------- fp32 -> fp16 convert ----------------
__global__ void conv_h(const float* __restrict__ src, __half* __restrict__ dst, size_t n) {
    size_t i = ((size_t)blockIdx.x * blockDim.x + threadIdx.x) * 4;
    size_t stride = (size_t)gridDim.x * blockDim.x * 4;
    for (; i < n; i += stride) {
        float4 v = *reinterpret_cast<const float4*>(src + i);
        *reinterpret_cast<__half2*>(dst + i) = __floats2half2_rn(v.x, v.y);
        *reinterpret_cast<__half2*>(dst + i + 2) = __floats2half2_rn(v.z, v.w);
    }
}

// transpose + convert: w [K,N] fp32 -> wT [N,K] fp16
__global__ void transpose_h(const float* __restrict__ w, __half* __restrict__ wT,
                            int K, int N) {
    __shared__ float t[32][33];
    int n0 = blockIdx.x << 5, k0 = blockIdx.y << 5;
    int tx = threadIdx.x, ty = threadIdx.y;
#pragma unroll
    for (int j = 0; j < 4; j++)
        t[ty + j * 8][tx] = w[(size_t)(k0 + ty + j * 8) * N + n0 + tx];
    __syncthreads();
#pragma unroll
    for (int j = 0; j < 4; j++) {
        int n = n0 + ty + j * 8;
        wT[(size_t)n * K + k0 + tx] = __float2half(t[tx][ty + j * 8]);
    }
}

// ---------------- trig table ----------------
__global__ void trig_table_kernel() {
    int idx = blockIdx.x * blockDim.x + threadIdx.x;
    if (idx >= Tq * 64) return;
    int p = idx & 63;
    int t = idx >> 6;
    double freq = exp(-((double)p / 64.0) * log(10000.0));
    double ang = (double)t * freq;
    double sd, cd;
    sincos(ang, &sd, &cd);
    g_trig[idx] = make_float2((float)cd, (float)sd);
}

// ---------------- block compression ----------------
__global__ void compress_kernel(const float* __restrict__ cwa, const float* __restrict__ cwb) {
    int n = blockIdx.x % NBq;
    int hk = (blockIdx.x / NBq) % HKVq;
    int b = blockIdx.x / (NBq * HKVq);
    __shared__ float kb[Rq][HDq + 4];
    __shared__ float vb[Rq][HDq + 4];
    __shared__ float sa[Rq], sb[Rq], w[Rq];
    int d = threadIdx.x;
    for (int r = 0; r < Rq; r++) {
        int t = n * Rq + r;
        size_t off = ((size_t)(b * Tq + t)) * (HKVq * HDq) + hk * HDq + d;
        kb[r][d] = g_k[off];
        vb[r][d] = g_v[off];
    }
    __syncthreads();
    {
        int grp = d >> 3, sub = d & 7;
        float da = 0.f, db = 0.f;
        for (int i = sub; i < HDq; i += 8) {
            float kv = kb[grp][i];
            da = fmaf(kv, __ldg(cwa + i), da);
            db = fmaf(kv, __ldg(cwb + i), db);
        }
#pragma unroll
        for (int o = 4; o > 0; o >>= 1) {
            da += __shfl_down_sync(0xffffffffu, da, o, 8);
            db += __shfl_down_sync(0xffffffffu, db, o, 8);
        }
        if (sub == 0) { sa[grp] = da; sb[grp] = db; }
    }
    __syncthreads();
    if (d < 16) {
        float a = sa[d], bb = sb[d];
        float ma = a, mb = bb;
#pragma unroll
        for (int o = 8; o > 0; o >>= 1) {
            ma = fmaxf(ma, __shfl_xor_sync(0x0000ffffu, ma, o, 16));
            mb = fmaxf(mb, __shfl_xor_sync(0x0000ffffu, mb, o, 16));
        }
        float ea = expf(a - ma), eb = expf(bb - mb);
        float sua = ea, sub2 = eb;
#pragma unroll
        for (int o = 8; o > 0; o >>= 1) {
            sua += __shfl_xor_sync(0x0000ffffu, sua, o, 16);
            sub2 += __shfl_xor_sync(0x0000ffffu, sub2, o, 16);
        }
        w[d] = 0.5f * (ea / sua + eb / sub2);
    }
    __syncthreads();
    float ck = 0.f, cv = 0.f;
#pragma unroll
    for (int r = 0; r < Rq; r++) {
        ck = fmaf(w[r], kb[r][d], ck);
        cv = fmaf(w[r], vb[r][d], cv);
    }
    size_t o = ((size_t)((b * HKVq + hk) * NBq + n)) * HDq + d;
    g_ck[o] = ck;
    g_cv[o] = cv;
}

// ---------------- selection chain ----------------
__global__ void xmean_part_kernel(const float* __restrict__ x) {
    int b = blockIdx.z;
    int chunk = blockIdx.y;
    int c = blockIdx.x * 128 + threadIdx.x;
    float s = 0.f;
    for (int tt = chunk * 256; tt < (chunk + 1) * 256; tt++)
        s += x[((size_t)(b * Tq + tt)) * DIMq + c];
    g_xmean_part[((size_t)(b * 16 + chunk)) * DIMq + c] = s;
}
__global__ void xmean_final_kernel() {
    int b = blockIdx.x / 16;
    int c = (blockIdx.x % 16) * 128 + threadIdx.x;
    float s = 0.f;
    for (int ch = 0; ch < 16; ch++) s += g_xmean_part[((size_t)(b * 16 + ch)) * DIMq + c];
    g_xmean[b * DIMq + c] = s * (1.0f / (float)Tq);
}
__global__ void kimean_kernel(const float* __restrict__ wik) {
    int b = blockIdx.x;
    int d = threadIdx.x;
    float s = 0.f;
    for (int c = 0; c < DIMq; c++) s += g_xmean[b * DIMq + c] * wik[(size_t)c * HDq + d];
    g_kimean[b * HDq + d] = s;
}
__global__ void u_kernel(const float* __restrict__ wiq) {
    int b = blockIdx.x / 16;
    int c = (blockIdx.x % 16) * 128 + threadIdx.x;
    float s = 0.f;
    for (int d = 0; d < HDq; d++) s += wiq[(size_t)c * HDq + d] * g_kimean[b * HDq + d];
    g_u[b * DIMq + c] = s;
}
__global__ void scores_kernel(const float* __restrict__ x) {
    int t = blockIdx.x % NBq;
    int b = blockIdx.x / NBq;
    __shared__ float red[128];
    float s = 0.f;
    const float* xp = x + ((size_t)(b * Tq + t)) * DIMq;
    const float* up = g_u + b * DIMq;
    for (int c = threadIdx.x; c < DIMq; c += 128) s += xp[c] * up[c];
    red[threadIdx.x] = s;
    __syncthreads();
    for (int off = 64; off > 0; off >>= 1) {
        if (threadIdx.x < off) red[threadIdx.x] += red[threadIdx.x + off];
        __syncthreads();
    }
    if (threadIdx.x == 0) g_scores[b * NBq + t] = red[0];
}
__global__ void topk_kernel() {
    int b = blockIdx.x;
    int t = threadIdx.x;
    __shared__ float sc[256];
    sc[t] = g_scores[b * NBq + t];
    __syncthreads();
    float v = sc[t];
    int rank = 0;
    for (int j = 0; j < 256; j++) {
        float o = sc[j];
        rank += (o > v) || (o == v && j < t);
    }
    if (rank < TOPKq) g_topk[b * TOPKq + rank] = t;
}
__global__ void gather_kernel() {
    int j = blockIdx.x % TOPKq;
    int hk = (blockIdx.x / TOPKq) % HKVq;
    int b = blockIdx.x / (TOPKq * HKVq);
    int d = threadIdx.x;
    int n = g_topk[b * TOPKq + j];
    size_t src = ((size_t)((b * HKVq + hk) * NBq + n)) * HDq + d;
    size_t dst = ((size_t)((b * HKVq + hk) * TOPKq + j)) * HDq + d;
    g_ksel[dst] = g_ck[src];
    g_vsel[dst] = g_cv[src];
}

// ---------------- attention (1 CTA per (b,hk,tile), 4 heads share K/V smem) ----------------
#define ATTN_SMEM (128 * 66 * 4 + 64 * 132 * 4)
__global__ __launch_bounds__(256)
void attn_kernel() {
    extern __shared__ char asmem[];
    float (*Kt)[66] = reinterpret_cast<float(*)[66]>(asmem);           // [d][key]
    float (*Vs)[132] = reinterpret_cast<float(*)[132]>(asmem + 128 * 66 * 4);

    int ntiles = Tq / 32;
    int tile = blockIdx.x % ntiles;
    int hk = (blockIdx.x / ntiles) % HKVq;
    int b = blockIdx.x / (ntiles * HKVq);

    const float* kselp = g_ksel + ((size_t)(b * HKVq + hk)) * TOPKq * HDq;
    const float* vselp = g_vsel + ((size_t)(b * HKVq + hk)) * TOPKq * HDq;
    int lane = threadIdx.x & 31;
    int warp = threadIdx.x >> 5;

#pragma unroll
    for (int half = 0; half < 2; half++) {
        int j = lane + (half << 5);
        const float4* krow = reinterpret_cast<const float4*>(kselp + (size_t)j * HDq);
        for (int c = warp; c < 32; c += 8) {
            float4 kv = __ldg(krow + c);
            Kt[c * 4 + 0][j] = kv.x;
            Kt[c * 4 + 1][j] = kv.y;
            Kt[c * 4 + 2][j] = kv.z;
            Kt[c * 4 + 3][j] = kv.w;
        }
    }
    for (int idx = threadIdx.x; idx < TOPKq * 32; idx += 256) {
        int r = idx >> 5, c = idx & 31;
        float4 v = __ldg(reinterpret_cast<const float4*>(vselp + (size_t)r * HDq + c * 4));
        Vs[r][c * 4 + 0] = v.x;
        Vs[r][c * 4 + 1] = v.y;
        Vs[r][c * 4 + 2] = v.z;
        Vs[r][c * 4 + 3] = v.w;
    }
    __syncthreads();

    const float scale = 0.08838834764831845f;
    const int j0 = lane << 1;

#pragma unroll
    for (int hi = 0; hi < NREPq; hi++) {
        int h = hk * NREPq + hi;
#pragma unroll
        for (int pp = 0; pp < 2; pp++) {
            int t = tile * 32 + warp * 4 + pp * 2;
            const float4* qa = reinterpret_cast<const float4*>(
                g_q + ((size_t)(b * Tq + t)) * (Hq * HDq) + h * HDq);
            const float4* qb = qa + (Hq * HDq) / 4;
            float s0a = 0.f, s1a = 0.f, s0b = 0.f, s1b = 0.f;
#pragma unroll 4
            for (int i = 0; i < 32; i++) {
                float4 qav = __ldg(qa + i);
                float4 qbv = __ldg(qb + i);
#pragma unroll
                for (int ii = 0; ii < 4; ii++) {
                    float2 k2 = *reinterpret_cast<const float2*>(&Kt[i * 4 + ii][j0]);
                    float qas = (ii == 0) ? qav.x : (ii == 1) ? qav.y : (ii == 2) ? qav.z : qav.w;
                    float qbs = (ii == 0) ? qbv.x : (ii == 1) ? qbv.y : (ii == 2) ? qbv.z : qbv.w;
                    s0a = fmaf(qas, k2.x, s0a);
                    s1a = fmaf(qas, k2.y, s1a);
                    s0b = fmaf(qbs, k2.x, s0b);
                    s1b = fmaf(qbs, k2.y, s1b);
                }
            }
            s0a *= scale; s1a *= scale; s0b *= scale; s1b *= scale;

            float ma = fmaxf(s0a, s1a);
            float mb = fmaxf(s0b, s1b);
#pragma unroll
            for (int o = 16; o > 0; o >>= 1) {
                ma = fmaxf(ma, __shfl_xor_sync(0xffffffffu, ma, o));
                mb = fmaxf(mb, __shfl_xor_sync(0xffffffffu, mb, o));
            }
            float e0a = expf(s0a - ma), e1a = expf(s1a - ma);
            float e0b = expf(s0b - mb), e1b = expf(s1b - mb);
            float sua = e0a + e1a, sub = e0b + e1b;
#pragma unroll
            for (int o = 16; o > 0; o >>= 1) {
                sua += __shfl_xor_sync(0xffffffffu, sua, o);
                sub += __shfl_xor_sync(0xffffffffu, sub, o);
            }
            float inva = 1.f / sua, invb = 1.f / sub;
            e0a *= inva; e1a *= inva; e0b *= invb; e1b *= invb;

            float aa0 = 0.f, aa1 = 0.f, aa2 = 0.f, aa3 = 0.f;
            float ab0 = 0.f, ab1 = 0.f, ab2 = 0.f, ab3 = 0.f;
#pragma unroll 4
            for (int j2 = 0; j2 < 32; j2++) {
                float pa0 = __shfl_sync(0xffffffffu, e0a, j2);
                float pa1 = __shfl_sync(0xffffffffu, e1a, j2);
                float pb0 = __shfl_sync(0xffffffffu, e0b, j2);
                float pb1 = __shfl_sync(0xffffffffu, e1b, j2);
                int j = j2 << 1;
                float v0 = Vs[j][lane], v1 = Vs[j][lane + 32];
                float v2 = Vs[j][lane + 64], v3 = Vs[j][lane + 96];
                aa0 = fmaf(pa0, v0, aa0); aa1 = fmaf(pa0, v1, aa1);
                aa2 = fmaf(pa0, v2, aa2); aa3 = fmaf(pa0, v3, aa3);
                ab0 = fmaf(pb0, v0, ab0); ab1 = fmaf(pb0, v1, ab1);
                ab2 = fmaf(pb0, v2, ab2); ab3 = fmaf(pb0, v3, ab3);
                v0 = Vs[j + 1][lane]; v1 = Vs[j + 1][lane + 32];
                v2 = Vs[j + 1][lane + 64]; v3 = Vs[j + 1][lane + 96];
                aa0 = fmaf(pa1, v0, aa0); aa1 = fmaf(pa1, v1, aa1);
                aa2 = fmaf(pa1, v2, aa2); aa3 = fmaf(pa1, v3, aa3);
                ab0 = fmaf(pb1, v0, ab0); ab1 = fmaf(pb1, v1, ab1);
                ab2 = fmaf(pb1, v2, ab2); ab3 = fmaf(pb1, v3, ab3);
            }
            __half* opa = g_xoh + ((size_t)(b * Tq + t)) * DIMq + h * HDq + lane;
            opa[0] = __float2half(aa0);
            opa[32] = __float2half(aa1);
            opa[64] = __float2half(aa2);
            opa[96] = __float2half(aa3);
            __half* opb = opa + DIMq;
            opb[0] = __float2half(ab0);
            opb[32] = __float2half(ab1);
            opb[64] = __float2half(ab2);
            opb[96] = __float2half(ab3);
        }
    }
}

// ---------------- launch (multi-stream fork-join, capture-safe) ----------------
extern "C" void kernel_launch(void* const* d_in, const int* in_sizes, int n_in,
                              void* d_out, int out_size) {
    const float* x   = (const float*)d_in[0];
    const float* wq  = (const float*)d_in[1];
    const float* wk  = (const float*)d_in[2];
    const float* wv  = (const float*)d_in[3];
    const float* wo  = (const float*)d_in[4];
    const float* wiq = (const float*)d_in[5];
    const float* wik = (const float*)d_in[6];
    const float* cwa = (const float*)d_in[7];
    const float* cwb = (const float*)d_in[8];
    float* out = (float*)d_out;

    static cudaStream_t s2 = nullptr, s3 = nullptr;
    static cudaEvent_t eFork = nullptr, e2 = nullptr, e3 = nullptr, e4 = nullptr;
    if (!s2) {
        cudaStreamCreateWithFlags(&s2, cudaStreamNonBlocking);
        cudaStreamCreateWithFlags(&s3, cudaStreamNonBlocking);
        cudaEventCreateWithFlags(&eFork, cudaEventDisableTiming);
        cudaEventCreateWithFlags(&e2, cudaEventDisableTiming);
        cudaEventCreateWithFlags(&e3, cudaEventDisableTiming);
        cudaEventCreateWithFlags(&e4, cudaEventDisableTiming);
        cudaFuncSetAttribute(gemm_qkv, cudaFuncAttributeMaxDynamicSharedMemorySize, GEMM_SMEM);
        cudaFuncSetAttribute(gemm_f16, cudaFuncAttributeMaxDynamicSharedMemorySize, GEMM_SMEM);
        cudaFuncSetAttribute(attn_kernel, cudaFuncAttributeMaxDynamicSharedMemorySize, ATTN_SMEM);
    }

    __half *xh, *xoh, *wqkvT, *woT;
    cudaGetSymbolAddress((void**)&xh, g_xh);
    cudaGetSymbolAddress((void**)&xoh, g_xoh);
    cudaGetSymbolAddress((void**)&wqkvT, g_wqkvT);
    cudaGetSymbolAddress((void**)&woT, g_woT);

    // fork side streams from the capturing (legacy) stream
    cudaEventRecord(eFork, 0);
    cudaStreamWaitEvent(s2, eFork, 0);
    cudaStreamWaitEvent(s3, eFork, 0);

    // s2: trig + QKV weight transposes (needed before gemm_qkv), then wo transpose
    trig_table_kernel<<<(Tq * 64 + 255) / 256, 256, 0, s2>>>();
    transpose_h<<<dim3(DIMq / 32, DIMq / 32), dim3(32, 8), 0, s2>>>(wq, wqkvT, DIMq, DIMq);
    transpose_h<<<dim3((HKVq * HDq) / 32, DIMq / 32), dim3(32, 8), 0, s2>>>(wk, wqkvT + (size_t)2048 * DIMq, DIMq, HKVq * HDq);
    transpose_h<<<dim3((HKVq * HDq) / 32, DIMq / 32), dim3(32, 8), 0, s2>>>(wv, wqkvT + (size_t)2560 * DIMq, DIMq, HKVq * HDq);
    cudaEventRecord(e2, s2);
    transpose_h<<<dim3(DIMq / 32, DIMq / 32), dim3(32, 8), 0, s2>>>(wo, woT, DIMq, DIMq);
    cudaEventRecord(e4, s2);

    // s3: selection chain (depends only on x)
    xmean_part_kernel<<<dim3(16, 16, Bq), 128, 0, s3>>>(x);
    xmean_final_kernel<<<Bq * 16, 128, 0, s3>>>();
    kimean_kernel<<<Bq, 128, 0, s3>>>(wik);
    u_kernel<<<Bq * 16, 128, 0, s3>>>(wiq);
    scores_kernel<<<Bq * NBq, 128, 0, s3>>>(x);
    topk_kernel<<<Bq, 256, 0, s3>>>();
    cudaEventRecord(e3, s3);

    // main stream: critical path
    conv_h<<<2048, 256>>>(x, xh, (size_t)Mq * DIMq);
    cudaStreamWaitEvent(0, e2, 0);
    gemm_qkv<<<dim3(NQKV / 128, Mq / 128), 256, GEMM_SMEM>>>(xh, wqkvT);
    compress_kernel<<<Bq * HKVq * NBq, 128>>>(cwa, cwb);
    cudaStreamWaitEvent(0, e3, 0);
    gather_kernel<<<Bq * HKVq * TOPKq, 128>>>();
    attn_kernel<<<Bq * HKVq * (Tq / 32), 256, ATTN_SMEM>>>();
    cudaStreamWaitEvent(0, e4, 0);
    gemm_f16<<<dim3(DIMq / 128, Mq / 128), 256, GEMM_SMEM>>>(xoh, woT, out, Mq, DIMq, DIMq);
}

// round 10
// speedup vs baseline: 9.7516x; 1.4068x over previous
#include <cuda_runtime.h>
#include <cuda_fp16.h>
#include <math.h>
#include <cstdint>

#define Bq 2
#define Tq 4096
#define DIMq 2048
#define Hq 16
#define HKVq 4
#define HDq 128
#define NREPq 4
#define Rq 16
#define NBq 256
#define TOPKq 64
#define Mq (Bq * Tq)
#define NQKV 3072

// ---------------- scratch ----------------
__device__ float g_k[Mq * HKVq * HDq];
__device__ float g_v[Mq * HKVq * HDq];
__device__ float g_ck[Bq * HKVq * NBq * HDq];
__device__ float g_cv[Bq * HKVq * NBq * HDq];
__device__ float g_xmean_part[Bq * 16 * DIMq];
__device__ float g_xmean[Bq * DIMq];
__device__ float g_kimean[Bq * HDq];
__device__ float g_u[Bq * DIMq];
__device__ float g_scores[Bq * NBq];
__device__ int   g_topk[Bq * TOPKq];
__device__ float2 g_trig[Tq * 64];

__device__ __half g_qh[Mq * DIMq];                    // Q fp16 (RoPE applied)
__device__ __half g_kselh[Bq * HKVq * TOPKq * HDq];   // selected K fp16 [64][128]
__device__ __half g_vselhT[Bq * HKVq * HDq * TOPKq];  // selected V fp16 transposed [128][64]
__device__ __half g_xh[Mq * DIMq];
__device__ __half g_xoh[Mq * DIMq];
__device__ __half g_wqkvT[NQKV * DIMq];
__device__ __half g_woT[DIMq * DIMq];

// ---------------- helpers ----------------
__device__ __forceinline__ uint32_t smem_u32(const void* p) {
    uint32_t a;
    asm("{ .reg .u64 t; cvta.to.shared.u64 t, %1; cvt.u32.u64 %0, t; }" : "=r"(a) : "l"(p));
    return a;
}
__device__ __forceinline__ void cp16(uint32_t dst, const void* src) {
    asm volatile("cp.async.cg.shared.global [%0], [%1], 16;" :: "r"(dst), "l"(src));
}
__device__ __forceinline__ void ldsm4(uint32_t& r0, uint32_t& r1, uint32_t& r2, uint32_t& r3,
                                      uint32_t addr) {
    asm volatile("ldmatrix.sync.aligned.m8n8.x4.shared.b16 {%0,%1,%2,%3}, [%4];"
                 : "=r"(r0), "=r"(r1), "=r"(r2), "=r"(r3) : "r"(addr));
}
__device__ __forceinline__ void mma16816(float& c0, float& c1, float& c2, float& c3,
                                         uint32_t a0, uint32_t a1, uint32_t a2, uint32_t a3,
                                         uint32_t b0, uint32_t b1) {
    asm volatile(
        "mma.sync.aligned.m16n8k16.row.col.f32.f16.f16.f32 "
        "{%0,%1,%2,%3}, {%4,%5,%6,%7}, {%8,%9}, {%0,%1,%2,%3};"
        : "+f"(c0), "+f"(c1), "+f"(c2), "+f"(c3)
        : "r"(a0), "r"(a1), "r"(a2), "r"(a3), "r"(b0), "r"(b1));
}

// ---------------- GEMM core ----------------
#define NSTAGE 3
#define STAGE_BYTES 32768
#define GEMM_SMEM (NSTAGE * STAGE_BYTES)

#define GEMM_MAINLOOP(A_, Bt_, K_)                                                  \
    const int nchunks = (K_) >> 6;                                                  \
    const int wm = (wid & 3) << 5;                                                  \
    const int wn = (wid >> 2) << 6;                                                 \
    float acc[2][8][4];                                                             \
    _Pragma("unroll") for (int i = 0; i < 2; i++)                                   \
        _Pragma("unroll") for (int j = 0; j < 8; j++)                               \
            _Pragma("unroll") for (int c = 0; c < 4; c++) acc[i][j][c] = 0.f;       \
    auto produce = [&](int ci) {                                                    \
        const int slot = ci % NSTAGE;                                               \
        const int kk = ci << 6;                                                     \
        const uint32_t sA = tiles + slot * STAGE_BYTES;                             \
        const uint32_t sB = sA + 16384;                                             \
        _Pragma("unroll") for (int i = 0; i < 4; i++) {                             \
            int ch = tid + (i << 8);                                                \
            int row = ch >> 3;                                                      \
            int c = ch & 7;                                                         \
            uint32_t soff = (row << 7) + (((c ^ (row & 7))) << 4);                  \
            cp16(sA + soff, (A_) + (size_t)(brow + row) * (K_) + kk + c * 8);       \
            cp16(sB + soff, (Bt_) + (size_t)(bcol + row) * (K_) + kk + c * 8);      \
        }                                                                           \
        asm volatile("cp.async.commit_group;" ::: "memory");                        \
    };                                                                              \
    produce(0);                                                                     \
    produce(1);                                                                     \
    for (int ci = 0; ci < nchunks; ci++) {                                          \
        if (ci + 1 < nchunks)                                                       \
            asm volatile("cp.async.wait_group 1;" ::: "memory");                    \
        else                                                                        \
            asm volatile("cp.async.wait_group 0;" ::: "memory");                    \
        __syncthreads();                                                            \
        if (ci + 2 < nchunks) produce(ci + 2);                                      \
        const int slot = ci % NSTAGE;                                               \
        const uint32_t sA = tiles + slot * STAGE_BYTES;                             \
        const uint32_t sB = sA + 16384;                                             \
        _Pragma("unroll") for (int ks = 0; ks < 4; ks++) {                          \
            const int kc = (ks << 1) + (lane >> 4);                                 \
            uint32_t a[2][4];                                                       \
            _Pragma("unroll") for (int ma = 0; ma < 2; ma++) {                      \
                int row = wm + (ma << 4) + (lane & 15);                             \
                uint32_t addr = sA + (row << 7) + ((kc ^ (row & 7)) << 4);          \
                ldsm4(a[ma][0], a[ma][1], a[ma][2], a[ma][3], addr);                \
            }                                                                       \
            uint32_t b[4][4];                                                       \
            _Pragma("unroll") for (int nb = 0; nb < 4; nb++) {                      \
                int row = wn + (nb << 4) + (lane & 15);                             \
                uint32_t addr = sB + (row << 7) + ((kc ^ (row & 7)) << 4);          \
                ldsm4(b[nb][0], b[nb][1], b[nb][2], b[nb][3], addr);                \
            }                                                                       \
            _Pragma("unroll") for (int ma = 0; ma < 2; ma++)                        \
                _Pragma("unroll") for (int j = 0; j < 8; j++) {                     \
                    int nb = j >> 1, sel = j & 1;                                   \
                    mma16816(acc[ma][j][0], acc[ma][j][1], acc[ma][j][2],           \
                             acc[ma][j][3], a[ma][0], a[ma][1], a[ma][2],           \
                             a[ma][3], b[nb][sel], b[nb][sel + 2]);                 \
                }                                                                   \
        }                                                                           \
    }

// fused QKV projection + RoPE epilogue; bcol0 selects Q (0) vs KV (16) launch
__global__ __launch_bounds__(256, 2)
void gemm_qkv(const __half* __restrict__ A, const __half* __restrict__ Bt, int bcol0) {
    extern __shared__ char smem[];
    const uint32_t tiles = smem_u32(smem);
    const int tid = threadIdx.x;
    const int wid = tid >> 5;
    const int lane = tid & 31;
    const int brow = blockIdx.y << 7;
    const int bcol = (blockIdx.x + bcol0) << 7;

    GEMM_MAINLOOP(A, Bt, DIMq)

    const int g = lane >> 2;
    const int tg = lane & 3;
    if (bcol < 2048) {
        // Q: RoPE + fp16 store to g_qh
#pragma unroll
        for (int ma = 0; ma < 2; ma++) {
#pragma unroll
            for (int j = 0; j < 8; j++) {
                int row = brow + wm + (ma << 4) + g;
                int col = bcol + wn + (j << 3) + (tg << 1);
                float2 lo = make_float2(acc[ma][j][0], acc[ma][j][1]);
                float2 hi = make_float2(acc[ma][j][2], acc[ma][j][3]);
                int p = (col & 127) >> 1;
                float2 c1 = g_trig[((row & (Tq - 1)) << 6) + p];
                float2 c2 = g_trig[(((row + 8) & (Tq - 1)) << 6) + p];
                float2 rl = make_float2(lo.x * c1.x - lo.y * c1.y, lo.x * c1.y + lo.y * c1.x);
                float2 rh = make_float2(hi.x * c2.x - hi.y * c2.y, hi.x * c2.y + hi.y * c2.x);
                *reinterpret_cast<__half2*>(g_qh + (size_t)row * DIMq + col) =
                    __floats2half2_rn(rl.x, rl.y);
                *reinterpret_cast<__half2*>(g_qh + (size_t)(row + 8) * DIMq + col) =
                    __floats2half2_rn(rh.x, rh.y);
            }
        }
    } else {
        float* Cout;
        int cbase;
        bool dorope;
        if (bcol < 2560) { Cout = g_k; cbase = bcol - 2048; dorope = true; }
        else             { Cout = g_v; cbase = bcol - 2560; dorope = false; }
#pragma unroll
        for (int ma = 0; ma < 2; ma++) {
#pragma unroll
            for (int j = 0; j < 8; j++) {
                int row = brow + wm + (ma << 4) + g;
                int col = cbase + wn + (j << 3) + (tg << 1);
                float2 lo = make_float2(acc[ma][j][0], acc[ma][j][1]);
                float2 hi = make_float2(acc[ma][j][2], acc[ma][j][3]);
                if (dorope) {
                    int p = (col & 127) >> 1;
                    float2 c1 = g_trig[((row & (Tq - 1)) << 6) + p];
                    float2 c2 = g_trig[(((row + 8) & (Tq - 1)) << 6) + p];
                    lo = make_float2(lo.x * c1.x - lo.y * c1.y, lo.x * c1.y + lo.y * c1.x);
                    hi = make_float2(hi.x * c2.x - hi.y * c2.y, hi.x * c2.y + hi.y * c2.x);
                }
                *reinterpret_cast<float2*>(Cout + (size_t)row * 512 + col) = lo;
                *reinterpret_cast<float2*>(Cout + (size_t)(row + 8) * 512 + col) = hi;
            }
        }
    }
}

// generic GEMM (output projection)
__global__ __launch_bounds__(256, 2)
void gemm_f16(const __half* __restrict__ A, const __half* __restrict__ Bt,
              float* __restrict__ C, int M, int N, int K) {
    extern __shared__ char smem[];
    const uint32_t tiles = smem_u32(smem);
    const int tid = threadIdx.x;
    const int wid = tid >> 5;
    const int lane = tid & 31;
    const int brow = blockIdx.y << 7;
    const int bcol = blockIdx.x << 7;

    GEMM_MAINLOOP(A, Bt, K)

    const int g = lane >> 2;
    const int tg = lane & 3;
#pragma unroll
    for (int ma = 0; ma < 2; ma++) {
#pragma unroll
        for (int j = 0; j < 8; j++) {
            int row = brow + wm + (ma << 4) + g;
            int col = bcol + wn + (j << 3) + (tg << 1);
            float2 lo = make_float2(acc[ma][j][0], acc[ma][j][1]);
            float2 hi = make_float2(acc[ma][j][2], acc[ma][j][3]);
            *reinterpret_cast<float2*>(C + (size_t)row * N + col) = lo;
            *reinterpret_cast<float2*>(C + (size_t)(row + 8) * N + col) = hi;
        }
    }
}

// ---------------- fp32 -> fp16 convert ----------------
__global__ void conv_h(const float* __restrict__ src, __half* __restrict__ dst, size_t n) {
    size_t i = ((size_t)blockIdx.x * blockDim.x + threadIdx.x) * 4;
    size_t stride = (size_t)gridDim.x * blockDim.x * 4;
    for (; i < n; i += stride) {
        float4 v = *reinterpret_cast<const float4*>(src + i);
        *reinterpret_cast<__half2*>(dst + i) = __floats2half2_rn(v.x, v.y);
        *reinterpret_cast<__half2*>(dst + i + 2) = __floats2half2_rn(v.z, v.w);
    }
}

// transpose + convert: w [K,N] fp32 -> wT [N,K] fp16
__global__ void transpose_h(const float* __restrict__ w, __half* __restrict__ wT,
                            int K, int N) {
    __shared__ float t[32][33];
    int n0 = blockIdx.x << 5, k0 = blockIdx.y << 5;
    int tx = threadIdx.x, ty = threadIdx.y;
#pragma unroll
    for (int j = 0; j < 4; j++)
        t[ty + j * 8][tx] = w[(size_t)(k0 + ty + j * 8) * N + n0 + tx];
    __syncthreads();
#pragma unroll
    for (int j = 0; j < 4; j++) {
        int n = n0 + ty + j * 8;
        wT[(size_t)n * K + k0 + tx] = __float2half(t[tx][ty + j * 8]);
    }
}

// ---------------- trig table ----------------
__global__ void trig_table_kernel() {
    int idx = blockIdx.x * blockDim.x + threadIdx.x;
    if (idx >= Tq * 64) return;
    int p = idx & 63;
    int t = idx >> 6;
    double freq = exp(-((double)p / 64.0) * log(10000.0));
    double ang = (double)t * freq;
    double sd, cd;
    sincos(ang, &sd, &cd);
    g_trig[idx] = make_float2((float)cd, (float)sd);
}

// ---------------- block compression ----------------
__global__ void compress_kernel(const float* __restrict__ cwa, const float* __restrict__ cwb) {
    int n = blockIdx.x % NBq;
    int hk = (blockIdx.x / NBq) % HKVq;
    int b = blockIdx.x / (NBq * HKVq);
    __shared__ float kb[Rq][HDq + 4];
    __shared__ float vb[Rq][HDq + 4];
    __shared__ float sa[Rq], sb[Rq], w[Rq];
    int d = threadIdx.x;
    for (int r = 0; r < Rq; r++) {
        int t = n * Rq + r;
        size_t off = ((size_t)(b * Tq + t)) * (HKVq * HDq) + hk * HDq + d;
        kb[r][d] = g_k[off];
        vb[r][d] = g_v[off];
    }
    __syncthreads();
    {
        int grp = d >> 3, sub = d & 7;
        float da = 0.f, db = 0.f;
        for (int i = sub; i < HDq; i += 8) {
            float kv = kb[grp][i];
            da = fmaf(kv, __ldg(cwa + i), da);
            db = fmaf(kv, __ldg(cwb + i), db);
        }
#pragma unroll
        for (int o = 4; o > 0; o >>= 1) {
            da += __shfl_down_sync(0xffffffffu, da, o, 8);
            db += __shfl_down_sync(0xffffffffu, db, o, 8);
        }
        if (sub == 0) { sa[grp] = da; sb[grp] = db; }
    }
    __syncthreads();
    if (d < 16) {
        float a = sa[d], bb = sb[d];
        float ma = a, mb = bb;
#pragma unroll
        for (int o = 8; o > 0; o >>= 1) {
            ma = fmaxf(ma, __shfl_xor_sync(0x0000ffffu, ma, o, 16));
            mb = fmaxf(mb, __shfl_xor_sync(0x0000ffffu, mb, o, 16));
        }
        float ea = expf(a - ma), eb = expf(bb - mb);
        float sua = ea, sub2 = eb;
#pragma unroll
        for (int o = 8; o > 0; o >>= 1) {
            sua += __shfl_xor_sync(0x0000ffffu, sua, o, 16);
            sub2 += __shfl_xor_sync(0x0000ffffu, sub2, o, 16);
        }
        w[d] = 0.5f * (ea / sua + eb / sub2);
    }
    __syncthreads();
    float ck = 0.f, cv = 0.f;
#pragma unroll
    for (int r = 0; r < Rq; r++) {
        ck = fmaf(w[r], kb[r][d], ck);
        cv = fmaf(w[r], vb[r][d], cv);
    }
    size_t o = ((size_t)((b * HKVq + hk) * NBq + n)) * HDq + d;
    g_ck[o] = ck;
    g_cv[o] = cv;
}

// ---------------- selection chain ----------------
__global__ void xmean_part_kernel(const float* __restrict__ x) {
    int b = blockIdx.z;
    int chunk = blockIdx.y;
    int c = blockIdx.x * 128 + threadIdx.x;
    float s = 0.f;
    for (int tt = chunk * 256; tt < (chunk + 1) * 256; tt++)
        s += x[((size_t)(b * Tq + tt)) * DIMq + c];
    g_xmean_part[((size_t)(b * 16 + chunk)) * DIMq + c] = s;
}
__global__ void xmean_final_kernel() {
    int b = blockIdx.x / 16;
    int c = (blockIdx.x % 16) * 128 + threadIdx.x;
    float s = 0.f;
    for (int ch = 0; ch < 16; ch++) s += g_xmean_part[((size_t)(b * 16 + ch)) * DIMq + c];
    g_xmean[b * DIMq + c] = s * (1.0f / (float)Tq);
}
__global__ void kimean_kernel(const float* __restrict__ wik) {
    int b = blockIdx.x;
    int d = threadIdx.x;
    float s = 0.f;
    for (int c = 0; c < DIMq; c++) s += g_xmean[b * DIMq + c] * wik[(size_t)c * HDq + d];
    g_kimean[b * HDq + d] = s;
}
__global__ void u_kernel(const float* __restrict__ wiq) {
    int b = blockIdx.x / 16;
    int c = (blockIdx.x % 16) * 128 + threadIdx.x;
    float s = 0.f;
    for (int d = 0; d < HDq; d++) s += wiq[(size_t)c * HDq + d] * g_kimean[b * HDq + d];
    g_u[b * DIMq + c] = s;
}
__global__ void scores_kernel(const float* __restrict__ x) {
    int t = blockIdx.x % NBq;
    int b = blockIdx.x / NBq;
    __shared__ float red[128];
    float s = 0.f;
    const float* xp = x + ((size_t)(b * Tq + t)) * DIMq;
    const float* up = g_u + b * DIMq;
    for (int c = threadIdx.x; c < DIMq; c += 128) s += xp[c] * up[c];
    red[threadIdx.x] = s;
    __syncthreads();
    for (int off = 64; off > 0; off >>= 1) {
        if (threadIdx.x < off) red[threadIdx.x] += red[threadIdx.x + off];
        __syncthreads();
    }
    if (threadIdx.x == 0) g_scores[b * NBq + t] = red[0];
}
__global__ void topk_kernel() {
    int b = blockIdx.x;
    int t = threadIdx.x;
    __shared__ float sc[256];
    sc[t] = g_scores[b * NBq + t];
    __syncthreads();
    float v = sc[t];
    int rank = 0;
    for (int j = 0; j < 256; j++) {
        float o = sc[j];
        rank += (o > v) || (o == v && j < t);
    }
    if (rank < TOPKq) g_topk[b * TOPKq + rank] = t;
}
// gather -> fp16 K [64][128] and fp16 V^T [128][64]
__global__ void gather_kernel() {
    int j = blockIdx.x % TOPKq;
    int hk = (blockIdx.x / TOPKq) % HKVq;
    int b = blockIdx.x / (TOPKq * HKVq);
    int d = threadIdx.x;
    int n = g_topk[b * TOPKq + j];
    int bhk = b * HKVq + hk;
    size_t src = ((size_t)(bhk * NBq + n)) * HDq + d;
    g_kselh[((size_t)bhk * TOPKq + j) * HDq + d] = __float2half(g_ck[src]);
    g_vselhT[(size_t)bhk * HDq * TOPKq + (size_t)d * TOPKq + j] = __float2half(g_cv[src]);
}

// ---------------- tensor-core attention ----------------
// CTA = (b, hk, 64-query tile); loops 4 heads. 256 threads = 8 warps (4m x 2n).
#define AQ_OFF 0
#define AK_OFF 16384
#define AV_OFF 32768
#define AP_OFF 49152
#define ARM_OFF 57344
#define ARS_OFF 57856
#define ATTN_SMEM2 58368

__global__ __launch_bounds__(256)
void attn_mma() {
    extern __shared__ char sm[];
    const uint32_t base = smem_u32(sm);
    const int tid = threadIdx.x;
    const int wid = tid >> 5;
    const int lane = tid & 31;
    const int ntile = Tq / 64;
    int tile = blockIdx.x % ntile;
    int hk = (blockIdx.x / ntile) % HKVq;
    int b = blockIdx.x / (ntile * HKVq);
    const int bhk = b * HKVq + hk;

    const __half* kp = g_kselh + (size_t)bhk * TOPKq * HDq;
    const __half* vtp = g_vselhT + (size_t)bhk * HDq * TOPKq;

    // stage K: [64 keys][128 d] as two 64x64-half swizzled tiles
    for (int i = tid; i < 1024; i += 256) {
        int r = i >> 4, c = i & 15;
        *reinterpret_cast<uint4*>(sm + AK_OFF + ((c >> 3) << 13) + (r << 7) +
                                  (((c & 7) ^ (r & 7)) << 4)) =
            *reinterpret_cast<const uint4*>(kp + r * HDq + c * 8);
    }
    // stage V^T: [128 d][64 keys] swizzled (128B rows)
    for (int i = tid; i < 1024; i += 256) {
        int r = i >> 3, c = i & 7;
        *reinterpret_cast<uint4*>(sm + AV_OFF + (r << 7) + ((c ^ (r & 7)) << 4)) =
            *reinterpret_cast<const uint4*>(vtp + r * TOPKq + c * 8);
    }
    __syncthreads();

    float* redm = reinterpret_cast<float*>(sm + ARM_OFF);
    float* reds = reinterpret_cast<float*>(sm + ARS_OFF);

    const int wm = (wid & 3) << 4;
    const int wn2 = wid >> 2;
    const int g = lane >> 2, tg = lane & 3;
    const int arow = wm + (lane & 15);
    const float scale = 0.08838834764831845f;
    const int qrow0 = b * Tq + tile * 64;

    for (int hi = 0; hi < NREPq; hi++) {
        int h = hk * NREPq + hi;
        // stage Q tile (64 x 128 halves)
        for (int i = tid; i < 1024; i += 256) {
            int r = i >> 4, c = i & 15;
            *reinterpret_cast<uint4*>(sm + AQ_OFF + ((c >> 3) << 13) + (r << 7) +
                                      (((c & 7) ^ (r & 7)) << 4)) =
                *reinterpret_cast<const uint4*>(g_qh + (size_t)(qrow0 + r) * DIMq + h * HDq + c * 8);
        }
        __syncthreads();

        // S = Q @ K^T (64x64)
        float sacc[4][4];
#pragma unroll
        for (int nb = 0; nb < 4; nb++)
#pragma unroll
            for (int c = 0; c < 4; c++) sacc[nb][c] = 0.f;
#pragma unroll
        for (int ks = 0; ks < 8; ks++) {
            int t2 = ks >> 2;
            int kc = ((ks & 3) << 1) + (lane >> 4);
            uint32_t a0, a1, a2, a3;
            ldsm4(a0, a1, a2, a3,
                  base + AQ_OFF + (t2 << 13) + (arow << 7) + ((kc ^ (arow & 7)) << 4));
            uint32_t bf[2][4];
#pragma unroll
            for (int nb2 = 0; nb2 < 2; nb2++) {
                int brw = wn2 * 32 + nb2 * 16 + (lane & 15);
                ldsm4(bf[nb2][0], bf[nb2][1], bf[nb2][2], bf[nb2][3],
                      base + AK_OFF + (t2 << 13) + (brw << 7) + ((kc ^ (brw & 7)) << 4));
            }
#pragma unroll
            for (int nb = 0; nb < 4; nb++) {
                int nb2 = nb >> 1, sel = nb & 1;
                mma16816(sacc[nb][0], sacc[nb][1], sacc[nb][2], sacc[nb][3],
                         a0, a1, a2, a3, bf[nb2][sel], bf[nb2][sel + 2]);
            }
        }
        // softmax
        float m0 = -1e30f, m1 = -1e30f;
#pragma unroll
        for (int nb = 0; nb < 4; nb++) {
#pragma unroll
            for (int c = 0; c < 4; c++) sacc[nb][c] *= scale;
            m0 = fmaxf(m0, fmaxf(sacc[nb][0], sacc[nb][1]));
            m1 = fmaxf(m1, fmaxf(sacc[nb][2], sacc[nb][3]));
        }
        m0 = fmaxf(m0, __shfl_xor_sync(0xffffffffu, m0, 1));
        m0 = fmaxf(m0, __shfl_xor_sync(0xffffffffu, m0, 2));
        m1 = fmaxf(m1, __shfl_xor_sync(0xffffffffu, m1, 1));
        m1 = fmaxf(m1, __shfl_xor_sync(0xffffffffu, m1, 2));
        if (tg == 0) {
            redm[wn2 * 64 + wm + g] = m0;
            redm[wn2 * 64 + wm + g + 8] = m1;
        }
        __syncthreads();
        float M0 = fmaxf(redm[wm + g], redm[64 + wm + g]);
        float M1 = fmaxf(redm[wm + g + 8], redm[64 + wm + g + 8]);
        float s0 = 0.f, s1 = 0.f;
#pragma unroll
        for (int nb = 0; nb < 4; nb++) {
            sacc[nb][0] = expf(sacc[nb][0] - M0);
            sacc[nb][1] = expf(sacc[nb][1] - M0);
            sacc[nb][2] = expf(sacc[nb][2] - M1);
            sacc[nb][3] = expf(sacc[nb][3] - M1);
            s0 += sacc[nb][0] + sacc[nb][1];
            s1 += sacc[nb][2] + sacc[nb][3];
        }
        s0 += __shfl_xor_sync(0xffffffffu, s0, 1);
        s0 += __shfl_xor_sync(0xffffffffu, s0, 2);
        s1 += __shfl_xor_sync(0xffffffffu, s1, 1);
        s1 += __shfl_xor_sync(0xffffffffu, s1, 2);
        if (tg == 0) {
            reds[wn2 * 64 + wm + g] = s0;
            reds[wn2 * 64 + wm + g + 8] = s1;
        }
        __syncthreads();
        float inv0 = 1.f / (reds[wm + g] + reds[64 + wm + g]);
        float inv1 = 1.f / (reds[wm + g + 8] + reds[64 + wm + g + 8]);
        // store P fp16 (A-layout, swizzled)
#pragma unroll
        for (int nb = 0; nb < 4; nb++) {
            int chunk = wn2 * 4 + nb;
            int r0 = wm + g, r1 = wm + g + 8;
            *reinterpret_cast<__half2*>(sm + AP_OFF + (r0 << 7) +
                                        ((chunk ^ (r0 & 7)) << 4) + (tg << 2)) =
                __floats2half2_rn(sacc[nb][0] * inv0, sacc[nb][1] * inv0);
            *reinterpret_cast<__half2*>(sm + AP_OFF + (r1 << 7) +
                                        ((chunk ^ (r1 & 7)) << 4) + (tg << 2)) =
                __floats2half2_rn(sacc[nb][2] * inv1, sacc[nb][3] * inv1);
        }
        __syncthreads();
        // O = P @ V (64 x 128)
        float oacc[8][4];
#pragma unroll
        for (int j = 0; j < 8; j++)
#pragma unroll
            for (int c = 0; c < 4; c++) oacc[j][c] = 0.f;
#pragma unroll
        for (int ks = 0; ks < 4; ks++) {
            int kc = (ks << 1) + (lane >> 4);
            uint32_t a0, a1, a2, a3;
            ldsm4(a0, a1, a2, a3,
                  base + AP_OFF + (arow << 7) + ((kc ^ (arow & 7)) << 4));
            uint32_t bf[4][4];
#pragma unroll
            for (int nb2 = 0; nb2 < 4; nb2++) {
                int brw = wn2 * 64 + nb2 * 16 + (lane & 15);
                ldsm4(bf[nb2][0], bf[nb2][1], bf[nb2][2], bf[nb2][3],
                      base + AV_OFF + (brw << 7) + ((kc ^ (brw & 7)) << 4));
            }
#pragma unroll
            for (int j = 0; j < 8; j++) {
                int nb2 = j >> 1, sel = j & 1;
                mma16816(oacc[j][0], oacc[j][1], oacc[j][2], oacc[j][3],
                         a0, a1, a2, a3, bf[nb2][sel], bf[nb2][sel + 2]);
            }
        }
        // write O (fp16)
#pragma unroll
        for (int j = 0; j < 8; j++) {
            int col = wn2 * 64 + (j << 3) + (tg << 1);
            int r0 = tile * 64 + wm + g;
            __half* o0 = g_xoh + (size_t)(b * Tq + r0) * DIMq + h * HDq + col;
            *reinterpret_cast<__half2*>(o0) = __floats2half2_rn(oacc[j][0], oacc[j][1]);
            *reinterpret_cast<__half2*>(o0 + (size_t)8 * DIMq) =
                __floats2half2_rn(oacc[j][2], oacc[j][3]);
        }
        __syncthreads();
    }
}

// ---------------- launch (multi-stream; every wait AFTER its record) ----------------
extern "C" void kernel_launch(void* const* d_in, const int* in_sizes, int n_in,
                              void* d_out, int out_size) {
    const float* x   = (const float*)d_in[0];
    const float* wq  = (const float*)d_in[1];
    const float* wk  = (const float*)d_in[2];
    const float* wv  = (const float*)d_in[3];
    const float* wo  = (const float*)d_in[4];
    const float* wiq = (const float*)d_in[5];
    const float* wik = (const float*)d_in[6];
    const float* cwa = (const float*)d_in[7];
    const float* cwb = (const float*)d_in[8];
    float* out = (float*)d_out;

    static cudaStream_t s2 = nullptr, s3 = nullptr;
    static cudaEvent_t eFork = nullptr, eT = nullptr, eKV = nullptr, eGa = nullptr, eWo = nullptr;
    if (!s2) {
        cudaStreamCreateWithFlags(&s2, cudaStreamNonBlocking);
        cudaStreamCreateWithFlags(&s3, cudaStreamNonBlocking);
        cudaEventCreateWithFlags(&eFork, cudaEventDisableTiming);
        cudaEventCreateWithFlags(&eT, cudaEventDisableTiming);
        cudaEventCreateWithFlags(&eKV, cudaEventDisableTiming);
        cudaEventCreateWithFlags(&eGa, cudaEventDisableTiming);
        cudaEventCreateWithFlags(&eWo, cudaEventDisableTiming);
        cudaFuncSetAttribute(gemm_qkv, cudaFuncAttributeMaxDynamicSharedMemorySize, GEMM_SMEM);
        cudaFuncSetAttribute(gemm_f16, cudaFuncAttributeMaxDynamicSharedMemorySize, GEMM_SMEM);
        cudaFuncSetAttribute(attn_mma, cudaFuncAttributeMaxDynamicSharedMemorySize, ATTN_SMEM2);
    }

    __half *xh, *xoh, *wqkvT, *woT;
    cudaGetSymbolAddress((void**)&xh, g_xh);
    cudaGetSymbolAddress((void**)&xoh, g_xoh);
    cudaGetSymbolAddress((void**)&wqkvT, g_wqkvT);
    cudaGetSymbolAddress((void**)&woT, g_woT);

    // fork
    cudaEventRecord(eFork, 0);
    cudaStreamWaitEvent(s2, eFork, 0);
    cudaStreamWaitEvent(s3, eFork, 0);

    // s2: trig + QKV weight transposes, then wo transpose
    trig_table_kernel<<<(Tq * 64 + 255) / 256, 256, 0, s2>>>();
    transpose_h<<<dim3(DIMq / 32, DIMq / 32), dim3(32, 8), 0, s2>>>(wq, wqkvT, DIMq, DIMq);
    transpose_h<<<dim3((HKVq * HDq) / 32, DIMq / 32), dim3(32, 8), 0, s2>>>(
        wk, wqkvT + (size_t)2048 * DIMq, DIMq, HKVq * HDq);
    transpose_h<<<dim3((HKVq * HDq) / 32, DIMq / 32), dim3(32, 8), 0, s2>>>(
        wv, wqkvT + (size_t)2560 * DIMq, DIMq, HKVq * HDq);
    cudaEventRecord(eT, s2);
    transpose_h<<<dim3(DIMq / 32, DIMq / 32), dim3(32, 8), 0, s2>>>(wo, woT, DIMq, DIMq);
    cudaEventRecord(eWo, s2);

    // s3: selection chain prefix (needs only x)
    xmean_part_kernel<<<dim3(16, 16, Bq), 128, 0, s3>>>(x);
    xmean_final_kernel<<<Bq * 16, 128, 0, s3>>>();
    kimean_kernel<<<Bq, 128, 0, s3>>>(wik);
    u_kernel<<<Bq * 16, 128, 0, s3>>>(wiq);
    scores_kernel<<<Bq * NBq, 128, 0, s3>>>(x);
    topk_kernel<<<Bq, 256, 0, s3>>>();

    // main: conv + KV GEMM, record eKV
    conv_h<<<2048, 256>>>(x, xh, (size_t)Mq * DIMq);
    cudaStreamWaitEvent(0, eT, 0);
    gemm_qkv<<<dim3(8, Mq / 128), 256, GEMM_SMEM>>>(xh, wqkvT, 16);   // K, V
    cudaEventRecord(eKV, 0);

    // s3: compress + gather (wait enqueued AFTER eKV record)
    cudaStreamWaitEvent(s3, eKV, 0);
    compress_kernel<<<Bq * HKVq * NBq, 128, 0, s3>>>(cwa, cwb);
    gather_kernel<<<Bq * HKVq * TOPKq, 128, 0, s3>>>();
    cudaEventRecord(eGa, s3);

    // main: Q GEMM overlaps compress/gather; then attention; then output GEMM
    gemm_qkv<<<dim3(16, Mq / 128), 256, GEMM_SMEM>>>(xh, wqkvT, 0);   // Q
    cudaStreamWaitEvent(0, eGa, 0);
    attn_mma<<<Bq * HKVq * (Tq / 64), 256, ATTN_SMEM2>>>();
    cudaStreamWaitEvent(0, eWo, 0);
    gemm_f16<<<dim3(DIMq / 128, Mq / 128), 256, GEMM_SMEM>>>(xoh, woT, out, Mq, DIMq, DIMq);
}

// round 11
// speedup vs baseline: 9.8541x; 1.0105x over previous
#include <cuda_runtime.h>
#include <cuda_fp16.h>
#include <math.h>
#include <cstdint>

#define Bq 2
#define Tq 4096
#define DIMq 2048
#define Hq 16
#define HKVq 4
#define HDq 128
#define NREPq 4
#define Rq 16
#define NBq 256
#define TOPKq 64
#define Mq (Bq * Tq)
#define NQKV 3072

// ---------------- scratch ----------------
__device__ __half g_k[Mq * HKVq * HDq];               // K fp16 (RoPE applied)
__device__ __half g_v[Mq * HKVq * HDq];               // V fp16
__device__ float g_xmean_part[Bq * 16 * DIMq];
__device__ float g_xmean[Bq * DIMq];
__device__ float g_kimean[Bq * HDq];
__device__ float g_u[Bq * DIMq];
__device__ float g_scores[Bq * NBq];
__device__ int   g_topk[Bq * TOPKq];
__device__ float2 g_trig[Tq * 64];

__device__ __half g_qh[Mq * DIMq];                    // Q fp16 (RoPE applied)
__device__ __half g_kselh[Bq * HKVq * TOPKq * HDq];   // selected compressed K fp16 [64][128]
__device__ __half g_vselhT[Bq * HKVq * HDq * TOPKq];  // selected compressed V fp16 T [128][64]
__device__ __half g_xh[Mq * DIMq];
__device__ __half g_xoh[Mq * DIMq];
__device__ __half g_wqkvT[NQKV * DIMq];
__device__ __half g_woT[DIMq * DIMq];

// ---------------- helpers ----------------
__device__ __forceinline__ uint32_t smem_u32(const void* p) {
    uint32_t a;
    asm("{ .reg .u64 t; cvta.to.shared.u64 t, %1; cvt.u32.u64 %0, t; }" : "=r"(a) : "l"(p));
    return a;
}
__device__ __forceinline__ void cp16(uint32_t dst, const void* src) {
    asm volatile("cp.async.cg.shared.global [%0], [%1], 16;" :: "r"(dst), "l"(src));
}
__device__ __forceinline__ void ldsm4(uint32_t& r0, uint32_t& r1, uint32_t& r2, uint32_t& r3,
                                      uint32_t addr) {
    asm volatile("ldmatrix.sync.aligned.m8n8.x4.shared.b16 {%0,%1,%2,%3}, [%4];"
                 : "=r"(r0), "=r"(r1), "=r"(r2), "=r"(r3) : "r"(addr));
}
__device__ __forceinline__ void mma16816(float& c0, float& c1, float& c2, float& c3,
                                         uint32_t a0, uint32_t a1, uint32_t a2, uint32_t a3,
                                         uint32_t b0, uint32_t b1) {
    asm volatile(
        "mma.sync.aligned.m16n8k16.row.col.f32.f16.f16.f32 "
        "{%0,%1,%2,%3}, {%4,%5,%6,%7}, {%8,%9}, {%0,%1,%2,%3};"
        : "+f"(c0), "+f"(c1), "+f"(c2), "+f"(c3)
        : "r"(a0), "r"(a1), "r"(a2), "r"(a3), "r"(b0), "r"(b1));
}

// ---------------- GEMM core ----------------
#define NSTAGE 3
#define STAGE_BYTES 32768
#define GEMM_SMEM (NSTAGE * STAGE_BYTES)

#define GEMM_MAINLOOP(A_, Bt_, K_)                                                  \
    const int nchunks = (K_) >> 6;                                                  \
    const int wm = (wid & 3) << 5;                                                  \
    const int wn = (wid >> 2) << 6;                                                 \
    float acc[2][8][4];                                                             \
    _Pragma("unroll") for (int i = 0; i < 2; i++)                                   \
        _Pragma("unroll") for (int j = 0; j < 8; j++)                               \
            _Pragma("unroll") for (int c = 0; c < 4; c++) acc[i][j][c] = 0.f;       \
    auto produce = [&](int ci) {                                                    \
        const int slot = ci % NSTAGE;                                               \
        const int kk = ci << 6;                                                     \
        const uint32_t sA = tiles + slot * STAGE_BYTES;                             \
        const uint32_t sB = sA + 16384;                                             \
        _Pragma("unroll") for (int i = 0; i < 4; i++) {                             \
            int ch = tid + (i << 8);                                                \
            int row = ch >> 3;                                                      \
            int c = ch & 7;                                                         \
            uint32_t soff = (row << 7) + (((c ^ (row & 7))) << 4);                  \
            cp16(sA + soff, (A_) + (size_t)(brow + row) * (K_) + kk + c * 8);       \
            cp16(sB + soff, (Bt_) + (size_t)(bcol + row) * (K_) + kk + c * 8);      \
        }                                                                           \
        asm volatile("cp.async.commit_group;" ::: "memory");                        \
    };                                                                              \
    produce(0);                                                                     \
    produce(1);                                                                     \
    for (int ci = 0; ci < nchunks; ci++) {                                          \
        if (ci + 1 < nchunks)                                                       \
            asm volatile("cp.async.wait_group 1;" ::: "memory");                    \
        else                                                                        \
            asm volatile("cp.async.wait_group 0;" ::: "memory");                    \
        __syncthreads();                                                            \
        if (ci + 2 < nchunks) produce(ci + 2);                                      \
        const int slot = ci % NSTAGE;                                               \
        const uint32_t sA = tiles + slot * STAGE_BYTES;                             \
        const uint32_t sB = sA + 16384;                                             \
        _Pragma("unroll") for (int ks = 0; ks < 4; ks++) {                          \
            const int kc = (ks << 1) + (lane >> 4);                                 \
            uint32_t a[2][4];                                                       \
            _Pragma("unroll") for (int ma = 0; ma < 2; ma++) {                      \
                int row = wm + (ma << 4) + (lane & 15);                             \
                uint32_t addr = sA + (row << 7) + ((kc ^ (row & 7)) << 4);          \
                ldsm4(a[ma][0], a[ma][1], a[ma][2], a[ma][3], addr);                \
            }                                                                       \
            uint32_t b[4][4];                                                       \
            _Pragma("unroll") for (int nb = 0; nb < 4; nb++) {                      \
                int row = wn + (nb << 4) + (lane & 15);                             \
                uint32_t addr = sB + (row << 7) + ((kc ^ (row & 7)) << 4);          \
                ldsm4(b[nb][0], b[nb][1], b[nb][2], b[nb][3], addr);                \
            }                                                                       \
            _Pragma("unroll") for (int ma = 0; ma < 2; ma++)                        \
                _Pragma("unroll") for (int j = 0; j < 8; j++) {                     \
                    int nb = j >> 1, sel = j & 1;                                   \
                    mma16816(acc[ma][j][0], acc[ma][j][1], acc[ma][j][2],           \
                             acc[ma][j][3], a[ma][0], a[ma][1], a[ma][2],           \
                             a[ma][3], b[nb][sel], b[nb][sel + 2]);                 \
                }                                                                   \
        }                                                                           \
    }

// fused QKV projection + RoPE epilogue; bcol0 selects Q (0) vs KV (16) launch
__global__ __launch_bounds__(256, 2)
void gemm_qkv(const __half* __restrict__ A, const __half* __restrict__ Bt, int bcol0) {
    extern __shared__ char smem[];
    const uint32_t tiles = smem_u32(smem);
    const int tid = threadIdx.x;
    const int wid = tid >> 5;
    const int lane = tid & 31;
    const int brow = blockIdx.y << 7;
    const int bcol = (blockIdx.x + bcol0) << 7;

    GEMM_MAINLOOP(A, Bt, DIMq)

    const int g = lane >> 2;
    const int tg = lane & 3;
    __half* Cout;
    int cbase, cstride;
    bool dorope;
    if (bcol < 2048)      { Cout = g_qh; cbase = bcol;        cstride = 2048; dorope = true; }
    else if (bcol < 2560) { Cout = g_k;  cbase = bcol - 2048; cstride = 512;  dorope = true; }
    else                  { Cout = g_v;  cbase = bcol - 2560; cstride = 512;  dorope = false; }
#pragma unroll
    for (int ma = 0; ma < 2; ma++) {
#pragma unroll
        for (int j = 0; j < 8; j++) {
            int row = brow + wm + (ma << 4) + g;
            int col = cbase + wn + (j << 3) + (tg << 1);
            float2 lo = make_float2(acc[ma][j][0], acc[ma][j][1]);
            float2 hi = make_float2(acc[ma][j][2], acc[ma][j][3]);
            if (dorope) {
                int p = (col & 127) >> 1;
                float2 c1 = g_trig[((row & (Tq - 1)) << 6) + p];
                float2 c2 = g_trig[(((row + 8) & (Tq - 1)) << 6) + p];
                lo = make_float2(lo.x * c1.x - lo.y * c1.y, lo.x * c1.y + lo.y * c1.x);
                hi = make_float2(hi.x * c2.x - hi.y * c2.y, hi.x * c2.y + hi.y * c2.x);
            }
            *reinterpret_cast<__half2*>(Cout + (size_t)row * cstride + col) =
                __floats2half2_rn(lo.x, lo.y);
            *reinterpret_cast<__half2*>(Cout + (size_t)(row + 8) * cstride + col) =
                __floats2half2_rn(hi.x, hi.y);
        }
    }
}

// generic GEMM (output projection)
__global__ __launch_bounds__(256, 2)
void gemm_f16(const __half* __restrict__ A, const __half* __restrict__ Bt,
              float* __restrict__ C, int M, int N, int K) {
    extern __shared__ char smem[];
    const uint32_t tiles = smem_u32(smem);
    const int tid = threadIdx.x;
    const int wid = tid >> 5;
    const int lane = tid & 31;
    const int brow = blockIdx.y << 7;
    const int bcol = blockIdx.x << 7;

    GEMM_MAINLOOP(A, Bt, K)

    const int g = lane >> 2;
    const int tg = lane & 3;
#pragma unroll
    for (int ma = 0; ma < 2; ma++) {
#pragma unroll
        for (int j = 0; j < 8; j++) {
            int row = brow + wm + (ma << 4) + g;
            int col = bcol + wn + (j << 3) + (tg << 1);
            float2 lo = make_float2(acc[ma][j][0], acc[ma][j][1]);
            float2 hi = make_float2(acc[ma][j][2], acc[ma][j][3]);
            *reinterpret_cast<float2*>(C + (size_t)row * N + col) = lo;
            *reinterpret_cast<float2*>(C + (size_t)(row + 8) * N + col) = hi;
        }
    }
}

// ---------------- fp32 -> fp16 convert ----------------
__global__ void conv_h(const float* __restrict__ src, __half* __restrict__ dst, size_t n) {
    size_t i = ((size_t)blockIdx.x * blockDim.x + threadIdx.x) * 4;
    size_t stride = (size_t)gridDim.x * blockDim.x * 4;
    for (; i < n; i += stride) {
        float4 v = *reinterpret_cast<const float4*>(src + i);
        *reinterpret_cast<__half2*>(dst + i) = __floats2half2_rn(v.x, v.y);
        *reinterpret_cast<__half2*>(dst + i + 2) = __floats2half2_rn(v.z, v.w);
    }
}

// transpose + convert: w [K,N] fp32 -> wT [N,K] fp16
__global__ void transpose_h(const float* __restrict__ w, __half* __restrict__ wT,
                            int K, int N) {
    __shared__ float t[32][33];
    int n0 = blockIdx.x << 5, k0 = blockIdx.y << 5;
    int tx = threadIdx.x, ty = threadIdx.y;
#pragma unroll
    for (int j = 0; j < 4; j++)
        t[ty + j * 8][tx] = w[(size_t)(k0 + ty + j * 8) * N + n0 + tx];
    __syncthreads();
#pragma unroll
    for (int j = 0; j < 4; j++) {
        int n = n0 + ty + j * 8;
        wT[(size_t)n * K + k0 + tx] = __float2half(t[tx][ty + j * 8]);
    }
}

// ---------------- trig table ----------------
__global__ void trig_table_kernel() {
    int idx = blockIdx.x * blockDim.x + threadIdx.x;
    if (idx >= Tq * 64) return;
    int p = idx & 63;
    int t = idx >> 6;
    double freq = exp(-((double)p / 64.0) * log(10000.0));
    double ang = (double)t * freq;
    double sd, cd;
    sincos(ang, &sd, &cd);
    g_trig[idx] = make_float2((float)cd, (float)sd);
}

// ---------------- compress ONLY the selected blocks, write attn layouts ----------------
__global__ void compress_sel(const float* __restrict__ cwa, const float* __restrict__ cwb) {
    int j = blockIdx.x % TOPKq;
    int hk = (blockIdx.x / TOPKq) % HKVq;
    int b = blockIdx.x / (TOPKq * HKVq);
    int bhk = b * HKVq + hk;
    int n = g_topk[b * TOPKq + j];
    __shared__ float kb[Rq][HDq + 4];
    __shared__ float vb[Rq][HDq + 4];
    __shared__ float sa[Rq], sb[Rq], w[Rq];
    int d = threadIdx.x;
    for (int r = 0; r < Rq; r++) {
        int t = n * Rq + r;
        size_t off = ((size_t)(b * Tq + t)) * (HKVq * HDq) + hk * HDq + d;
        kb[r][d] = __half2float(g_k[off]);
        vb[r][d] = __half2float(g_v[off]);
    }
    __syncthreads();
    {
        int grp = d >> 3, sub = d & 7;
        float da = 0.f, db = 0.f;
        for (int i = sub; i < HDq; i += 8) {
            float kv = kb[grp][i];
            da = fmaf(kv, __ldg(cwa + i), da);
            db = fmaf(kv, __ldg(cwb + i), db);
        }
#pragma unroll
        for (int o = 4; o > 0; o >>= 1) {
            da += __shfl_down_sync(0xffffffffu, da, o, 8);
            db += __shfl_down_sync(0xffffffffu, db, o, 8);
        }
        if (sub == 0) { sa[grp] = da; sb[grp] = db; }
    }
    __syncthreads();
    if (d < 16) {
        float a = sa[d], bb = sb[d];
        float ma = a, mb = bb;
#pragma unroll
        for (int o = 8; o > 0; o >>= 1) {
            ma = fmaxf(ma, __shfl_xor_sync(0x0000ffffu, ma, o, 16));
            mb = fmaxf(mb, __shfl_xor_sync(0x0000ffffu, mb, o, 16));
        }
        float ea = expf(a - ma), eb = expf(bb - mb);
        float sua = ea, sub2 = eb;
#pragma unroll
        for (int o = 8; o > 0; o >>= 1) {
            sua += __shfl_xor_sync(0x0000ffffu, sua, o, 16);
            sub2 += __shfl_xor_sync(0x0000ffffu, sub2, o, 16);
        }
        w[d] = 0.5f * (ea / sua + eb / sub2);
    }
    __syncthreads();
    float ck = 0.f, cv = 0.f;
#pragma unroll
    for (int r = 0; r < Rq; r++) {
        ck = fmaf(w[r], kb[r][d], ck);
        cv = fmaf(w[r], vb[r][d], cv);
    }
    g_kselh[((size_t)bhk * TOPKq + j) * HDq + d] = __float2half(ck);
    g_vselhT[(size_t)bhk * HDq * TOPKq + (size_t)d * TOPKq + j] = __float2half(cv);
}

// ---------------- selection chain ----------------
__global__ void xmean_part_kernel(const float* __restrict__ x) {
    int b = blockIdx.z;
    int chunk = blockIdx.y;
    int c = blockIdx.x * 128 + threadIdx.x;
    float s = 0.f;
    for (int tt = chunk * 256; tt < (chunk + 1) * 256; tt++)
        s += x[((size_t)(b * Tq + tt)) * DIMq + c];
    g_xmean_part[((size_t)(b * 16 + chunk)) * DIMq + c] = s;
}
__global__ void xmean_final_kernel() {
    int b = blockIdx.x / 16;
    int c = (blockIdx.x % 16) * 128 + threadIdx.x;
    float s = 0.f;
    for (int ch = 0; ch < 16; ch++) s += g_xmean_part[((size_t)(b * 16 + ch)) * DIMq + c];
    g_xmean[b * DIMq + c] = s * (1.0f / (float)Tq);
}
__global__ void kimean_kernel(const float* __restrict__ wik) {
    int b = blockIdx.x;
    int d = threadIdx.x;
    float s = 0.f;
    for (int c = 0; c < DIMq; c++) s += g_xmean[b * DIMq + c] * wik[(size_t)c * HDq + d];
    g_kimean[b * HDq + d] = s;
}
__global__ void u_kernel(const float* __restrict__ wiq) {
    int b = blockIdx.x / 16;
    int c = (blockIdx.x % 16) * 128 + threadIdx.x;
    float s = 0.f;
    for (int d = 0; d < HDq; d++) s += wiq[(size_t)c * HDq + d] * g_kimean[b * HDq + d];
    g_u[b * DIMq + c] = s;
}
__global__ void scores_kernel(const float* __restrict__ x) {
    int t = blockIdx.x % NBq;
    int b = blockIdx.x / NBq;
    __shared__ float red[128];
    float s = 0.f;
    const float* xp = x + ((size_t)(b * Tq + t)) * DIMq;
    const float* up = g_u + b * DIMq;
    for (int c = threadIdx.x; c < DIMq; c += 128) s += xp[c] * up[c];
    red[threadIdx.x] = s;
    __syncthreads();
    for (int off = 64; off > 0; off >>= 1) {
        if (threadIdx.x < off) red[threadIdx.x] += red[threadIdx.x + off];
        __syncthreads();
    }
    if (threadIdx.x == 0) g_scores[b * NBq + t] = red[0];
}
__global__ void topk_kernel() {
    int b = blockIdx.x;
    int t = threadIdx.x;
    __shared__ float sc[256];
    sc[t] = g_scores[b * NBq + t];
    __syncthreads();
    float v = sc[t];
    int rank = 0;
    for (int j = 0; j < 256; j++) {
        float o = sc[j];
        rank += (o > v) || (o == v && j < t);
    }
    if (rank < TOPKq) g_topk[b * TOPKq + rank] = t;
}

// ---------------- tensor-core attention ----------------
#define AQ_OFF 0
#define AK_OFF 16384
#define AV_OFF 32768
#define AP_OFF 49152
#define ARM_OFF 57344
#define ARS_OFF 57856
#define ATTN_SMEM2 58368

__global__ __launch_bounds__(256)
void attn_mma() {
    extern __shared__ char sm[];
    const uint32_t base = smem_u32(sm);
    const int tid = threadIdx.x;
    const int wid = tid >> 5;
    const int lane = tid & 31;
    const int ntile = Tq / 64;
    int tile = blockIdx.x % ntile;
    int hk = (blockIdx.x / ntile) % HKVq;
    int b = blockIdx.x / (ntile * HKVq);
    const int bhk = b * HKVq + hk;

    const __half* kp = g_kselh + (size_t)bhk * TOPKq * HDq;
    const __half* vtp = g_vselhT + (size_t)bhk * HDq * TOPKq;

    for (int i = tid; i < 1024; i += 256) {
        int r = i >> 4, c = i & 15;
        *reinterpret_cast<uint4*>(sm + AK_OFF + ((c >> 3) << 13) + (r << 7) +
                                  (((c & 7) ^ (r & 7)) << 4)) =
            *reinterpret_cast<const uint4*>(kp + r * HDq + c * 8);
    }
    for (int i = tid; i < 1024; i += 256) {
        int r = i >> 3, c = i & 7;
        *reinterpret_cast<uint4*>(sm + AV_OFF + (r << 7) + ((c ^ (r & 7)) << 4)) =
            *reinterpret_cast<const uint4*>(vtp + r * TOPKq + c * 8);
    }
    __syncthreads();

    float* redm = reinterpret_cast<float*>(sm + ARM_OFF);
    float* reds = reinterpret_cast<float*>(sm + ARS_OFF);

    const int wm = (wid & 3) << 4;
    const int wn2 = wid >> 2;
    const int g = lane >> 2, tg = lane & 3;
    const int arow = wm + (lane & 15);
    const float scale = 0.08838834764831845f;
    const int qrow0 = b * Tq + tile * 64;

    for (int hi = 0; hi < NREPq; hi++) {
        int h = hk * NREPq + hi;
        for (int i = tid; i < 1024; i += 256) {
            int r = i >> 4, c = i & 15;
            *reinterpret_cast<uint4*>(sm + AQ_OFF + ((c >> 3) << 13) + (r << 7) +
                                      (((c & 7) ^ (r & 7)) << 4)) =
                *reinterpret_cast<const uint4*>(g_qh + (size_t)(qrow0 + r) * DIMq + h * HDq + c * 8);
        }
        __syncthreads();

        float sacc[4][4];
#pragma unroll
        for (int nb = 0; nb < 4; nb++)
#pragma unroll
            for (int c = 0; c < 4; c++) sacc[nb][c] = 0.f;
#pragma unroll
        for (int ks = 0; ks < 8; ks++) {
            int t2 = ks >> 2;
            int kc = ((ks & 3) << 1) + (lane >> 4);
            uint32_t a0, a1, a2, a3;
            ldsm4(a0, a1, a2, a3,
                  base + AQ_OFF + (t2 << 13) + (arow << 7) + ((kc ^ (arow & 7)) << 4));
            uint32_t bf[2][4];
#pragma unroll
            for (int nb2 = 0; nb2 < 2; nb2++) {
                int brw = wn2 * 32 + nb2 * 16 + (lane & 15);
                ldsm4(bf[nb2][0], bf[nb2][1], bf[nb2][2], bf[nb2][3],
                      base + AK_OFF + (t2 << 13) + (brw << 7) + ((kc ^ (brw & 7)) << 4));
            }
#pragma unroll
            for (int nb = 0; nb < 4; nb++) {
                int nb2 = nb >> 1, sel = nb & 1;
                mma16816(sacc[nb][0], sacc[nb][1], sacc[nb][2], sacc[nb][3],
                         a0, a1, a2, a3, bf[nb2][sel], bf[nb2][sel + 2]);
            }
        }
        float m0 = -1e30f, m1 = -1e30f;
#pragma unroll
        for (int nb = 0; nb < 4; nb++) {
#pragma unroll
            for (int c = 0; c < 4; c++) sacc[nb][c] *= scale;
            m0 = fmaxf(m0, fmaxf(sacc[nb][0], sacc[nb][1]));
            m1 = fmaxf(m1, fmaxf(sacc[nb][2], sacc[nb][3]));
        }
        m0 = fmaxf(m0, __shfl_xor_sync(0xffffffffu, m0, 1));
        m0 = fmaxf(m0, __shfl_xor_sync(0xffffffffu, m0, 2));
        m1 = fmaxf(m1, __shfl_xor_sync(0xffffffffu, m1, 1));
        m1 = fmaxf(m1, __shfl_xor_sync(0xffffffffu, m1, 2));
        if (tg == 0) {
            redm[wn2 * 64 + wm + g] = m0;
            redm[wn2 * 64 + wm + g + 8] = m1;
        }
        __syncthreads();
        float M0 = fmaxf(redm[wm + g], redm[64 + wm + g]);
        float M1 = fmaxf(redm[wm + g + 8], redm[64 + wm + g + 8]);
        float s0 = 0.f, s1 = 0.f;
#pragma unroll
        for (int nb = 0; nb < 4; nb++) {
            sacc[nb][0] = expf(sacc[nb][0] - M0);
            sacc[nb][1] = expf(sacc[nb][1] - M0);
            sacc[nb][2] = expf(sacc[nb][2] - M1);
            sacc[nb][3] = expf(sacc[nb][3] - M1);
            s0 += sacc[nb][0] + sacc[nb][1];
            s1 += sacc[nb][2] + sacc[nb][3];
        }
        s0 += __shfl_xor_sync(0xffffffffu, s0, 1);
        s0 += __shfl_xor_sync(0xffffffffu, s0, 2);
        s1 += __shfl_xor_sync(0xffffffffu, s1, 1);
        s1 += __shfl_xor_sync(0xffffffffu, s1, 2);
        if (tg == 0) {
            reds[wn2 * 64 + wm + g] = s0;
            reds[wn2 * 64 + wm + g + 8] = s1;
        }
        __syncthreads();
        float inv0 = 1.f / (reds[wm + g] + reds[64 + wm + g]);
        float inv1 = 1.f / (reds[wm + g + 8] + reds[64 + wm + g + 8]);
#pragma unroll
        for (int nb = 0; nb < 4; nb++) {
            int chunk = wn2 * 4 + nb;
            int r0 = wm + g, r1 = wm + g + 8;
            *reinterpret_cast<__half2*>(sm + AP_OFF + (r0 << 7) +
                                        ((chunk ^ (r0 & 7)) << 4) + (tg << 2)) =
                __floats2half2_rn(sacc[nb][0] * inv0, sacc[nb][1] * inv0);
            *reinterpret_cast<__half2*>(sm + AP_OFF + (r1 << 7) +
                                        ((chunk ^ (r1 & 7)) << 4) + (tg << 2)) =
                __floats2half2_rn(sacc[nb][2] * inv1, sacc[nb][3] * inv1);
        }
        __syncthreads();
        float oacc[8][4];
#pragma unroll
        for (int j = 0; j < 8; j++)
#pragma unroll
            for (int c = 0; c < 4; c++) oacc[j][c] = 0.f;
#pragma unroll
        for (int ks = 0; ks < 4; ks++) {
            int kc = (ks << 1) + (lane >> 4);
            uint32_t a0, a1, a2, a3;
            ldsm4(a0, a1, a2, a3,
                  base + AP_OFF + (arow << 7) + ((kc ^ (arow & 7)) << 4));
            uint32_t bf[4][4];
#pragma unroll
            for (int nb2 = 0; nb2 < 4; nb2++) {
                int brw = wn2 * 64 + nb2 * 16 + (lane & 15);
                ldsm4(bf[nb2][0], bf[nb2][1], bf[nb2][2], bf[nb2][3],
                      base + AV_OFF + (brw << 7) + ((kc ^ (brw & 7)) << 4));
            }
#pragma unroll
            for (int j = 0; j < 8; j++) {
                int nb2 = j >> 1, sel = j & 1;
                mma16816(oacc[j][0], oacc[j][1], oacc[j][2], oacc[j][3],
                         a0, a1, a2, a3, bf[nb2][sel], bf[nb2][sel + 2]);
            }
        }
#pragma unroll
        for (int j = 0; j < 8; j++) {
            int col = wn2 * 64 + (j << 3) + (tg << 1);
            int r0 = tile * 64 + wm + g;
            __half* o0 = g_xoh + (size_t)(b * Tq + r0) * DIMq + h * HDq + col;
            *reinterpret_cast<__half2*>(o0) = __floats2half2_rn(oacc[j][0], oacc[j][1]);
            *reinterpret_cast<__half2*>(o0 + (size_t)8 * DIMq) =
                __floats2half2_rn(oacc[j][2], oacc[j][3]);
        }
        __syncthreads();
    }
}

// ---------------- launch ----------------
extern "C" void kernel_launch(void* const* d_in, const int* in_sizes, int n_in,
                              void* d_out, int out_size) {
    const float* x   = (const float*)d_in[0];
    const float* wq  = (const float*)d_in[1];
    const float* wk  = (const float*)d_in[2];
    const float* wv  = (const float*)d_in[3];
    const float* wo  = (const float*)d_in[4];
    const float* wiq = (const float*)d_in[5];
    const float* wik = (const float*)d_in[6];
    const float* cwa = (const float*)d_in[7];
    const float* cwb = (const float*)d_in[8];
    float* out = (float*)d_out;

    static cudaStream_t s2 = nullptr, s3 = nullptr;
    static cudaEvent_t eFork = nullptr, eT = nullptr, eKV = nullptr, eGa = nullptr, eWo = nullptr;
    if (!s2) {
        cudaStreamCreateWithFlags(&s2, cudaStreamNonBlocking);
        cudaStreamCreateWithFlags(&s3, cudaStreamNonBlocking);
        cudaEventCreateWithFlags(&eFork, cudaEventDisableTiming);
        cudaEventCreateWithFlags(&eT, cudaEventDisableTiming);
        cudaEventCreateWithFlags(&eKV, cudaEventDisableTiming);
        cudaEventCreateWithFlags(&eGa, cudaEventDisableTiming);
        cudaEventCreateWithFlags(&eWo, cudaEventDisableTiming);
        cudaFuncSetAttribute(gemm_qkv, cudaFuncAttributeMaxDynamicSharedMemorySize, GEMM_SMEM);
        cudaFuncSetAttribute(gemm_f16, cudaFuncAttributeMaxDynamicSharedMemorySize, GEMM_SMEM);
        cudaFuncSetAttribute(attn_mma, cudaFuncAttributeMaxDynamicSharedMemorySize, ATTN_SMEM2);
    }

    __half *xh, *xoh, *wqkvT, *woT;
    cudaGetSymbolAddress((void**)&xh, g_xh);
    cudaGetSymbolAddress((void**)&xoh, g_xoh);
    cudaGetSymbolAddress((void**)&wqkvT, g_wqkvT);
    cudaGetSymbolAddress((void**)&woT, g_woT);

    // fork
    cudaEventRecord(eFork, 0);
    cudaStreamWaitEvent(s2, eFork, 0);
    cudaStreamWaitEvent(s3, eFork, 0);

    // s2: trig + QKV weight transposes
    trig_table_kernel<<<(Tq * 64 + 255) / 256, 256, 0, s2>>>();
    transpose_h<<<dim3(DIMq / 32, DIMq / 32), dim3(32, 8), 0, s2>>>(wq, wqkvT, DIMq, DIMq);
    transpose_h<<<dim3((HKVq * HDq) / 32, DIMq / 32), dim3(32, 8), 0, s2>>>(
        wk, wqkvT + (size_t)2048 * DIMq, DIMq, HKVq * HDq);
    transpose_h<<<dim3((HKVq * HDq) / 32, DIMq / 32), dim3(32, 8), 0, s2>>>(
        wv, wqkvT + (size_t)2560 * DIMq, DIMq, HKVq * HDq);
    cudaEventRecord(eT, s2);

    // main: conv + KV GEMM
    conv_h<<<2048, 256>>>(x, xh, (size_t)Mq * DIMq);
    cudaStreamWaitEvent(0, eT, 0);
    gemm_qkv<<<dim3(8, Mq / 128), 256, GEMM_SMEM>>>(xh, wqkvT, 16);   // K, V
    cudaEventRecord(eKV, 0);

    // s2 tail: wo transpose (overlaps main GEMMs)
    transpose_h<<<dim3(DIMq / 32, DIMq / 32), dim3(32, 8), 0, s2>>>(wo, woT, DIMq, DIMq);
    cudaEventRecord(eWo, s2);

    // s3: selection chain + selected-only compress (waits eKV; enqueued after its record)
    xmean_part_kernel<<<dim3(16, 16, Bq), 128, 0, s3>>>(x);
    xmean_final_kernel<<<Bq * 16, 128, 0, s3>>>();
    kimean_kernel<<<Bq, 128, 0, s3>>>(wik);
    u_kernel<<<Bq * 16, 128, 0, s3>>>(wiq);
    scores_kernel<<<Bq * NBq, 128, 0, s3>>>(x);
    topk_kernel<<<Bq, 256, 0, s3>>>();
    cudaStreamWaitEvent(s3, eKV, 0);
    compress_sel<<<Bq * HKVq * TOPKq, 128, 0, s3>>>(cwa, cwb);
    cudaEventRecord(eGa, s3);

    // main: Q GEMM overlaps compress; then attention; then output GEMM
    gemm_qkv<<<dim3(16, Mq / 128), 256, GEMM_SMEM>>>(xh, wqkvT, 0);   // Q
    cudaStreamWaitEvent(0, eGa, 0);
    attn_mma<<<Bq * HKVq * (Tq / 64), 256, ATTN_SMEM2>>>();
    cudaStreamWaitEvent(0, eWo, 0);
    gemm_f16<<<dim3(DIMq / 128, Mq / 128), 256, GEMM_SMEM>>>(xoh, woT, out, Mq, DIMq, DIMq);
}